// round 10
// baseline (speedup 1.0000x reference)
#include <cuda_runtime.h>
#include <cuda_bf16.h>
#include <cstdint>

// Problem constants (fixed by dataset)
#define BATCH 4
#define SEQ   4096
#define DIM   512
#define DK    64
#define BAND  128
#define SCALE 0.125f            // 1/sqrt(64)
#define ROWS  (BATCH*SEQ)       // 16384
#define MTOT  (2*ROWS)          // 32768 (q rows then kv rows)

// ---- tensor-core helpers ---------------------------------------------------
#define LDSM_X4(r0, r1, r2, r3, addr) \
    asm volatile("ldmatrix.sync.aligned.m8n8.x4.shared.b16 {%0,%1,%2,%3}, [%4];" \
        : "=r"(r0), "=r"(r1), "=r"(r2), "=r"(r3) : "r"(addr))

#define LDSM_X4_T(r0, r1, r2, r3, addr) \
    asm volatile("ldmatrix.sync.aligned.m8n8.x4.trans.shared.b16 {%0,%1,%2,%3}, [%4];" \
        : "=r"(r0), "=r"(r1), "=r"(r2), "=r"(r3) : "r"(addr))

#define MMA_BF16(c, a, b0, b1) \
    asm volatile("mma.sync.aligned.m16n8k16.row.col.f32.bf16.bf16.f32 " \
        "{%0,%1,%2,%3},{%4,%5,%6,%7},{%8,%9},{%0,%1,%2,%3};" \
        : "+f"((c)[0]), "+f"((c)[1]), "+f"((c)[2]), "+f"((c)[3]) \
        : "r"((a)[0]), "r"((a)[1]), "r"((a)[2]), "r"((a)[3]), "r"(b0), "r"(b1))

__device__ __forceinline__ uint32_t pack_bf16x2(__nv_bfloat16 a, __nv_bfloat16 b) {
    __nv_bfloat162 p;
    p.x = a; p.y = b;
    return *reinterpret_cast<uint32_t*>(&p);
}
// split two f32 into (hi, lo) bf16x2 words
__device__ __forceinline__ void split2(float x0, float x1, uint32_t& hw, uint32_t& lw) {
    __nv_bfloat16 h0 = __float2bfloat16(x0);
    __nv_bfloat16 h1 = __float2bfloat16(x1);
    __nv_bfloat16 l0 = __float2bfloat16(x0 - __bfloat162float(h0));
    __nv_bfloat16 l1 = __float2bfloat16(x1 - __bfloat162float(h1));
    hw = pack_bf16x2(h0, h1);
    lw = pack_bf16x2(l0, l1);
}

// Scratch (device globals; no allocation allowed). All split bf16 hi/lo pairs.
__device__ __nv_bfloat16 g_qh[ROWS * DK];
__device__ __nv_bfloat16 g_ql[ROWS * DK];
__device__ __nv_bfloat16 g_kvh[ROWS * DK];
__device__ __nv_bfloat16 g_kvl[ROWS * DK];
__device__ __nv_bfloat16 g_atth[ROWS * DK];
__device__ __nv_bfloat16 g_attl[ROWS * DK];
// Pre-split weights
__device__ __nv_bfloat16 g_wihT[DK * DIM];   // Wi^T: [n=64][k=512]
__device__ __nv_bfloat16 g_wilT[DK * DIM];
__device__ __nv_bfloat16 g_woh[DK * DIM];    // Wo:   [k=64][n=512]
__device__ __nv_bfloat16 g_wol[DK * DIM];

// ---------------------------------------------------------------------------
// Kernel 0: split weights once.
// ---------------------------------------------------------------------------
__global__ void __launch_bounds__(256) split_w_kernel(const float* __restrict__ Wi,
                                                      const float* __restrict__ Wo)
{
    int idx = blockIdx.x * 256 + threadIdx.x;   // 0..32767
    // Wi [k=512][n=64] -> transposed split
    {
        int k = idx >> 6, n = idx & 63;
        float x = Wi[idx];
        __nv_bfloat16 h = __float2bfloat16(x);
        __nv_bfloat16 l = __float2bfloat16(x - __bfloat162float(h));
        g_wihT[n * DIM + k] = h;
        g_wilT[n * DIM + k] = l;
    }
    // Wo [k=64][n=512] -> same-layout split
    {
        float y = Wo[idx];
        __nv_bfloat16 h = __float2bfloat16(y);
        __nv_bfloat16 l = __float2bfloat16(y - __bfloat162float(h));
        g_woh[idx] = h;
        g_wol[idx] = l;
    }
}

// ---------------------------------------------------------------------------
// Kernel 1: shared input projection via split-bf16 MMA, 2-deep prefetch.
//   dst(split) = src @ Wi + bi,  src 32768x512, Wi pre-split.
// CTA: 64 rows x 64 cols, 256 threads = 8 warps (wm 0..3 m16, wn 0..1 n32).
// ---------------------------------------------------------------------------
#define ASTRIDE 40   // bf16 units per row (32 data + 8 pad)

__global__ void __launch_bounds__(256) proj_kernel(const float* __restrict__ query,
                                                   const float* __restrict__ value,
                                                   const float* __restrict__ bi)
{
    __shared__ __align__(16) __nv_bfloat16 Ah[2][64 * ASTRIDE];
    __shared__ __align__(16) __nv_bfloat16 Al[2][64 * ASTRIDE];
    __shared__ __align__(16) __nv_bfloat16 Wh[2][64 * ASTRIDE];  // [n][k]
    __shared__ __align__(16) __nv_bfloat16 Wl[2][64 * ASTRIDE];

    const int t    = threadIdx.x;
    const int lane = t & 31;
    const int warp = t >> 5;
    const int row0 = blockIdx.x * 64;

    const float* src;
    uint32_t* dsth;
    uint32_t* dstl;
    int roff;
    if (row0 < ROWS) {
        src = query;
        dsth = reinterpret_cast<uint32_t*>(g_qh);
        dstl = reinterpret_cast<uint32_t*>(g_ql);
        roff = row0;
    } else {
        src = value;
        dsth = reinterpret_cast<uint32_t*>(g_kvh);
        dstl = reinterpret_cast<uint32_t*>(g_kvl);
        roff = row0 - ROWS;
    }

    const int wm = warp & 3;
    const int wn = warp >> 2;
    const int m_base = wm * 16;
    const int n_base = wn * 32;

    // A loader: 64 rows x 32 k, each thread 8 fp32 of one row
    const int lr = t >> 2;
    const int ls = (t & 3) * 8;
    // W loader: one uint4 (8 bf16) per array per chunk
    const int wnl = t & 63;
    const int wkg = t >> 6;

    // ldmatrix lane addressing
    const int a_row = lane & 15;
    const int a_c8  = (lane >> 4) * 8;
    const int b_row = (lane & 7) + ((lane >> 4) & 1) * 8;
    const int b_c8  = ((lane >> 3) & 1) * 8;

    const uint32_t ahB0 = (uint32_t)__cvta_generic_to_shared(Ah);
    const uint32_t alB0 = (uint32_t)__cvta_generic_to_shared(Al);
    const uint32_t whB0 = (uint32_t)__cvta_generic_to_shared(Wh);
    const uint32_t wlB0 = (uint32_t)__cvta_generic_to_shared(Wl);
    const uint32_t bufBytes = 64 * ASTRIDE * 2;

    float c[4][4];
#pragma unroll
    for (int n = 0; n < 4; n++)
#pragma unroll
        for (int r = 0; r < 4; r++) c[n][r] = 0.0f;

    // 2-deep prefetch registers
    float4 a0[2], a1[2];
    uint4 whr[2], wlr[2];

    const float* arow_p = src + (size_t)(roff + lr) * DIM + ls;
    const __nv_bfloat16* whp = g_wihT + wnl * DIM + wkg * 8;
    const __nv_bfloat16* wlp = g_wilT + wnl * DIM + wkg * 8;

#pragma unroll
    for (int s = 0; s < 2; s++) {
        const float4* ap = reinterpret_cast<const float4*>(arow_p + s * 32);
        a0[s] = ap[0]; a1[s] = ap[1];
        whr[s] = *reinterpret_cast<const uint4*>(whp + s * 32);
        wlr[s] = *reinterpret_cast<const uint4*>(wlp + s * 32);
    }

    for (int k0i = 0; k0i < 16; k0i++) {
        const int s = k0i & 1;
        // split + store prefetched chunk into smem[s]
        {
            uint32_t hw[4], lw[4];
            split2(a0[s].x, a0[s].y, hw[0], lw[0]);
            split2(a0[s].z, a0[s].w, hw[1], lw[1]);
            split2(a1[s].x, a1[s].y, hw[2], lw[2]);
            split2(a1[s].z, a1[s].w, hw[3], lw[3]);
            int wo = lr * (ASTRIDE / 2) + (ls >> 1);
            *reinterpret_cast<uint4*>(reinterpret_cast<uint32_t*>(Ah[s]) + wo) =
                make_uint4(hw[0], hw[1], hw[2], hw[3]);
            *reinterpret_cast<uint4*>(reinterpret_cast<uint32_t*>(Al[s]) + wo) =
                make_uint4(lw[0], lw[1], lw[2], lw[3]);
            *reinterpret_cast<uint4*>(&Wh[s][wnl * ASTRIDE + wkg * 8]) = whr[s];
            *reinterpret_cast<uint4*>(&Wl[s][wnl * ASTRIDE + wkg * 8]) = wlr[s];
        }
        __syncthreads();

        // issue global loads for chunk k0i+2 into the just-freed register stage
        if (k0i < 14) {
            int k0 = (k0i + 2) * 32;
            const float4* ap = reinterpret_cast<const float4*>(arow_p + k0);
            a0[s] = ap[0]; a1[s] = ap[1];
            whr[s] = *reinterpret_cast<const uint4*>(whp + k0);
            wlr[s] = *reinterpret_cast<const uint4*>(wlp + k0);
        }

        const uint32_t ahB = ahB0 + s * bufBytes;
        const uint32_t alB = alB0 + s * bufBytes;
        const uint32_t whB = whB0 + s * bufBytes;
        const uint32_t wlB = wlB0 + s * bufBytes;

#pragma unroll
        for (int ks = 0; ks < 32; ks += 16) {
            uint32_t ah[4], al[4];
            {
                uint32_t off = (uint32_t)(((m_base + a_row) * ASTRIDE + ks + a_c8) * 2);
                LDSM_X4(ah[0], ah[1], ah[2], ah[3], ahB + off);
                LDSM_X4(al[0], al[1], al[2], al[3], alB + off);
            }
            uint32_t bh[8], bl[8];
            {
                uint32_t off0 = (uint32_t)(((n_base + b_row) * ASTRIDE + ks + b_c8) * 2);
                uint32_t off1 = off0 + 16 * ASTRIDE * 2;
                LDSM_X4(bh[0], bh[1], bh[2], bh[3], whB + off0);
                LDSM_X4(bh[4], bh[5], bh[6], bh[7], whB + off1);
                LDSM_X4(bl[0], bl[1], bl[2], bl[3], wlB + off0);
                LDSM_X4(bl[4], bl[5], bl[6], bl[7], wlB + off1);
            }
#pragma unroll
            for (int n = 0; n < 4; n++) {
                MMA_BF16(c[n], ah, bh[2 * n], bh[2 * n + 1]);
                MMA_BF16(c[n], ah, bl[2 * n], bl[2 * n + 1]);
                MMA_BF16(c[n], al, bh[2 * n], bh[2 * n + 1]);
            }
        }
    }

    // epilogue: add bias, split to bf16 hi/lo, store packed words
    const int g = lane >> 2, tig = lane & 3;
    {
        int row = roff + m_base + g;
#pragma unroll
        for (int n = 0; n < 4; n++) {
            int col = n_base + n * 8 + tig * 2;
            float b0v = bi[col], b1v = bi[col + 1];
            uint32_t hw, lw;
            split2(c[n][0] + b0v, c[n][1] + b1v, hw, lw);
            dsth[(size_t)row * 32 + (col >> 1)] = hw;
            dstl[(size_t)row * 32 + (col >> 1)] = lw;
            split2(c[n][2] + b0v, c[n][3] + b1v, hw, lw);
            dsth[(size_t)(row + 8) * 32 + (col >> 1)] = hw;
            dstl[(size_t)(row + 8) * 32 + (col >> 1)] = lw;
        }
    }
}

// ---------------------------------------------------------------------------
// Kernel 2: banded attention, tensor cores, j-split across 8 warps.
// Double-buffered K tiles + register prefetch; one sync per tile.
// ---------------------------------------------------------------------------
#define QSTR 72   // bf16 stride for 64-wide tiles (144B rows)
#define KBUF_BYTES (64 * QSTR * 2)
#define ATTN_SMEM_BYTES (6 * 64 * QSTR * 2 + 64 * 66 * 4)

__global__ void __launch_bounds__(256) attn_kernel()
{
    extern __shared__ __align__(16) char asmem[];
    __nv_bfloat16* Qh = reinterpret_cast<__nv_bfloat16*>(asmem);
    __nv_bfloat16* Ql = Qh + 64 * QSTR;
    __nv_bfloat16* Kh = Ql + 64 * QSTR;          // [2][64*QSTR]
    __nv_bfloat16* Kl = Kh + 2 * 64 * QSTR;      // [2][64*QSTR]
    float (*red)[66] = reinterpret_cast<float(*)[66]>(Kl + 2 * 64 * QSTR);

    const int t    = threadIdx.x;
    const int lane = t & 31;
    const int warp = t >> 5;
    const int b    = blockIdx.x >> 6;
    const int qs   = blockIdx.x & 63;
    const int q0   = qs * 64;

    const int wm = warp & 3;
    const int wj = warp >> 2;
    const int m_base = wm * 16;
    const int jcol0  = wj * 32;

    const uint32_t qhB = (uint32_t)__cvta_generic_to_shared(Qh);
    const uint32_t qlB = (uint32_t)__cvta_generic_to_shared(Ql);
    const uint32_t khB0 = (uint32_t)__cvta_generic_to_shared(Kh);
    const uint32_t klB0 = (uint32_t)__cvta_generic_to_shared(Kl);

    // loaders: row r0 & r0+32, uint4 s0 of 8 per row
    const int r0 = t >> 3;
    const int s0 = t & 7;

    // load Q tile (split bf16)
    {
        size_t gb0 = ((size_t)b * SEQ + q0 + r0) * DK;
        size_t gb1 = gb0 + (size_t)32 * DK;
        reinterpret_cast<uint4*>(&Qh[r0 * QSTR])[s0] =
            reinterpret_cast<const uint4*>(g_qh + gb0)[s0];
        reinterpret_cast<uint4*>(&Ql[r0 * QSTR])[s0] =
            reinterpret_cast<const uint4*>(g_ql + gb0)[s0];
        reinterpret_cast<uint4*>(&Qh[(r0 + 32) * QSTR])[s0] =
            reinterpret_cast<const uint4*>(g_qh + gb1)[s0];
        reinterpret_cast<uint4*>(&Ql[(r0 + 32) * QSTR])[s0] =
            reinterpret_cast<const uint4*>(g_ql + gb1)[s0];
    }
    __syncthreads();

    // ldmatrix lane addressing
    const int a_row = lane & 15;
    const int a_c8  = (lane >> 4) * 8;
    const int b_row = (lane & 7) + ((lane >> 4) & 1) * 8;
    const int b_c8  = ((lane >> 3) & 1) * 8;
    const int tj    = (lane & 7) + ((lane >> 3) & 1) * 8;
    const int td8   = (lane >> 4) * 8;

    // Q a-fragments: persistent across all j-tiles
    uint32_t qha[4][4], qla[4][4];
#pragma unroll
    for (int kc = 0; kc < 4; kc++) {
        uint32_t off = (uint32_t)(((m_base + a_row) * QSTR + kc * 16 + a_c8) * 2);
        LDSM_X4(qha[kc][0], qha[kc][1], qha[kc][2], qha[kc][3], qhB + off);
        LDSM_X4(qla[kc][0], qla[kc][1], qla[kc][2], qla[kc][3], qlB + off);
    }

    float attv[8][4];
#pragma unroll
    for (int n = 0; n < 8; n++)
#pragma unroll
        for (int r = 0; r < 4; r++) attv[n][r] = 0.0f;

    const int g = lane >> 2, tq = lane & 3;
    const int gi_lo = q0 + m_base;
    const int gi_hi = gi_lo + 15;

    // build valid tile list
    int tiles[5];
    int nt = 0;
    for (int jt = qs - 2; jt <= qs + 2; jt++)
        if (jt >= 0 && jt < 64) tiles[nt++] = jt;

    // prefetch first K tile into registers
    uint4 ph0, ph1, pl0, pl1;
    {
        size_t gb0 = ((size_t)b * SEQ + tiles[0] * 64 + r0) * DK;
        size_t gb1 = gb0 + (size_t)32 * DK;
        ph0 = reinterpret_cast<const uint4*>(g_kvh + gb0)[s0];
        pl0 = reinterpret_cast<const uint4*>(g_kvl + gb0)[s0];
        ph1 = reinterpret_cast<const uint4*>(g_kvh + gb1)[s0];
        pl1 = reinterpret_cast<const uint4*>(g_kvl + gb1)[s0];
    }

    for (int it = 0; it < nt; it++) {
        const int jt  = tiles[it];
        const int buf = it & 1;
        // store prefetched tile into smem[buf]
        {
            __nv_bfloat16* kh = Kh + buf * 64 * QSTR;
            __nv_bfloat16* kl = Kl + buf * 64 * QSTR;
            reinterpret_cast<uint4*>(&kh[r0 * QSTR])[s0] = ph0;
            reinterpret_cast<uint4*>(&kl[r0 * QSTR])[s0] = pl0;
            reinterpret_cast<uint4*>(&kh[(r0 + 32) * QSTR])[s0] = ph1;
            reinterpret_cast<uint4*>(&kl[(r0 + 32) * QSTR])[s0] = pl1;
        }
        __syncthreads();
        // prefetch next tile
        if (it + 1 < nt) {
            size_t gb0 = ((size_t)b * SEQ + tiles[it + 1] * 64 + r0) * DK;
            size_t gb1 = gb0 + (size_t)32 * DK;
            ph0 = reinterpret_cast<const uint4*>(g_kvh + gb0)[s0];
            pl0 = reinterpret_cast<const uint4*>(g_kvl + gb0)[s0];
            ph1 = reinterpret_cast<const uint4*>(g_kvh + gb1)[s0];
            pl1 = reinterpret_cast<const uint4*>(g_kvl + gb1)[s0];
        }

        const uint32_t khB = khB0 + buf * KBUF_BYTES;
        const uint32_t klB = klB0 + buf * KBUF_BYTES;
        const int jbase = jt * 64;

        // block in-band predicates for this warp's two 16-wide j blocks
        bool keep[2];
#pragma unroll
        for (int blk = 0; blk < 2; blk++) {
            int jlo = jbase + jcol0 + blk * 16;
            keep[blk] = !(gi_lo - (jlo + 15) > BAND || jlo - gi_hi > BAND);
        }

        // ---- Phase A: S (m16 x n32) = Q K^T, 3-term split ----
        float S[4][4];
#pragma unroll
        for (int n = 0; n < 4; n++)
#pragma unroll
            for (int r = 0; r < 4; r++) S[n][r] = 0.0f;

#pragma unroll
        for (int kc = 0; kc < 4; kc++) {
#pragma unroll
            for (int ng = 0; ng < 2; ng++) {
                if (!keep[ng]) continue;
                uint32_t off = (uint32_t)(((jcol0 + ng * 16 + b_row) * QSTR + kc * 16 + b_c8) * 2);
                uint32_t bh[4], bl[4];
                LDSM_X4(bh[0], bh[1], bh[2], bh[3], khB + off);
                LDSM_X4(bl[0], bl[1], bl[2], bl[3], klB + off);
                MMA_BF16(S[2 * ng],     qha[kc], bh[0], bh[1]);
                MMA_BF16(S[2 * ng],     qha[kc], bl[0], bl[1]);
                MMA_BF16(S[2 * ng],     qla[kc], bh[0], bh[1]);
                MMA_BF16(S[2 * ng + 1], qha[kc], bh[2], bh[3]);
                MMA_BF16(S[2 * ng + 1], qha[kc], bl[2], bl[3]);
                MMA_BF16(S[2 * ng + 1], qla[kc], bh[2], bh[3]);
            }
        }

        // ---- mask + scale in registers ----
        const int gi0 = gi_lo + g;
#pragma unroll
        for (int n = 0; n < 4; n++) {
            int gj = jbase + jcol0 + n * 8 + tq * 2;
            int d0 = gi0 - gj;
            int d1 = d0 - 1;
            int d2 = d0 + 8;
            int d3 = d2 - 1;
            S[n][0] = (d0 <= BAND && d0 >= -BAND) ? S[n][0] * SCALE : 0.0f;
            S[n][1] = (d1 <= BAND && d1 >= -BAND) ? S[n][1] * SCALE : 0.0f;
            S[n][2] = (d2 <= BAND && d2 >= -BAND) ? S[n][2] * SCALE : 0.0f;
            S[n][3] = (d3 <= BAND && d3 >= -BAND) ? S[n][3] * SCALE : 0.0f;
        }

        // ---- split S C-frags into phase-B A-frags ----
        uint32_t pah[2][4], pal[2][4];
#pragma unroll
        for (int kc = 0; kc < 2; kc++) {
            split2(S[2 * kc][0],     S[2 * kc][1],     pah[kc][0], pal[kc][0]);
            split2(S[2 * kc][2],     S[2 * kc][3],     pah[kc][1], pal[kc][1]);
            split2(S[2 * kc + 1][0], S[2 * kc + 1][1], pah[kc][2], pal[kc][2]);
            split2(S[2 * kc + 1][2], S[2 * kc + 1][3], pah[kc][3], pal[kc][3]);
        }

        // ---- Phase B: attv += S @ KV (this warp's j-half) ----
#pragma unroll
        for (int kc = 0; kc < 2; kc++) {
            if (!keep[kc]) continue;
#pragma unroll
            for (int dg = 0; dg < 4; dg++) {
                uint32_t off = (uint32_t)(((jcol0 + kc * 16 + tj) * QSTR + dg * 16 + td8) * 2);
                uint32_t vh[4], vl[4];
                LDSM_X4_T(vh[0], vh[1], vh[2], vh[3], khB + off);
                LDSM_X4_T(vl[0], vl[1], vl[2], vl[3], klB + off);
                MMA_BF16(attv[2 * dg],     pah[kc], vh[0], vh[1]);
                MMA_BF16(attv[2 * dg],     pah[kc], vl[0], vl[1]);
                MMA_BF16(attv[2 * dg],     pal[kc], vh[0], vh[1]);
                MMA_BF16(attv[2 * dg + 1], pah[kc], vh[2], vh[3]);
                MMA_BF16(attv[2 * dg + 1], pah[kc], vl[2], vl[3]);
                MMA_BF16(attv[2 * dg + 1], pal[kc], vh[2], vh[3]);
            }
        }
    }

    // ---- cross-warp reduction over wj, then epilogue ----
    __syncthreads();
    if (wj == 1) {
#pragma unroll
        for (int n = 0; n < 8; n++) {
            int col = n * 8 + tq * 2;
            *reinterpret_cast<float2*>(&red[m_base + g][col])     = make_float2(attv[n][0], attv[n][1]);
            *reinterpret_cast<float2*>(&red[m_base + g + 8][col]) = make_float2(attv[n][2], attv[n][3]);
        }
    }
    __syncthreads();
    if (wj == 0) {
        uint32_t* atth_w = reinterpret_cast<uint32_t*>(g_atth);
        uint32_t* attl_w = reinterpret_cast<uint32_t*>(g_attl);
        const size_t rbase = (size_t)b * SEQ + q0 + m_base + g;
#pragma unroll
        for (int n = 0; n < 8; n++) {
            int col = n * 8 + tq * 2;
            float2 rr0 = *reinterpret_cast<const float2*>(&red[m_base + g][col]);
            float2 rr1 = *reinterpret_cast<const float2*>(&red[m_base + g + 8][col]);
            int cw = n * 4 + tq;
            uint32_t hw, lw;
            split2(attv[n][0] + rr0.x, attv[n][1] + rr0.y, hw, lw);
            atth_w[rbase * 32 + cw] = hw;
            attl_w[rbase * 32 + cw] = lw;
            split2(attv[n][2] + rr1.x, attv[n][3] + rr1.y, hw, lw);
            atth_w[(rbase + 8) * 32 + cw] = hw;
            attl_w[(rbase + 8) * 32 + cw] = lw;
        }
    }
}

// ---------------------------------------------------------------------------
// Kernel 3: out = att @ Wo + bo via split-bf16 MMA.  [16384,64]x[64,512]
// CTA: 128 rows x 128 cols, 256 threads = 8 warps (wm 0..3 x wn 0..1).
// Wo pre-split in gmem; loaders are pure uint4 copies.
// ---------------------------------------------------------------------------
#define WSTR 136   // bf16 stride for 128-wide Wo tiles
#define OUT_SMEM_BYTES ((2*128*QSTR + 2*64*WSTR) * 2)

__global__ void __launch_bounds__(256) out_kernel(const float* __restrict__ bo,
                                                  float* __restrict__ out)
{
    extern __shared__ __align__(16) __nv_bfloat16 smo[];
    __nv_bfloat16* Ah = smo;
    __nv_bfloat16* Al = Ah + 128 * QSTR;
    __nv_bfloat16* Wh = Al + 128 * QSTR;
    __nv_bfloat16* Wl = Wh + 64 * WSTR;

    const int t    = threadIdx.x;
    const int lane = t & 31;
    const int warp = t >> 5;
    const int rb   = blockIdx.x >> 2;
    const int cb   = blockIdx.x & 3;
    const int row0 = rb * 128;
    const int col0 = cb * 128;

    const int wm = warp & 3;
    const int wn = warp >> 2;

    const uint32_t ahB = (uint32_t)__cvta_generic_to_shared(Ah);
    const uint32_t alB = (uint32_t)__cvta_generic_to_shared(Al);
    const uint32_t whB = (uint32_t)__cvta_generic_to_shared(Wh);
    const uint32_t wlB = (uint32_t)__cvta_generic_to_shared(Wl);

    // load att tile (split bf16): 128 rows, each thread one half-row
    {
        int lr = t >> 1, lhf = t & 1;
        size_t gbase = (size_t)(row0 + lr) * DK;
        const uint4* sh = reinterpret_cast<const uint4*>(g_atth + gbase) + lhf * 4;
        const uint4* sl = reinterpret_cast<const uint4*>(g_attl + gbase) + lhf * 4;
        uint4* dh = reinterpret_cast<uint4*>(&Ah[lr * QSTR + lhf * 32]);
        uint4* dl = reinterpret_cast<uint4*>(&Al[lr * QSTR + lhf * 32]);
#pragma unroll
        for (int v = 0; v < 4; v++) { dh[v] = sh[v]; dl[v] = sl[v]; }
    }
    // load pre-split Wo tile: [64 k][128 n], keep [k][n]
    {
        int wk = t >> 2, seg = (t & 3) * 32;
        const uint4* sh = reinterpret_cast<const uint4*>(g_woh + (size_t)wk * DIM + col0 + seg);
        const uint4* sl = reinterpret_cast<const uint4*>(g_wol + (size_t)wk * DIM + col0 + seg);
        uint4* dh = reinterpret_cast<uint4*>(&Wh[wk * WSTR + seg]);
        uint4* dl = reinterpret_cast<uint4*>(&Wl[wk * WSTR + seg]);
#pragma unroll
        for (int v = 0; v < 4; v++) { dh[v] = sh[v]; dl[v] = sl[v]; }
    }
    __syncthreads();

    const int a_row = lane & 15;
    const int a_c8  = (lane >> 4) * 8;
    const int tj    = (lane & 7) + ((lane >> 3) & 1) * 8;
    const int td8   = (lane >> 4) * 8;

    float c[2][8][4];
#pragma unroll
    for (int m = 0; m < 2; m++)
#pragma unroll
        for (int n = 0; n < 8; n++)
#pragma unroll
            for (int r = 0; r < 4; r++) c[m][n][r] = 0.0f;

#pragma unroll
    for (int kc = 0; kc < 4; kc++) {
        uint32_t ah[2][4], al[2][4];
#pragma unroll
        for (int m = 0; m < 2; m++) {
            uint32_t off = (uint32_t)(((wm * 32 + m * 16 + a_row) * QSTR + kc * 16 + a_c8) * 2);
            LDSM_X4(ah[m][0], ah[m][1], ah[m][2], ah[m][3], ahB + off);
            LDSM_X4(al[m][0], al[m][1], al[m][2], al[m][3], alB + off);
        }
#pragma unroll
        for (int dg = 0; dg < 4; dg++) {
            uint32_t off = (uint32_t)(((kc * 16 + tj) * WSTR + wn * 64 + dg * 16 + td8) * 2);
            uint32_t vh[4], vl[4];
            LDSM_X4_T(vh[0], vh[1], vh[2], vh[3], whB + off);
            LDSM_X4_T(vl[0], vl[1], vl[2], vl[3], wlB + off);
#pragma unroll
            for (int m = 0; m < 2; m++) {
                MMA_BF16(c[m][2 * dg],     ah[m], vh[0], vh[1]);
                MMA_BF16(c[m][2 * dg],     ah[m], vl[0], vl[1]);
                MMA_BF16(c[m][2 * dg],     al[m], vh[0], vh[1]);
                MMA_BF16(c[m][2 * dg + 1], ah[m], vh[2], vh[3]);
                MMA_BF16(c[m][2 * dg + 1], ah[m], vl[2], vl[3]);
                MMA_BF16(c[m][2 * dg + 1], al[m], vh[2], vh[3]);
            }
        }
    }

    // epilogue: bias + fp32 store
    const int g = lane >> 2, tq = lane & 3;
#pragma unroll
    for (int m = 0; m < 2; m++) {
        int row = row0 + wm * 32 + m * 16 + g;
#pragma unroll
        for (int n = 0; n < 8; n++) {
            int col = col0 + wn * 64 + n * 8 + tq * 2;
            float b0v = bo[col], b1v = bo[col + 1];
            float2 o0 = {c[m][n][0] + b0v, c[m][n][1] + b1v};
            float2 o1 = {c[m][n][2] + b0v, c[m][n][3] + b1v};
            *reinterpret_cast<float2*>(&out[(size_t)row * DIM + col]) = o0;
            *reinterpret_cast<float2*>(&out[(size_t)(row + 8) * DIM + col]) = o1;
        }
    }
}

// ---------------------------------------------------------------------------
extern "C" void kernel_launch(void* const* d_in, const int* in_sizes, int n_in,
                              void* d_out, int out_size)
{
    const float* query = (const float*)d_in[0];
    const float* value = (const float*)d_in[1];
    const float* Wi    = (const float*)d_in[2];
    const float* bi    = (const float*)d_in[3];
    const float* Wo    = (const float*)d_in[4];
    const float* bo    = (const float*)d_in[5];
    float* out = (float*)d_out;

    static bool attr_set = false;
    if (!attr_set) {
        cudaFuncSetAttribute(attn_kernel, cudaFuncAttributeMaxDynamicSharedMemorySize,
                             ATTN_SMEM_BYTES);
        cudaFuncSetAttribute(out_kernel, cudaFuncAttributeMaxDynamicSharedMemorySize,
                             OUT_SMEM_BYTES);
        attr_set = true;
    }

    split_w_kernel<<<128, 256>>>(Wi, Wo);
    proj_kernel<<<MTOT / 64, 256>>>(query, value, bi);
    attn_kernel<<<BATCH * (SEQ / 64), 256, ATTN_SMEM_BYTES>>>();
    out_kernel<<<(ROWS / 128) * (DIM / 128), 256, OUT_SMEM_BYTES>>>(bo, out);
}

// round 11
// speedup vs baseline: 1.4079x; 1.4079x over previous
#include <cuda_runtime.h>
#include <cuda_bf16.h>
#include <cstdint>

// Problem constants (fixed by dataset)
#define BATCH 4
#define SEQ   4096
#define DIM   512
#define DK    64
#define BAND  128
#define SCALE 0.125f            // 1/sqrt(64)
#define ROWS  (BATCH*SEQ)       // 16384
#define MTOT  (2*ROWS)          // 32768 (q rows then kv rows)

// ---- tensor-core helpers ---------------------------------------------------
#define LDSM_X4(r0, r1, r2, r3, addr) \
    asm volatile("ldmatrix.sync.aligned.m8n8.x4.shared.b16 {%0,%1,%2,%3}, [%4];" \
        : "=r"(r0), "=r"(r1), "=r"(r2), "=r"(r3) : "r"(addr))

#define LDSM_X4_T(r0, r1, r2, r3, addr) \
    asm volatile("ldmatrix.sync.aligned.m8n8.x4.trans.shared.b16 {%0,%1,%2,%3}, [%4];" \
        : "=r"(r0), "=r"(r1), "=r"(r2), "=r"(r3) : "r"(addr))

#define MMA_BF16(c, a, b0, b1) \
    asm volatile("mma.sync.aligned.m16n8k16.row.col.f32.bf16.bf16.f32 " \
        "{%0,%1,%2,%3},{%4,%5,%6,%7},{%8,%9},{%0,%1,%2,%3};" \
        : "+f"((c)[0]), "+f"((c)[1]), "+f"((c)[2]), "+f"((c)[3]) \
        : "r"((a)[0]), "r"((a)[1]), "r"((a)[2]), "r"((a)[3]), "r"(b0), "r"(b1))

__device__ __forceinline__ uint32_t pack_bf16x2(__nv_bfloat16 a, __nv_bfloat16 b) {
    __nv_bfloat162 p;
    p.x = a; p.y = b;
    return *reinterpret_cast<uint32_t*>(&p);
}
// split two f32 into (hi, lo) bf16x2 words
__device__ __forceinline__ void split2(float x0, float x1, uint32_t& hw, uint32_t& lw) {
    __nv_bfloat16 h0 = __float2bfloat16(x0);
    __nv_bfloat16 h1 = __float2bfloat16(x1);
    __nv_bfloat16 l0 = __float2bfloat16(x0 - __bfloat162float(h0));
    __nv_bfloat16 l1 = __float2bfloat16(x1 - __bfloat162float(h1));
    hw = pack_bf16x2(h0, h1);
    lw = pack_bf16x2(l0, l1);
}

// Scratch (device globals; no allocation allowed). All split bf16 hi/lo pairs.
__device__ __nv_bfloat16 g_qh[ROWS * DK];
__device__ __nv_bfloat16 g_ql[ROWS * DK];
__device__ __nv_bfloat16 g_kvh[ROWS * DK];
__device__ __nv_bfloat16 g_kvl[ROWS * DK];
__device__ __nv_bfloat16 g_woh[DK * DIM];    // Wo split: [k=64][n=512]
__device__ __nv_bfloat16 g_wol[DK * DIM];

// ---------------------------------------------------------------------------
// Kernel 1: shared input projection via split-bf16 MMA (identical to the
// 80us version), plus 8 tail CTAs that pre-split Wo into g_woh/g_wol.
// CTA: 64 rows x 64 cols, 256 threads = 8 warps (wm 0..3 m16, wn 0..1 n32).
// ---------------------------------------------------------------------------
#define ASTRIDE 40   // bf16 units per row (32 data + 8 pad)

__global__ void __launch_bounds__(256) proj_kernel(const float* __restrict__ query,
                                                   const float* __restrict__ value,
                                                   const float* __restrict__ Wi,
                                                   const float* __restrict__ Wo,
                                                   const float* __restrict__ bi)
{
    const int t    = threadIdx.x;
    const int row0 = blockIdx.x * 64;

    // ---- tail CTAs: split Wo once ----
    if (row0 >= MTOT) {
        int base = (blockIdx.x - (MTOT / 64)) * 4096 + t * 16;
        const float4* wp = reinterpret_cast<const float4*>(Wo + base);
        uint32_t hw[8], lw[8];
#pragma unroll
        for (int v = 0; v < 4; v++) {
            float4 f = wp[v];
            split2(f.x, f.y, hw[2 * v],     lw[2 * v]);
            split2(f.z, f.w, hw[2 * v + 1], lw[2 * v + 1]);
        }
        uint4* dh = reinterpret_cast<uint4*>(g_woh + base);
        uint4* dl = reinterpret_cast<uint4*>(g_wol + base);
        dh[0] = make_uint4(hw[0], hw[1], hw[2], hw[3]);
        dh[1] = make_uint4(hw[4], hw[5], hw[6], hw[7]);
        dl[0] = make_uint4(lw[0], lw[1], lw[2], lw[3]);
        dl[1] = make_uint4(lw[4], lw[5], lw[6], lw[7]);
        return;
    }

    __shared__ __align__(16) __nv_bfloat16 Ah[2][64 * ASTRIDE];
    __shared__ __align__(16) __nv_bfloat16 Al[2][64 * ASTRIDE];
    __shared__ __align__(16) __nv_bfloat16 Wh[2][64 * ASTRIDE];  // [n][k]
    __shared__ __align__(16) __nv_bfloat16 Wl[2][64 * ASTRIDE];

    const int lane = t & 31;
    const int warp = t >> 5;

    const float* src;
    uint32_t* dsth;
    uint32_t* dstl;
    int roff;
    if (row0 < ROWS) {
        src = query;
        dsth = reinterpret_cast<uint32_t*>(g_qh);
        dstl = reinterpret_cast<uint32_t*>(g_ql);
        roff = row0;
    } else {
        src = value;
        dsth = reinterpret_cast<uint32_t*>(g_kvh);
        dstl = reinterpret_cast<uint32_t*>(g_kvl);
        roff = row0 - ROWS;
    }

    const int wm = warp & 3;
    const int wn = warp >> 2;
    const int m_base = wm * 16;
    const int n_base = wn * 32;

    // A loader: 64 rows x 32 k, each thread 8 fp32 of one row
    const int lr = t >> 2;
    const int ls = (t & 3) * 8;
    // W loader: col wcol, k-group wkg (8 k each)
    const int wcol = t & 63;
    const int wkg  = t >> 6;

    // ldmatrix lane addressing
    const int a_row = lane & 15;
    const int a_c8  = (lane >> 4) * 8;
    const int b_row = (lane & 7) + ((lane >> 4) & 1) * 8;
    const int b_c8  = ((lane >> 3) & 1) * 8;

    const uint32_t ahB0 = (uint32_t)__cvta_generic_to_shared(Ah);
    const uint32_t alB0 = (uint32_t)__cvta_generic_to_shared(Al);
    const uint32_t whB0 = (uint32_t)__cvta_generic_to_shared(Wh);
    const uint32_t wlB0 = (uint32_t)__cvta_generic_to_shared(Wl);
    const uint32_t bufBytes = 64 * ASTRIDE * 2;

    float c[4][4];
#pragma unroll
    for (int n = 0; n < 4; n++)
#pragma unroll
        for (int r = 0; r < 4; r++) c[n][r] = 0.0f;

    // prefetch registers (1-deep)
    float4 fA0, fA1;
    float wv[8];

    // load chunk 0
    {
        const float4* ap = reinterpret_cast<const float4*>(src + (size_t)(roff + lr) * DIM + ls);
        fA0 = ap[0]; fA1 = ap[1];
        const float* wp = Wi + (size_t)(wkg * 8) * DK + wcol;
#pragma unroll
        for (int j = 0; j < 8; j++) wv[j] = wp[j * DK];
    }

    for (int k0i = 0; k0i < 16; k0i++) {
        const int buf = k0i & 1;
        // split + store prefetched chunk into smem[buf]
        {
            uint32_t hw[4], lw[4];
            split2(fA0.x, fA0.y, hw[0], lw[0]);
            split2(fA0.z, fA0.w, hw[1], lw[1]);
            split2(fA1.x, fA1.y, hw[2], lw[2]);
            split2(fA1.z, fA1.w, hw[3], lw[3]);
            int wo = lr * (ASTRIDE / 2) + (ls >> 1);
            *reinterpret_cast<uint4*>(reinterpret_cast<uint32_t*>(Ah[buf]) + wo) =
                make_uint4(hw[0], hw[1], hw[2], hw[3]);
            *reinterpret_cast<uint4*>(reinterpret_cast<uint32_t*>(Al[buf]) + wo) =
                make_uint4(lw[0], lw[1], lw[2], lw[3]);
            split2(wv[0], wv[1], hw[0], lw[0]);
            split2(wv[2], wv[3], hw[1], lw[1]);
            split2(wv[4], wv[5], hw[2], lw[2]);
            split2(wv[6], wv[7], hw[3], lw[3]);
            int wo2 = wcol * (ASTRIDE / 2) + wkg * 4;
            *reinterpret_cast<uint4*>(reinterpret_cast<uint32_t*>(Wh[buf]) + wo2) =
                make_uint4(hw[0], hw[1], hw[2], hw[3]);
            *reinterpret_cast<uint4*>(reinterpret_cast<uint32_t*>(Wl[buf]) + wo2) =
                make_uint4(lw[0], lw[1], lw[2], lw[3]);
        }
        __syncthreads();

        // issue global loads for next chunk (overlap with MMA below)
        if (k0i < 15) {
            int k0 = (k0i + 1) * 32;
            const float4* ap = reinterpret_cast<const float4*>(
                src + (size_t)(roff + lr) * DIM + k0 + ls);
            fA0 = ap[0]; fA1 = ap[1];
            const float* wp = Wi + (size_t)(k0 + wkg * 8) * DK + wcol;
#pragma unroll
            for (int j = 0; j < 8; j++) wv[j] = wp[j * DK];
        }

        const uint32_t ahB = ahB0 + buf * bufBytes;
        const uint32_t alB = alB0 + buf * bufBytes;
        const uint32_t whB = whB0 + buf * bufBytes;
        const uint32_t wlB = wlB0 + buf * bufBytes;

#pragma unroll
        for (int ks = 0; ks < 32; ks += 16) {
            uint32_t ah[4], al[4];
            {
                uint32_t off = (uint32_t)(((m_base + a_row) * ASTRIDE + ks + a_c8) * 2);
                LDSM_X4(ah[0], ah[1], ah[2], ah[3], ahB + off);
                LDSM_X4(al[0], al[1], al[2], al[3], alB + off);
            }
            uint32_t bh[8], bl[8];
            {
                uint32_t off0 = (uint32_t)(((n_base + b_row) * ASTRIDE + ks + b_c8) * 2);
                uint32_t off1 = off0 + 16 * ASTRIDE * 2;
                LDSM_X4(bh[0], bh[1], bh[2], bh[3], whB + off0);
                LDSM_X4(bh[4], bh[5], bh[6], bh[7], whB + off1);
                LDSM_X4(bl[0], bl[1], bl[2], bl[3], wlB + off0);
                LDSM_X4(bl[4], bl[5], bl[6], bl[7], wlB + off1);
            }
#pragma unroll
            for (int n = 0; n < 4; n++) {
                MMA_BF16(c[n], ah, bh[2 * n], bh[2 * n + 1]);
                MMA_BF16(c[n], ah, bl[2 * n], bl[2 * n + 1]);
                MMA_BF16(c[n], al, bh[2 * n], bh[2 * n + 1]);
            }
        }
    }

    // epilogue: add bias, split to bf16 hi/lo, store packed words
    const int g = lane >> 2, tig = lane & 3;
    {
        int row = roff + m_base + g;
#pragma unroll
        for (int n = 0; n < 4; n++) {
            int col = n_base + n * 8 + tig * 2;
            float b0v = bi[col], b1v = bi[col + 1];
            uint32_t hw, lw;
            split2(c[n][0] + b0v, c[n][1] + b1v, hw, lw);
            dsth[(size_t)row * 32 + (col >> 1)] = hw;
            dstl[(size_t)row * 32 + (col >> 1)] = lw;
            split2(c[n][2] + b0v, c[n][3] + b1v, hw, lw);
            dsth[(size_t)(row + 8) * 32 + (col >> 1)] = hw;
            dstl[(size_t)(row + 8) * 32 + (col >> 1)] = lw;
        }
    }
}

// ---------------------------------------------------------------------------
// Kernel 2: banded attention + fused output projection.
//   att[i,:] = sum_{|i-j|<=128} (q_i . kv_j) * SCALE * kv_j
//   out[i,:] = att[i,:] @ Wo + bo
// CTA = (batch, 64-row q tile), 256 threads: warp = (wm 0..3, wj/wn 0..1).
// Mainloop identical to the 80us version; epilogue keeps att in smem (split
// bf16) and runs the Wo GEMM in-CTA over 4 chunks of 128 cols, with Wo smem
// aliased over the dead Q/K buffers and register-prefetched chunks.
// ---------------------------------------------------------------------------
#define QSTR 72    // bf16 stride for 64-wide tiles (144B rows)
#define WSTR 136   // bf16 stride for 128-wide Wo chunks
// smem byte offsets
#define Q_OFF    0            // Qh 9216 | Ql 9216
#define K_OFF    18432        // Kh 9216 | Kl 9216
#define RED_OFF  36864        // float red[64][66] = 16896
#define ATT_OFF  53760        // AttH 9216 | AttL 9216
#define ATTN_SMEM_BYTES 72192
// Wo chunk aliases the Q/K region: WoH @0 (17408B), WoL @17408

__global__ void __launch_bounds__(256) attn_kernel(const float* __restrict__ bo,
                                                   float* __restrict__ out)
{
    extern __shared__ __align__(16) char asmem[];
    __nv_bfloat16* Qh = reinterpret_cast<__nv_bfloat16*>(asmem + Q_OFF);
    __nv_bfloat16* Ql = Qh + 64 * QSTR;
    __nv_bfloat16* Kh = reinterpret_cast<__nv_bfloat16*>(asmem + K_OFF);
    __nv_bfloat16* Kl = Kh + 64 * QSTR;
    float (*red)[66]  = reinterpret_cast<float(*)[66]>(asmem + RED_OFF);
    __nv_bfloat16* AttH = reinterpret_cast<__nv_bfloat16*>(asmem + ATT_OFF);
    __nv_bfloat16* AttL = AttH + 64 * QSTR;
    __nv_bfloat16* WoH = reinterpret_cast<__nv_bfloat16*>(asmem);           // alias
    __nv_bfloat16* WoL = reinterpret_cast<__nv_bfloat16*>(asmem + 17408);   // alias

    const int t    = threadIdx.x;
    const int lane = t & 31;
    const int warp = t >> 5;
    const int b    = blockIdx.x >> 6;
    const int qs   = blockIdx.x & 63;
    const int q0   = qs * 64;

    const int wm = warp & 3;
    const int wj = warp >> 2;
    const int m_base = wm * 16;
    const int jcol0  = wj * 32;

    const uint32_t qhB = (uint32_t)__cvta_generic_to_shared(Qh);
    const uint32_t qlB = (uint32_t)__cvta_generic_to_shared(Ql);
    const uint32_t khB = (uint32_t)__cvta_generic_to_shared(Kh);
    const uint32_t klB = (uint32_t)__cvta_generic_to_shared(Kl);
    const uint32_t athB = (uint32_t)__cvta_generic_to_shared(AttH);
    const uint32_t atlB = (uint32_t)__cvta_generic_to_shared(AttL);
    const uint32_t whB = (uint32_t)__cvta_generic_to_shared(WoH);
    const uint32_t wlB = (uint32_t)__cvta_generic_to_shared(WoL);

    // load Q tile (split bf16): 512 uint4 per array, 2 per thread
#pragma unroll
    for (int f = t; f < 512; f += 256) {
        int r = f >> 3, s = f & 7;
        size_t gb = ((size_t)b * SEQ + q0 + r) * DK;
        reinterpret_cast<uint4*>(&Qh[r * QSTR])[s] =
            reinterpret_cast<const uint4*>(g_qh + gb)[s];
        reinterpret_cast<uint4*>(&Ql[r * QSTR])[s] =
            reinterpret_cast<const uint4*>(g_ql + gb)[s];
    }
    __syncthreads();

    // ldmatrix lane addressing
    const int a_row = lane & 15;
    const int a_c8  = (lane >> 4) * 8;
    const int b_row = (lane & 7) + ((lane >> 4) & 1) * 8;
    const int b_c8  = ((lane >> 3) & 1) * 8;
    const int tj    = (lane & 7) + ((lane >> 3) & 1) * 8;
    const int td8   = (lane >> 4) * 8;

    // Q a-fragments: persistent across all j-tiles
    uint32_t qha[4][4], qla[4][4];
#pragma unroll
    for (int kc = 0; kc < 4; kc++) {
        uint32_t off = (uint32_t)(((m_base + a_row) * QSTR + kc * 16 + a_c8) * 2);
        LDSM_X4(qha[kc][0], qha[kc][1], qha[kc][2], qha[kc][3], qhB + off);
        LDSM_X4(qla[kc][0], qla[kc][1], qla[kc][2], qla[kc][3], qlB + off);
    }

    float attv[8][4];
#pragma unroll
    for (int n = 0; n < 8; n++)
#pragma unroll
        for (int r = 0; r < 4; r++) attv[n][r] = 0.0f;

    const int g = lane >> 2, tq = lane & 3;
    const int gi_lo = q0 + m_base;
    const int gi_hi = gi_lo + 15;

    for (int jt = qs - 2; jt <= qs + 2; jt++) {
        if (jt < 0 || jt >= 64) continue;
        __syncthreads();   // previous tile's reads done before overwrite
        // load K tile (split bf16)
#pragma unroll
        for (int f = t; f < 512; f += 256) {
            int r = f >> 3, s = f & 7;
            size_t gb = ((size_t)b * SEQ + jt * 64 + r) * DK;
            reinterpret_cast<uint4*>(&Kh[r * QSTR])[s] =
                reinterpret_cast<const uint4*>(g_kvh + gb)[s];
            reinterpret_cast<uint4*>(&Kl[r * QSTR])[s] =
                reinterpret_cast<const uint4*>(g_kvl + gb)[s];
        }
        __syncthreads();

        const int jbase = jt * 64;

        // block in-band predicates for the two 16-wide j blocks of this warp
        bool keep[2];
#pragma unroll
        for (int blk = 0; blk < 2; blk++) {
            int jlo = jbase + jcol0 + blk * 16;
            keep[blk] = !(gi_lo - (jlo + 15) > BAND || jlo - gi_hi > BAND);
        }

        // ---- Phase A: S (m16 x n32) = Q K^T, 3-term split ----
        float S[4][4];
#pragma unroll
        for (int n = 0; n < 4; n++)
#pragma unroll
            for (int r = 0; r < 4; r++) S[n][r] = 0.0f;

#pragma unroll
        for (int kc = 0; kc < 4; kc++) {
#pragma unroll
            for (int ng = 0; ng < 2; ng++) {
                if (!keep[ng]) continue;
                uint32_t off = (uint32_t)(((jcol0 + ng * 16 + b_row) * QSTR + kc * 16 + b_c8) * 2);
                uint32_t bh[4], bl[4];
                LDSM_X4(bh[0], bh[1], bh[2], bh[3], khB + off);
                LDSM_X4(bl[0], bl[1], bl[2], bl[3], klB + off);
                MMA_BF16(S[2 * ng],     qha[kc], bh[0], bh[1]);
                MMA_BF16(S[2 * ng],     qha[kc], bl[0], bl[1]);
                MMA_BF16(S[2 * ng],     qla[kc], bh[0], bh[1]);
                MMA_BF16(S[2 * ng + 1], qha[kc], bh[2], bh[3]);
                MMA_BF16(S[2 * ng + 1], qha[kc], bl[2], bl[3]);
                MMA_BF16(S[2 * ng + 1], qla[kc], bh[2], bh[3]);
            }
        }

        // ---- mask + scale in registers ----
        const int gi0 = gi_lo + g;
#pragma unroll
        for (int n = 0; n < 4; n++) {
            int gj = jbase + jcol0 + n * 8 + tq * 2;
            int d0 = gi0 - gj;
            int d1 = d0 - 1;
            int d2 = d0 + 8;
            int d3 = d2 - 1;
            S[n][0] = (d0 <= BAND && d0 >= -BAND) ? S[n][0] * SCALE : 0.0f;
            S[n][1] = (d1 <= BAND && d1 >= -BAND) ? S[n][1] * SCALE : 0.0f;
            S[n][2] = (d2 <= BAND && d2 >= -BAND) ? S[n][2] * SCALE : 0.0f;
            S[n][3] = (d3 <= BAND && d3 >= -BAND) ? S[n][3] * SCALE : 0.0f;
        }

        // ---- split S C-frags into phase-B A-frags ----
        uint32_t pah[2][4], pal[2][4];
#pragma unroll
        for (int kc = 0; kc < 2; kc++) {
            split2(S[2 * kc][0],     S[2 * kc][1],     pah[kc][0], pal[kc][0]);
            split2(S[2 * kc][2],     S[2 * kc][3],     pah[kc][1], pal[kc][1]);
            split2(S[2 * kc + 1][0], S[2 * kc + 1][1], pah[kc][2], pal[kc][2]);
            split2(S[2 * kc + 1][2], S[2 * kc + 1][3], pah[kc][3], pal[kc][3]);
        }

        // ---- Phase B: attv += S @ KV (this warp's j-half) ----
#pragma unroll
        for (int kc = 0; kc < 2; kc++) {
            if (!keep[kc]) continue;
#pragma unroll
            for (int dg = 0; dg < 4; dg++) {
                uint32_t off = (uint32_t)(((jcol0 + kc * 16 + tj) * QSTR + dg * 16 + td8) * 2);
                uint32_t vh[4], vl[4];
                LDSM_X4_T(vh[0], vh[1], vh[2], vh[3], khB + off);
                LDSM_X4_T(vl[0], vl[1], vl[2], vl[3], klB + off);
                MMA_BF16(attv[2 * dg],     pah[kc], vh[0], vh[1]);
                MMA_BF16(attv[2 * dg],     pah[kc], vl[0], vl[1]);
                MMA_BF16(attv[2 * dg],     pal[kc], vh[0], vh[1]);
                MMA_BF16(attv[2 * dg + 1], pah[kc], vh[2], vh[3]);
                MMA_BF16(attv[2 * dg + 1], pah[kc], vl[2], vl[3]);
                MMA_BF16(attv[2 * dg + 1], pal[kc], vh[2], vh[3]);
            }
        }
    }

    // ---- cross-warp reduction over wj; att (split bf16) goes to smem ----
    __syncthreads();
    if (wj == 1) {
#pragma unroll
        for (int n = 0; n < 8; n++) {
            int col = n * 8 + tq * 2;
            *reinterpret_cast<float2*>(&red[m_base + g][col])     = make_float2(attv[n][0], attv[n][1]);
            *reinterpret_cast<float2*>(&red[m_base + g + 8][col]) = make_float2(attv[n][2], attv[n][3]);
        }
    }
    __syncthreads();
    if (wj == 0) {
        uint32_t* ath = reinterpret_cast<uint32_t*>(AttH);
        uint32_t* atl = reinterpret_cast<uint32_t*>(AttL);
#pragma unroll
        for (int n = 0; n < 8; n++) {
            int col = n * 8 + tq * 2;
            float2 rr0 = *reinterpret_cast<const float2*>(&red[m_base + g][col]);
            float2 rr1 = *reinterpret_cast<const float2*>(&red[m_base + g + 8][col]);
            int cw = n * 4 + tq;   // word index within row
            uint32_t hw, lw;
            split2(attv[n][0] + rr0.x, attv[n][1] + rr0.y, hw, lw);
            ath[(m_base + g) * (QSTR / 2) + cw] = hw;
            atl[(m_base + g) * (QSTR / 2) + cw] = lw;
            split2(attv[n][2] + rr1.x, attv[n][3] + rr1.y, hw, lw);
            ath[(m_base + g + 8) * (QSTR / 2) + cw] = hw;
            atl[(m_base + g + 8) * (QSTR / 2) + cw] = lw;
        }
    }
    __syncthreads();

    // ---- fused output GEMM: out[64, 512] = att @ Wo + bo ----
    // A-fragments from att smem (persistent across chunks)
    uint32_t oah[4][4], oal[4][4];
#pragma unroll
    for (int kc = 0; kc < 4; kc++) {
        uint32_t off = (uint32_t)(((m_base + a_row) * QSTR + kc * 16 + a_c8) * 2);
        LDSM_X4(oah[kc][0], oah[kc][1], oah[kc][2], oah[kc][3], athB + off);
        LDSM_X4(oal[kc][0], oal[kc][1], oal[kc][2], oal[kc][3], atlB + off);
    }

    const int wn = wj;          // column half within each 128-col chunk
    const int wk = t >> 2;      // Wo loader: k row
    const int seg = (t & 3) * 32;

    // prefetch Wo chunk 0 into registers
    uint4 pwh[4], pwl[4];
    {
        const uint4* sh = reinterpret_cast<const uint4*>(g_woh + (size_t)wk * DIM + seg);
        const uint4* sl = reinterpret_cast<const uint4*>(g_wol + (size_t)wk * DIM + seg);
#pragma unroll
        for (int v = 0; v < 4; v++) { pwh[v] = sh[v]; pwl[v] = sl[v]; }
    }

    const size_t row_g = (size_t)b * SEQ + q0 + m_base + g;

#pragma unroll
    for (int cc = 0; cc < 4; cc++) {
        // store prefetched Wo chunk to smem
        {
            uint4* dh = reinterpret_cast<uint4*>(&WoH[wk * WSTR + seg]);
            uint4* dl = reinterpret_cast<uint4*>(&WoL[wk * WSTR + seg]);
#pragma unroll
            for (int v = 0; v < 4; v++) { dh[v] = pwh[v]; dl[v] = pwl[v]; }
        }
        __syncthreads();
        // prefetch next chunk
        if (cc < 3) {
            const uint4* sh = reinterpret_cast<const uint4*>(
                g_woh + (size_t)wk * DIM + (cc + 1) * 128 + seg);
            const uint4* sl = reinterpret_cast<const uint4*>(
                g_wol + (size_t)wk * DIM + (cc + 1) * 128 + seg);
#pragma unroll
            for (int v = 0; v < 4; v++) { pwh[v] = sh[v]; pwl[v] = sl[v]; }
        }

        float oc[8][4];
#pragma unroll
        for (int n = 0; n < 8; n++)
#pragma unroll
            for (int r = 0; r < 4; r++) oc[n][r] = 0.0f;

#pragma unroll
        for (int kc = 0; kc < 4; kc++) {
#pragma unroll
            for (int dg = 0; dg < 4; dg++) {
                uint32_t off = (uint32_t)(((kc * 16 + tj) * WSTR + wn * 64 + dg * 16 + td8) * 2);
                uint32_t vh[4], vl[4];
                LDSM_X4_T(vh[0], vh[1], vh[2], vh[3], whB + off);
                LDSM_X4_T(vl[0], vl[1], vl[2], vl[3], wlB + off);
                MMA_BF16(oc[2 * dg],     oah[kc], vh[0], vh[1]);
                MMA_BF16(oc[2 * dg],     oah[kc], vl[0], vl[1]);
                MMA_BF16(oc[2 * dg],     oal[kc], vh[0], vh[1]);
                MMA_BF16(oc[2 * dg + 1], oah[kc], vh[2], vh[3]);
                MMA_BF16(oc[2 * dg + 1], oah[kc], vl[2], vl[3]);
                MMA_BF16(oc[2 * dg + 1], oal[kc], vh[2], vh[3]);
            }
        }

        // epilogue: bias + fp32 store for this chunk
#pragma unroll
        for (int n = 0; n < 8; n++) {
            int col = cc * 128 + wn * 64 + n * 8 + tq * 2;
            float b0v = bo[col], b1v = bo[col + 1];
            float2 o0 = {oc[n][0] + b0v, oc[n][1] + b1v};
            float2 o1 = {oc[n][2] + b0v, oc[n][3] + b1v};
            *reinterpret_cast<float2*>(&out[row_g * DIM + col]) = o0;
            *reinterpret_cast<float2*>(&out[(row_g + 8) * DIM + col]) = o1;
        }
        __syncthreads();   // all reads of WoH/WoL done before next overwrite
    }
}

// ---------------------------------------------------------------------------
extern "C" void kernel_launch(void* const* d_in, const int* in_sizes, int n_in,
                              void* d_out, int out_size)
{
    const float* query = (const float*)d_in[0];
    const float* value = (const float*)d_in[1];
    const float* Wi    = (const float*)d_in[2];
    const float* bi    = (const float*)d_in[3];
    const float* Wo    = (const float*)d_in[4];
    const float* bo    = (const float*)d_in[5];
    float* out = (float*)d_out;

    static bool attr_set = false;
    if (!attr_set) {
        cudaFuncSetAttribute(attn_kernel, cudaFuncAttributeMaxDynamicSharedMemorySize,
                             ATTN_SMEM_BYTES);
        attr_set = true;
    }

    proj_kernel<<<MTOT / 64 + 8, 256>>>(query, value, Wi, Wo, bi);
    attn_kernel<<<BATCH * (SEQ / 64), 256, ATTN_SMEM_BYTES>>>(bo, out);
}

// round 12
// speedup vs baseline: 1.4326x; 1.0176x over previous
#include <cuda_runtime.h>
#include <cuda_bf16.h>
#include <cstdint>

// Problem constants (fixed by dataset)
#define BATCH 4
#define SEQ   4096
#define DIM   512
#define DK    64
#define BAND  128
#define SCALE 0.125f            // 1/sqrt(64)
#define ROWS  (BATCH*SEQ)       // 16384
#define MTOT  (2*ROWS)          // 32768 (q rows then kv rows)

// ---- tensor-core helpers ---------------------------------------------------
#define LDSM_X4(r0, r1, r2, r3, addr) \
    asm volatile("ldmatrix.sync.aligned.m8n8.x4.shared.b16 {%0,%1,%2,%3}, [%4];" \
        : "=r"(r0), "=r"(r1), "=r"(r2), "=r"(r3) : "r"(addr))

#define LDSM_X4_T(r0, r1, r2, r3, addr) \
    asm volatile("ldmatrix.sync.aligned.m8n8.x4.trans.shared.b16 {%0,%1,%2,%3}, [%4];" \
        : "=r"(r0), "=r"(r1), "=r"(r2), "=r"(r3) : "r"(addr))

#define MMA_BF16(c, a, b0, b1) \
    asm volatile("mma.sync.aligned.m16n8k16.row.col.f32.bf16.bf16.f32 " \
        "{%0,%1,%2,%3},{%4,%5,%6,%7},{%8,%9},{%0,%1,%2,%3};" \
        : "+f"((c)[0]), "+f"((c)[1]), "+f"((c)[2]), "+f"((c)[3]) \
        : "r"((a)[0]), "r"((a)[1]), "r"((a)[2]), "r"((a)[3]), "r"(b0), "r"(b1))

#define CP_ASYNC16(dst_u32, src_ptr) \
    asm volatile("cp.async.cg.shared.global [%0], [%1], 16;" \
        :: "r"(dst_u32), "l"(src_ptr) : "memory")
#define CP_COMMIT() asm volatile("cp.async.commit_group;" ::: "memory")
#define CP_WAIT(N)  asm volatile("cp.async.wait_group %0;" :: "n"(N) : "memory")

__device__ __forceinline__ uint32_t pack_bf16x2(__nv_bfloat16 a, __nv_bfloat16 b) {
    __nv_bfloat162 p;
    p.x = a; p.y = b;
    return *reinterpret_cast<uint32_t*>(&p);
}
// split two f32 into (hi, lo) bf16x2 words
__device__ __forceinline__ void split2(float x0, float x1, uint32_t& hw, uint32_t& lw) {
    __nv_bfloat16 h0 = __float2bfloat16(x0);
    __nv_bfloat16 h1 = __float2bfloat16(x1);
    __nv_bfloat16 l0 = __float2bfloat16(x0 - __bfloat162float(h0));
    __nv_bfloat16 l1 = __float2bfloat16(x1 - __bfloat162float(h1));
    hw = pack_bf16x2(h0, h1);
    lw = pack_bf16x2(l0, l1);
}

// Scratch (device globals; no allocation allowed). All split bf16 hi/lo pairs.
__device__ __nv_bfloat16 g_qh[ROWS * DK];
__device__ __nv_bfloat16 g_ql[ROWS * DK];
__device__ __nv_bfloat16 g_kvh[ROWS * DK];
__device__ __nv_bfloat16 g_kvl[ROWS * DK];
__device__ __nv_bfloat16 g_woh[DK * DIM];    // Wo split: [k=64][n=512]
__device__ __nv_bfloat16 g_wol[DK * DIM];

// ---------------------------------------------------------------------------
// Kernel 1: shared input projection via split-bf16 MMA, K-chunks of 64,
// double-buffered smem + 1-deep register prefetch. 8 tail CTAs split Wo.
// CTA: 64 rows x 64 cols, 256 threads = 8 warps (wm 0..3 m16, wn 0..1 n32).
// ---------------------------------------------------------------------------
#define PSTR 72   // bf16 stride (64 data + 8 pad); 16B-granule stride 9 -> conflict-free
#define PBUF_ELEMS (64 * PSTR)               // 4608
#define PROJ_SMEM_BYTES (8 * PBUF_ELEMS * 2) // Ah[2],Al[2],Wh[2],Wl[2] = 73728 B

__global__ void __launch_bounds__(256) proj_kernel(const float* __restrict__ query,
                                                   const float* __restrict__ value,
                                                   const float* __restrict__ Wi,
                                                   const float* __restrict__ Wo,
                                                   const float* __restrict__ bi)
{
    const int t    = threadIdx.x;
    const int row0 = blockIdx.x * 64;

    // ---- tail CTAs: split Wo once ----
    if (row0 >= MTOT) {
        int base = (blockIdx.x - (MTOT / 64)) * 4096 + t * 16;
        const float4* wp = reinterpret_cast<const float4*>(Wo + base);
        uint32_t hw[8], lw[8];
#pragma unroll
        for (int v = 0; v < 4; v++) {
            float4 f = wp[v];
            split2(f.x, f.y, hw[2 * v],     lw[2 * v]);
            split2(f.z, f.w, hw[2 * v + 1], lw[2 * v + 1]);
        }
        uint4* dh = reinterpret_cast<uint4*>(g_woh + base);
        uint4* dl = reinterpret_cast<uint4*>(g_wol + base);
        dh[0] = make_uint4(hw[0], hw[1], hw[2], hw[3]);
        dh[1] = make_uint4(hw[4], hw[5], hw[6], hw[7]);
        dl[0] = make_uint4(lw[0], lw[1], lw[2], lw[3]);
        dl[1] = make_uint4(lw[4], lw[5], lw[6], lw[7]);
        return;
    }

    extern __shared__ __align__(16) __nv_bfloat16 psmem[];
    __nv_bfloat16* Ah = psmem;                    // [2][PBUF_ELEMS]
    __nv_bfloat16* Al = psmem + 2 * PBUF_ELEMS;
    __nv_bfloat16* Wh = psmem + 4 * PBUF_ELEMS;   // [n][k]
    __nv_bfloat16* Wl = psmem + 6 * PBUF_ELEMS;

    const int lane = t & 31;
    const int warp = t >> 5;

    const float* src;
    uint32_t* dsth;
    uint32_t* dstl;
    int roff;
    if (row0 < ROWS) {
        src = query;
        dsth = reinterpret_cast<uint32_t*>(g_qh);
        dstl = reinterpret_cast<uint32_t*>(g_ql);
        roff = row0;
    } else {
        src = value;
        dsth = reinterpret_cast<uint32_t*>(g_kvh);
        dstl = reinterpret_cast<uint32_t*>(g_kvl);
        roff = row0 - ROWS;
    }

    const int wm = warp & 3;
    const int wn = warp >> 2;
    const int m_base = wm * 16;
    const int n_base = wn * 32;

    // A loader: 64 rows x 64 k fp32, each thread 16 fp32 (4 float4) of one row
    const int lr = t >> 2;
    const int ls = (t & 3) * 16;
    // W loader: col wcol, 16 consecutive k (strided source reads)
    const int wcol = t & 63;
    const int wkg  = (t >> 6) * 16;

    // ldmatrix lane addressing
    const int a_row = lane & 15;
    const int a_c8  = (lane >> 4) * 8;
    const int b_row = (lane & 7) + ((lane >> 4) & 1) * 8;
    const int b_c8  = ((lane >> 3) & 1) * 8;

    const uint32_t ahB0 = (uint32_t)__cvta_generic_to_shared(Ah);
    const uint32_t alB0 = (uint32_t)__cvta_generic_to_shared(Al);
    const uint32_t whB0 = (uint32_t)__cvta_generic_to_shared(Wh);
    const uint32_t wlB0 = (uint32_t)__cvta_generic_to_shared(Wl);
    const uint32_t bufBytes = PBUF_ELEMS * 2;

    float c[4][4];
#pragma unroll
    for (int n = 0; n < 4; n++)
#pragma unroll
        for (int r = 0; r < 4; r++) c[n][r] = 0.0f;

    // 1-deep register prefetch
    float4 fA[4];
    float wv[16];

    const float* arow_p = src + (size_t)(roff + lr) * DIM + ls;

    // load chunk 0
    {
        const float4* ap = reinterpret_cast<const float4*>(arow_p);
#pragma unroll
        for (int v = 0; v < 4; v++) fA[v] = ap[v];
        const float* wp = Wi + (size_t)wkg * DK + wcol;
#pragma unroll
        for (int j = 0; j < 16; j++) wv[j] = wp[j * DK];
    }

    for (int k0i = 0; k0i < 8; k0i++) {
        const int buf = k0i & 1;
        // split + store prefetched chunk into smem[buf]
        {
            uint32_t hw[8], lw[8];
#pragma unroll
            for (int v = 0; v < 4; v++) {
                split2(fA[v].x, fA[v].y, hw[2 * v],     lw[2 * v]);
                split2(fA[v].z, fA[v].w, hw[2 * v + 1], lw[2 * v + 1]);
            }
            int wo = lr * (PSTR / 2) + (ls >> 1);
            uint32_t* ahW = reinterpret_cast<uint32_t*>(Ah + buf * PBUF_ELEMS);
            uint32_t* alW = reinterpret_cast<uint32_t*>(Al + buf * PBUF_ELEMS);
            *reinterpret_cast<uint4*>(ahW + wo)     = make_uint4(hw[0], hw[1], hw[2], hw[3]);
            *reinterpret_cast<uint4*>(ahW + wo + 4) = make_uint4(hw[4], hw[5], hw[6], hw[7]);
            *reinterpret_cast<uint4*>(alW + wo)     = make_uint4(lw[0], lw[1], lw[2], lw[3]);
            *reinterpret_cast<uint4*>(alW + wo + 4) = make_uint4(lw[4], lw[5], lw[6], lw[7]);
#pragma unroll
            for (int v = 0; v < 8; v++) split2(wv[2 * v], wv[2 * v + 1], hw[v], lw[v]);
            int wo2 = wcol * (PSTR / 2) + (wkg >> 1);
            uint32_t* whW = reinterpret_cast<uint32_t*>(Wh + buf * PBUF_ELEMS);
            uint32_t* wlW = reinterpret_cast<uint32_t*>(Wl + buf * PBUF_ELEMS);
            *reinterpret_cast<uint4*>(whW + wo2)     = make_uint4(hw[0], hw[1], hw[2], hw[3]);
            *reinterpret_cast<uint4*>(whW + wo2 + 4) = make_uint4(hw[4], hw[5], hw[6], hw[7]);
            *reinterpret_cast<uint4*>(wlW + wo2)     = make_uint4(lw[0], lw[1], lw[2], lw[3]);
            *reinterpret_cast<uint4*>(wlW + wo2 + 4) = make_uint4(lw[4], lw[5], lw[6], lw[7]);
        }
        __syncthreads();

        // issue global loads for next chunk (overlap with MMA below)
        if (k0i < 7) {
            int k0 = (k0i + 1) * 64;
            const float4* ap = reinterpret_cast<const float4*>(arow_p + k0);
#pragma unroll
            for (int v = 0; v < 4; v++) fA[v] = ap[v];
            const float* wp = Wi + (size_t)(k0 + wkg) * DK + wcol;
#pragma unroll
            for (int j = 0; j < 16; j++) wv[j] = wp[j * DK];
        }

        const uint32_t ahB = ahB0 + buf * bufBytes;
        const uint32_t alB = alB0 + buf * bufBytes;
        const uint32_t whB = whB0 + buf * bufBytes;
        const uint32_t wlB = wlB0 + buf * bufBytes;

#pragma unroll
        for (int ks = 0; ks < 64; ks += 16) {
            uint32_t ah[4], al[4];
            {
                uint32_t off = (uint32_t)(((m_base + a_row) * PSTR + ks + a_c8) * 2);
                LDSM_X4(ah[0], ah[1], ah[2], ah[3], ahB + off);
                LDSM_X4(al[0], al[1], al[2], al[3], alB + off);
            }
            uint32_t bh[8], bl[8];
            {
                uint32_t off0 = (uint32_t)(((n_base + b_row) * PSTR + ks + b_c8) * 2);
                uint32_t off1 = off0 + 16 * PSTR * 2;
                LDSM_X4(bh[0], bh[1], bh[2], bh[3], whB + off0);
                LDSM_X4(bh[4], bh[5], bh[6], bh[7], whB + off1);
                LDSM_X4(bl[0], bl[1], bl[2], bl[3], wlB + off0);
                LDSM_X4(bl[4], bl[5], bl[6], bl[7], wlB + off1);
            }
#pragma unroll
            for (int n = 0; n < 4; n++) {
                MMA_BF16(c[n], ah, bh[2 * n], bh[2 * n + 1]);
                MMA_BF16(c[n], ah, bl[2 * n], bl[2 * n + 1]);
                MMA_BF16(c[n], al, bh[2 * n], bh[2 * n + 1]);
            }
        }
    }

    // epilogue: add bias, split to bf16 hi/lo, store packed words
    const int g = lane >> 2, tig = lane & 3;
    {
        int row = roff + m_base + g;
#pragma unroll
        for (int n = 0; n < 4; n++) {
            int col = n_base + n * 8 + tig * 2;
            float b0v = bi[col], b1v = bi[col + 1];
            uint32_t hw, lw;
            split2(c[n][0] + b0v, c[n][1] + b1v, hw, lw);
            dsth[(size_t)row * 32 + (col >> 1)] = hw;
            dstl[(size_t)row * 32 + (col >> 1)] = lw;
            split2(c[n][2] + b0v, c[n][3] + b1v, hw, lw);
            dsth[(size_t)(row + 8) * 32 + (col >> 1)] = hw;
            dstl[(size_t)(row + 8) * 32 + (col >> 1)] = lw;
        }
    }
}

// ---------------------------------------------------------------------------
// Kernel 2: banded attention + fused output projection.
// K tiles cp.async double-buffered: copy of tile it+1 overlaps compute of it.
// ---------------------------------------------------------------------------
#define QSTR 72    // bf16 stride for 64-wide tiles
#define WSTR 136   // bf16 stride for 128-wide Wo chunks
#define KBUF_BYTES (64 * QSTR * 2)   // 9216
// smem byte offsets
#define Q_OFF    0            // Qh 9216 | Ql 9216
#define K_OFF    18432        // Kh[2] 18432 | Kl[2] 18432
#define RED_OFF  55296        // float red[64][66] = 16896
#define ATT_OFF  72192        // AttH 9216 | AttL 9216
#define ATTN_SMEM_BYTES 90624
// Wo chunk aliases the Q/K region: WoH @0 (17408B), WoL @17408

__global__ void __launch_bounds__(256) attn_kernel(const float* __restrict__ bo,
                                                   float* __restrict__ out)
{
    extern __shared__ __align__(16) char asmem[];
    __nv_bfloat16* Qh = reinterpret_cast<__nv_bfloat16*>(asmem + Q_OFF);
    __nv_bfloat16* Ql = Qh + 64 * QSTR;
    float (*red)[66]  = reinterpret_cast<float(*)[66]>(asmem + RED_OFF);
    __nv_bfloat16* AttH = reinterpret_cast<__nv_bfloat16*>(asmem + ATT_OFF);
    __nv_bfloat16* AttL = AttH + 64 * QSTR;
    __nv_bfloat16* WoH = reinterpret_cast<__nv_bfloat16*>(asmem);           // alias
    __nv_bfloat16* WoL = reinterpret_cast<__nv_bfloat16*>(asmem + 17408);   // alias

    const int t    = threadIdx.x;
    const int lane = t & 31;
    const int warp = t >> 5;
    const int b    = blockIdx.x >> 6;
    const int qs   = blockIdx.x & 63;
    const int q0   = qs * 64;

    const int wm = warp & 3;
    const int wj = warp >> 2;
    const int m_base = wm * 16;
    const int jcol0  = wj * 32;

    const uint32_t qhB = (uint32_t)__cvta_generic_to_shared(Qh);
    const uint32_t qlB = (uint32_t)__cvta_generic_to_shared(Ql);
    const uint32_t smemB = (uint32_t)__cvta_generic_to_shared(asmem);
    const uint32_t athB = (uint32_t)__cvta_generic_to_shared(AttH);
    const uint32_t atlB = (uint32_t)__cvta_generic_to_shared(AttL);
    const uint32_t whB = (uint32_t)__cvta_generic_to_shared(WoH);
    const uint32_t wlB = (uint32_t)__cvta_generic_to_shared(WoL);

    // loaders: rows r0 & r0+32, 16B segment s0
    const int r0 = t >> 3;
    const int s0 = t & 7;

    // ---- prologue: cp.async Q tile (group 0), K tile 0 (group 1) ----
    {
        size_t gb0 = ((size_t)b * SEQ + q0 + r0) * DK + s0 * 8;
        size_t gb1 = gb0 + (size_t)32 * DK;
        uint32_t d0 = r0 * QSTR * 2 + s0 * 16;
        uint32_t d1 = (r0 + 32) * QSTR * 2 + s0 * 16;
        CP_ASYNC16(qhB + d0, g_qh + gb0);
        CP_ASYNC16(qhB + d1, g_qh + gb1);
        CP_ASYNC16(qlB + d0, g_ql + gb0);
        CP_ASYNC16(qlB + d1, g_ql + gb1);
    }
    CP_COMMIT();

    // build valid tile list
    int tiles[5];
    int nt = 0;
    for (int jt = qs - 2; jt <= qs + 2; jt++)
        if (jt >= 0 && jt < 64) tiles[nt++] = jt;

    // issue K tile 0 into buf 0
    {
        size_t gb0 = ((size_t)b * SEQ + tiles[0] * 64 + r0) * DK + s0 * 8;
        size_t gb1 = gb0 + (size_t)32 * DK;
        uint32_t kh = smemB + K_OFF;
        uint32_t kl = smemB + K_OFF + 2 * KBUF_BYTES;
        uint32_t d0 = r0 * QSTR * 2 + s0 * 16;
        uint32_t d1 = (r0 + 32) * QSTR * 2 + s0 * 16;
        CP_ASYNC16(kh + d0, g_kvh + gb0);
        CP_ASYNC16(kh + d1, g_kvh + gb1);
        CP_ASYNC16(kl + d0, g_kvl + gb0);
        CP_ASYNC16(kl + d1, g_kvl + gb1);
    }
    CP_COMMIT();

    CP_WAIT(1);          // Q complete (K0 may still be in flight)
    __syncthreads();

    // ldmatrix lane addressing
    const int a_row = lane & 15;
    const int a_c8  = (lane >> 4) * 8;
    const int b_row = (lane & 7) + ((lane >> 4) & 1) * 8;
    const int b_c8  = ((lane >> 3) & 1) * 8;
    const int tj    = (lane & 7) + ((lane >> 3) & 1) * 8;
    const int td8   = (lane >> 4) * 8;

    // Q a-fragments: persistent across all j-tiles
    uint32_t qha[4][4], qla[4][4];
#pragma unroll
    for (int kc = 0; kc < 4; kc++) {
        uint32_t off = (uint32_t)(((m_base + a_row) * QSTR + kc * 16 + a_c8) * 2);
        LDSM_X4(qha[kc][0], qha[kc][1], qha[kc][2], qha[kc][3], qhB + off);
        LDSM_X4(qla[kc][0], qla[kc][1], qla[kc][2], qla[kc][3], qlB + off);
    }

    float attv[8][4];
#pragma unroll
    for (int n = 0; n < 8; n++)
#pragma unroll
        for (int r = 0; r < 4; r++) attv[n][r] = 0.0f;

    const int g = lane >> 2, tq = lane & 3;
    const int gi_lo = q0 + m_base;
    const int gi_hi = gi_lo + 15;

    for (int it = 0; it < nt; it++) {
        const int jt  = tiles[it];
        const int cur = it & 1;
        CP_WAIT(0);          // tile it resident
        __syncthreads();     // visible to all; all warps done reading other buf

        // issue cp.async for tile it+1 into the other buffer (overlaps compute)
        if (it + 1 < nt) {
            size_t gb0 = ((size_t)b * SEQ + tiles[it + 1] * 64 + r0) * DK + s0 * 8;
            size_t gb1 = gb0 + (size_t)32 * DK;
            uint32_t kh = smemB + K_OFF + (cur ^ 1) * KBUF_BYTES;
            uint32_t kl = smemB + K_OFF + 2 * KBUF_BYTES + (cur ^ 1) * KBUF_BYTES;
            uint32_t d0 = r0 * QSTR * 2 + s0 * 16;
            uint32_t d1 = (r0 + 32) * QSTR * 2 + s0 * 16;
            CP_ASYNC16(kh + d0, g_kvh + gb0);
            CP_ASYNC16(kh + d1, g_kvh + gb1);
            CP_ASYNC16(kl + d0, g_kvl + gb0);
            CP_ASYNC16(kl + d1, g_kvl + gb1);
            CP_COMMIT();
        }

        const uint32_t khB = smemB + K_OFF + cur * KBUF_BYTES;
        const uint32_t klB = smemB + K_OFF + 2 * KBUF_BYTES + cur * KBUF_BYTES;
        const int jbase = jt * 64;

        // block in-band predicates for this warp's two 16-wide j blocks
        bool keep[2];
#pragma unroll
        for (int blk = 0; blk < 2; blk++) {
            int jlo = jbase + jcol0 + blk * 16;
            keep[blk] = !(gi_lo - (jlo + 15) > BAND || jlo - gi_hi > BAND);
        }

        // ---- Phase A: S (m16 x n32) = Q K^T, 3-term split ----
        float S[4][4];
#pragma unroll
        for (int n = 0; n < 4; n++)
#pragma unroll
            for (int r = 0; r < 4; r++) S[n][r] = 0.0f;

#pragma unroll
        for (int kc = 0; kc < 4; kc++) {
#pragma unroll
            for (int ng = 0; ng < 2; ng++) {
                if (!keep[ng]) continue;
                uint32_t off = (uint32_t)(((jcol0 + ng * 16 + b_row) * QSTR + kc * 16 + b_c8) * 2);
                uint32_t bh[4], bl[4];
                LDSM_X4(bh[0], bh[1], bh[2], bh[3], khB + off);
                LDSM_X4(bl[0], bl[1], bl[2], bl[3], klB + off);
                MMA_BF16(S[2 * ng],     qha[kc], bh[0], bh[1]);
                MMA_BF16(S[2 * ng],     qha[kc], bl[0], bl[1]);
                MMA_BF16(S[2 * ng],     qla[kc], bh[0], bh[1]);
                MMA_BF16(S[2 * ng + 1], qha[kc], bh[2], bh[3]);
                MMA_BF16(S[2 * ng + 1], qha[kc], bl[2], bl[3]);
                MMA_BF16(S[2 * ng + 1], qla[kc], bh[2], bh[3]);
            }
        }

        // ---- mask + scale in registers ----
        const int gi0 = gi_lo + g;
#pragma unroll
        for (int n = 0; n < 4; n++) {
            int gj = jbase + jcol0 + n * 8 + tq * 2;
            int d0 = gi0 - gj;
            int d1 = d0 - 1;
            int d2 = d0 + 8;
            int d3 = d2 - 1;
            S[n][0] = (d0 <= BAND && d0 >= -BAND) ? S[n][0] * SCALE : 0.0f;
            S[n][1] = (d1 <= BAND && d1 >= -BAND) ? S[n][1] * SCALE : 0.0f;
            S[n][2] = (d2 <= BAND && d2 >= -BAND) ? S[n][2] * SCALE : 0.0f;
            S[n][3] = (d3 <= BAND && d3 >= -BAND) ? S[n][3] * SCALE : 0.0f;
        }

        // ---- split S C-frags into phase-B A-frags ----
        uint32_t pah[2][4], pal[2][4];
#pragma unroll
        for (int kc = 0; kc < 2; kc++) {
            split2(S[2 * kc][0],     S[2 * kc][1],     pah[kc][0], pal[kc][0]);
            split2(S[2 * kc][2],     S[2 * kc][3],     pah[kc][1], pal[kc][1]);
            split2(S[2 * kc + 1][0], S[2 * kc + 1][1], pah[kc][2], pal[kc][2]);
            split2(S[2 * kc + 1][2], S[2 * kc + 1][3], pah[kc][3], pal[kc][3]);
        }

        // ---- Phase B: attv += S @ KV (this warp's j-half) ----
#pragma unroll
        for (int kc = 0; kc < 2; kc++) {
            if (!keep[kc]) continue;
#pragma unroll
            for (int dg = 0; dg < 4; dg++) {
                uint32_t off = (uint32_t)(((jcol0 + kc * 16 + tj) * QSTR + dg * 16 + td8) * 2);
                uint32_t vh[4], vl[4];
                LDSM_X4_T(vh[0], vh[1], vh[2], vh[3], khB + off);
                LDSM_X4_T(vl[0], vl[1], vl[2], vl[3], klB + off);
                MMA_BF16(attv[2 * dg],     pah[kc], vh[0], vh[1]);
                MMA_BF16(attv[2 * dg],     pah[kc], vl[0], vl[1]);
                MMA_BF16(attv[2 * dg],     pal[kc], vh[0], vh[1]);
                MMA_BF16(attv[2 * dg + 1], pah[kc], vh[2], vh[3]);
                MMA_BF16(attv[2 * dg + 1], pah[kc], vl[2], vl[3]);
                MMA_BF16(attv[2 * dg + 1], pal[kc], vh[2], vh[3]);
            }
        }
    }

    // ---- cross-warp reduction over wj; att (split bf16) goes to smem ----
    __syncthreads();
    if (wj == 1) {
#pragma unroll
        for (int n = 0; n < 8; n++) {
            int col = n * 8 + tq * 2;
            *reinterpret_cast<float2*>(&red[m_base + g][col])     = make_float2(attv[n][0], attv[n][1]);
            *reinterpret_cast<float2*>(&red[m_base + g + 8][col]) = make_float2(attv[n][2], attv[n][3]);
        }
    }
    __syncthreads();
    if (wj == 0) {
        uint32_t* ath = reinterpret_cast<uint32_t*>(AttH);
        uint32_t* atl = reinterpret_cast<uint32_t*>(AttL);
#pragma unroll
        for (int n = 0; n < 8; n++) {
            int col = n * 8 + tq * 2;
            float2 rr0 = *reinterpret_cast<const float2*>(&red[m_base + g][col]);
            float2 rr1 = *reinterpret_cast<const float2*>(&red[m_base + g + 8][col]);
            int cw = n * 4 + tq;   // word index within row
            uint32_t hw, lw;
            split2(attv[n][0] + rr0.x, attv[n][1] + rr0.y, hw, lw);
            ath[(m_base + g) * (QSTR / 2) + cw] = hw;
            atl[(m_base + g) * (QSTR / 2) + cw] = lw;
            split2(attv[n][2] + rr1.x, attv[n][3] + rr1.y, hw, lw);
            ath[(m_base + g + 8) * (QSTR / 2) + cw] = hw;
            atl[(m_base + g + 8) * (QSTR / 2) + cw] = lw;
        }
    }
    __syncthreads();

    // ---- fused output GEMM: out[64, 512] = att @ Wo + bo ----
    uint32_t oah[4][4], oal[4][4];
#pragma unroll
    for (int kc = 0; kc < 4; kc++) {
        uint32_t off = (uint32_t)(((m_base + a_row) * QSTR + kc * 16 + a_c8) * 2);
        LDSM_X4(oah[kc][0], oah[kc][1], oah[kc][2], oah[kc][3], athB + off);
        LDSM_X4(oal[kc][0], oal[kc][1], oal[kc][2], oal[kc][3], atlB + off);
    }

    const int wn = wj;          // column half within each 128-col chunk
    const int wk = t >> 2;      // Wo loader: k row
    const int seg = (t & 3) * 32;

    // prefetch Wo chunk 0 into registers
    uint4 pwh[4], pwl[4];
    {
        const uint4* sh = reinterpret_cast<const uint4*>(g_woh + (size_t)wk * DIM + seg);
        const uint4* sl = reinterpret_cast<const uint4*>(g_wol + (size_t)wk * DIM + seg);
#pragma unroll
        for (int v = 0; v < 4; v++) { pwh[v] = sh[v]; pwl[v] = sl[v]; }
    }

    const size_t row_g = (size_t)b * SEQ + q0 + m_base + g;

#pragma unroll
    for (int cc = 0; cc < 4; cc++) {
        // store prefetched Wo chunk to smem
        {
            uint4* dh = reinterpret_cast<uint4*>(&WoH[wk * WSTR + seg]);
            uint4* dl = reinterpret_cast<uint4*>(&WoL[wk * WSTR + seg]);
#pragma unroll
            for (int v = 0; v < 4; v++) { dh[v] = pwh[v]; dl[v] = pwl[v]; }
        }
        __syncthreads();
        // prefetch next chunk
        if (cc < 3) {
            const uint4* sh = reinterpret_cast<const uint4*>(
                g_woh + (size_t)wk * DIM + (cc + 1) * 128 + seg);
            const uint4* sl = reinterpret_cast<const uint4*>(
                g_wol + (size_t)wk * DIM + (cc + 1) * 128 + seg);
#pragma unroll
            for (int v = 0; v < 4; v++) { pwh[v] = sh[v]; pwl[v] = sl[v]; }
        }

        float oc[8][4];
#pragma unroll
        for (int n = 0; n < 8; n++)
#pragma unroll
            for (int r = 0; r < 4; r++) oc[n][r] = 0.0f;

#pragma unroll
        for (int kc = 0; kc < 4; kc++) {
#pragma unroll
            for (int dg = 0; dg < 4; dg++) {
                uint32_t off = (uint32_t)(((kc * 16 + tj) * WSTR + wn * 64 + dg * 16 + td8) * 2);
                uint32_t vh[4], vl[4];
                LDSM_X4_T(vh[0], vh[1], vh[2], vh[3], whB + off);
                LDSM_X4_T(vl[0], vl[1], vl[2], vl[3], wlB + off);
                MMA_BF16(oc[2 * dg],     oah[kc], vh[0], vh[1]);
                MMA_BF16(oc[2 * dg],     oah[kc], vl[0], vl[1]);
                MMA_BF16(oc[2 * dg],     oal[kc], vh[0], vh[1]);
                MMA_BF16(oc[2 * dg + 1], oah[kc], vh[2], vh[3]);
                MMA_BF16(oc[2 * dg + 1], oah[kc], vl[2], vl[3]);
                MMA_BF16(oc[2 * dg + 1], oal[kc], vh[2], vh[3]);
            }
        }

        // epilogue: bias + fp32 store for this chunk
#pragma unroll
        for (int n = 0; n < 8; n++) {
            int col = cc * 128 + wn * 64 + n * 8 + tq * 2;
            float b0v = bo[col], b1v = bo[col + 1];
            float2 o0 = {oc[n][0] + b0v, oc[n][1] + b1v};
            float2 o1 = {oc[n][2] + b0v, oc[n][3] + b1v};
            *reinterpret_cast<float2*>(&out[row_g * DIM + col]) = o0;
            *reinterpret_cast<float2*>(&out[(row_g + 8) * DIM + col]) = o1;
        }
        __syncthreads();   // all reads of WoH/WoL done before next overwrite
    }
}

// ---------------------------------------------------------------------------
extern "C" void kernel_launch(void* const* d_in, const int* in_sizes, int n_in,
                              void* d_out, int out_size)
{
    const float* query = (const float*)d_in[0];
    const float* value = (const float*)d_in[1];
    const float* Wi    = (const float*)d_in[2];
    const float* bi    = (const float*)d_in[3];
    const float* Wo    = (const float*)d_in[4];
    const float* bo    = (const float*)d_in[5];
    float* out = (float*)d_out;

    static bool attr_set = false;
    if (!attr_set) {
        cudaFuncSetAttribute(proj_kernel, cudaFuncAttributeMaxDynamicSharedMemorySize,
                             PROJ_SMEM_BYTES);
        cudaFuncSetAttribute(attn_kernel, cudaFuncAttributeMaxDynamicSharedMemorySize,
                             ATTN_SMEM_BYTES);
        attr_set = true;
    }

    proj_kernel<<<MTOT / 64 + 8, 256, PROJ_SMEM_BYTES>>>(query, value, Wi, Wo, bi);
    attn_kernel<<<BATCH * (SEQ / 64), 256, ATTN_SMEM_BYTES>>>(bo, out);
}

// round 13
// speedup vs baseline: 1.4485x; 1.0111x over previous
#include <cuda_runtime.h>
#include <cuda_bf16.h>
#include <cstdint>

// Problem constants (fixed by dataset)
#define BATCH 4
#define SEQ   4096
#define DIM   512
#define DK    64
#define BAND  128
#define SCALE 0.125f            // 1/sqrt(64)
#define ROWS  (BATCH*SEQ)       // 16384
#define MTOT  (2*ROWS)          // 32768 (q rows then kv rows)

// ---- tensor-core helpers ---------------------------------------------------
#define LDSM_X4(r0, r1, r2, r3, addr) \
    asm volatile("ldmatrix.sync.aligned.m8n8.x4.shared.b16 {%0,%1,%2,%3}, [%4];" \
        : "=r"(r0), "=r"(r1), "=r"(r2), "=r"(r3) : "r"(addr))

#define LDSM_X4_T(r0, r1, r2, r3, addr) \
    asm volatile("ldmatrix.sync.aligned.m8n8.x4.trans.shared.b16 {%0,%1,%2,%3}, [%4];" \
        : "=r"(r0), "=r"(r1), "=r"(r2), "=r"(r3) : "r"(addr))

// NOT volatile: pure register ops; lets ptxas interleave independent MMA chains.
#define MMA_BF16(c, a, b0, b1) \
    asm("mma.sync.aligned.m16n8k16.row.col.f32.bf16.bf16.f32 " \
        "{%0,%1,%2,%3},{%4,%5,%6,%7},{%8,%9},{%0,%1,%2,%3};" \
        : "+f"((c)[0]), "+f"((c)[1]), "+f"((c)[2]), "+f"((c)[3]) \
        : "r"((a)[0]), "r"((a)[1]), "r"((a)[2]), "r"((a)[3]), "r"(b0), "r"(b1))

#define CP_ASYNC16(dst_u32, src_ptr) \
    asm volatile("cp.async.cg.shared.global [%0], [%1], 16;" \
        :: "r"(dst_u32), "l"(src_ptr) : "memory")
#define CP_COMMIT() asm volatile("cp.async.commit_group;" ::: "memory")
#define CP_WAIT(N)  asm volatile("cp.async.wait_group %0;" :: "n"(N) : "memory")

__device__ __forceinline__ uint32_t pack_bf16x2(__nv_bfloat16 a, __nv_bfloat16 b) {
    __nv_bfloat162 p;
    p.x = a; p.y = b;
    return *reinterpret_cast<uint32_t*>(&p);
}
// split two f32 into (hi, lo) bf16x2 words
__device__ __forceinline__ void split2(float x0, float x1, uint32_t& hw, uint32_t& lw) {
    __nv_bfloat16 h0 = __float2bfloat16(x0);
    __nv_bfloat16 h1 = __float2bfloat16(x1);
    __nv_bfloat16 l0 = __float2bfloat16(x0 - __bfloat162float(h0));
    __nv_bfloat16 l1 = __float2bfloat16(x1 - __bfloat162float(h1));
    hw = pack_bf16x2(h0, h1);
    lw = pack_bf16x2(l0, l1);
}

// Scratch (device globals; no allocation allowed). All split bf16 hi/lo pairs.
__device__ __nv_bfloat16 g_qh[ROWS * DK];
__device__ __nv_bfloat16 g_ql[ROWS * DK];
__device__ __nv_bfloat16 g_kvh[ROWS * DK];
__device__ __nv_bfloat16 g_kvl[ROWS * DK];
__device__ __nv_bfloat16 g_woh[DK * DIM];    // Wo split: [k=64][n=512]
__device__ __nv_bfloat16 g_wol[DK * DIM];

// ---------------------------------------------------------------------------
// Kernel 1: shared input projection via split-bf16 MMA, K-chunks of 64,
// double-buffered smem + 1-deep register prefetch. 8 tail CTAs split Wo.
// CTA: 64 rows x 64 cols, 256 threads = 8 warps (wm 0..3 m16, wn 0..1 n32).
// ---------------------------------------------------------------------------
#define PSTR 72   // bf16 stride (64 data + 8 pad)
#define PBUF_ELEMS (64 * PSTR)               // 4608
#define PROJ_SMEM_BYTES (8 * PBUF_ELEMS * 2) // Ah[2],Al[2],Wh[2],Wl[2] = 73728 B

__global__ void __launch_bounds__(256) proj_kernel(const float* __restrict__ query,
                                                   const float* __restrict__ value,
                                                   const float* __restrict__ Wi,
                                                   const float* __restrict__ Wo,
                                                   const float* __restrict__ bi)
{
    const int t    = threadIdx.x;
    const int row0 = blockIdx.x * 64;

    // ---- tail CTAs: split Wo once ----
    if (row0 >= MTOT) {
        int base = (blockIdx.x - (MTOT / 64)) * 4096 + t * 16;
        const float4* wp = reinterpret_cast<const float4*>(Wo + base);
        uint32_t hw[8], lw[8];
#pragma unroll
        for (int v = 0; v < 4; v++) {
            float4 f = wp[v];
            split2(f.x, f.y, hw[2 * v],     lw[2 * v]);
            split2(f.z, f.w, hw[2 * v + 1], lw[2 * v + 1]);
        }
        uint4* dh = reinterpret_cast<uint4*>(g_woh + base);
        uint4* dl = reinterpret_cast<uint4*>(g_wol + base);
        dh[0] = make_uint4(hw[0], hw[1], hw[2], hw[3]);
        dh[1] = make_uint4(hw[4], hw[5], hw[6], hw[7]);
        dl[0] = make_uint4(lw[0], lw[1], lw[2], lw[3]);
        dl[1] = make_uint4(lw[4], lw[5], lw[6], lw[7]);
        return;
    }

    extern __shared__ __align__(16) __nv_bfloat16 psmem[];
    __nv_bfloat16* Ah = psmem;                    // [2][PBUF_ELEMS]
    __nv_bfloat16* Al = psmem + 2 * PBUF_ELEMS;
    __nv_bfloat16* Wh = psmem + 4 * PBUF_ELEMS;   // [n][k]
    __nv_bfloat16* Wl = psmem + 6 * PBUF_ELEMS;

    const int lane = t & 31;
    const int warp = t >> 5;

    const float* src;
    uint32_t* dsth;
    uint32_t* dstl;
    int roff;
    if (row0 < ROWS) {
        src = query;
        dsth = reinterpret_cast<uint32_t*>(g_qh);
        dstl = reinterpret_cast<uint32_t*>(g_ql);
        roff = row0;
    } else {
        src = value;
        dsth = reinterpret_cast<uint32_t*>(g_kvh);
        dstl = reinterpret_cast<uint32_t*>(g_kvl);
        roff = row0 - ROWS;
    }

    const int wm = warp & 3;
    const int wn = warp >> 2;
    const int m_base = wm * 16;
    const int n_base = wn * 32;

    // A loader: 64 rows x 64 k fp32, each thread 16 fp32 (4 float4) of one row
    const int lr = t >> 2;
    const int ls = (t & 3) * 16;
    // W loader: col wcol, 16 consecutive k (strided source reads)
    const int wcol = t & 63;
    const int wkg  = (t >> 6) * 16;

    // ldmatrix lane addressing
    const int a_row = lane & 15;
    const int a_c8  = (lane >> 4) * 8;
    const int b_row = (lane & 7) + ((lane >> 4) & 1) * 8;
    const int b_c8  = ((lane >> 3) & 1) * 8;

    const uint32_t ahB0 = (uint32_t)__cvta_generic_to_shared(Ah);
    const uint32_t alB0 = (uint32_t)__cvta_generic_to_shared(Al);
    const uint32_t whB0 = (uint32_t)__cvta_generic_to_shared(Wh);
    const uint32_t wlB0 = (uint32_t)__cvta_generic_to_shared(Wl);
    const uint32_t bufBytes = PBUF_ELEMS * 2;

    float c[4][4];
#pragma unroll
    for (int n = 0; n < 4; n++)
#pragma unroll
        for (int r = 0; r < 4; r++) c[n][r] = 0.0f;

    // 1-deep register prefetch
    float4 fA[4];
    float wv[16];

    const float* arow_p = src + (size_t)(roff + lr) * DIM + ls;

    // load chunk 0
    {
        const float4* ap = reinterpret_cast<const float4*>(arow_p);
#pragma unroll
        for (int v = 0; v < 4; v++) fA[v] = ap[v];
        const float* wp = Wi + (size_t)wkg * DK + wcol;
#pragma unroll
        for (int j = 0; j < 16; j++) wv[j] = wp[j * DK];
    }

    for (int k0i = 0; k0i < 8; k0i++) {
        const int buf = k0i & 1;
        // split + store prefetched chunk into smem[buf]
        {
            uint32_t hw[8], lw[8];
#pragma unroll
            for (int v = 0; v < 4; v++) {
                split2(fA[v].x, fA[v].y, hw[2 * v],     lw[2 * v]);
                split2(fA[v].z, fA[v].w, hw[2 * v + 1], lw[2 * v + 1]);
            }
            int wo = lr * (PSTR / 2) + (ls >> 1);
            uint32_t* ahW = reinterpret_cast<uint32_t*>(Ah + buf * PBUF_ELEMS);
            uint32_t* alW = reinterpret_cast<uint32_t*>(Al + buf * PBUF_ELEMS);
            *reinterpret_cast<uint4*>(ahW + wo)     = make_uint4(hw[0], hw[1], hw[2], hw[3]);
            *reinterpret_cast<uint4*>(ahW + wo + 4) = make_uint4(hw[4], hw[5], hw[6], hw[7]);
            *reinterpret_cast<uint4*>(alW + wo)     = make_uint4(lw[0], lw[1], lw[2], lw[3]);
            *reinterpret_cast<uint4*>(alW + wo + 4) = make_uint4(lw[4], lw[5], lw[6], lw[7]);
#pragma unroll
            for (int v = 0; v < 8; v++) split2(wv[2 * v], wv[2 * v + 1], hw[v], lw[v]);
            int wo2 = wcol * (PSTR / 2) + (wkg >> 1);
            uint32_t* whW = reinterpret_cast<uint32_t*>(Wh + buf * PBUF_ELEMS);
            uint32_t* wlW = reinterpret_cast<uint32_t*>(Wl + buf * PBUF_ELEMS);
            *reinterpret_cast<uint4*>(whW + wo2)     = make_uint4(hw[0], hw[1], hw[2], hw[3]);
            *reinterpret_cast<uint4*>(whW + wo2 + 4) = make_uint4(hw[4], hw[5], hw[6], hw[7]);
            *reinterpret_cast<uint4*>(wlW + wo2)     = make_uint4(lw[0], lw[1], lw[2], lw[3]);
            *reinterpret_cast<uint4*>(wlW + wo2 + 4) = make_uint4(lw[4], lw[5], lw[6], lw[7]);
        }
        __syncthreads();

        // issue global loads for next chunk (overlap with MMA below)
        if (k0i < 7) {
            int k0 = (k0i + 1) * 64;
            const float4* ap = reinterpret_cast<const float4*>(arow_p + k0);
#pragma unroll
            for (int v = 0; v < 4; v++) fA[v] = ap[v];
            const float* wp = Wi + (size_t)(k0 + wkg) * DK + wcol;
#pragma unroll
            for (int j = 0; j < 16; j++) wv[j] = wp[j * DK];
        }

        const uint32_t ahB = ahB0 + buf * bufBytes;
        const uint32_t alB = alB0 + buf * bufBytes;
        const uint32_t whB = whB0 + buf * bufBytes;
        const uint32_t wlB = wlB0 + buf * bufBytes;

#pragma unroll
        for (int ks = 0; ks < 64; ks += 16) {
            uint32_t ah[4], al[4];
            {
                uint32_t off = (uint32_t)(((m_base + a_row) * PSTR + ks + a_c8) * 2);
                LDSM_X4(ah[0], ah[1], ah[2], ah[3], ahB + off);
                LDSM_X4(al[0], al[1], al[2], al[3], alB + off);
            }
            uint32_t bh[8], bl[8];
            {
                uint32_t off0 = (uint32_t)(((n_base + b_row) * PSTR + ks + b_c8) * 2);
                uint32_t off1 = off0 + 16 * PSTR * 2;
                LDSM_X4(bh[0], bh[1], bh[2], bh[3], whB + off0);
                LDSM_X4(bh[4], bh[5], bh[6], bh[7], whB + off1);
                LDSM_X4(bl[0], bl[1], bl[2], bl[3], wlB + off0);
                LDSM_X4(bl[4], bl[5], bl[6], bl[7], wlB + off1);
            }
            // term-major: 4 independent chains per term
#pragma unroll
            for (int n = 0; n < 4; n++) MMA_BF16(c[n], ah, bh[2 * n], bh[2 * n + 1]);
#pragma unroll
            for (int n = 0; n < 4; n++) MMA_BF16(c[n], ah, bl[2 * n], bl[2 * n + 1]);
#pragma unroll
            for (int n = 0; n < 4; n++) MMA_BF16(c[n], al, bh[2 * n], bh[2 * n + 1]);
        }
    }

    // epilogue: add bias, split to bf16 hi/lo, store packed words
    const int g = lane >> 2, tig = lane & 3;
    {
        int row = roff + m_base + g;
#pragma unroll
        for (int n = 0; n < 4; n++) {
            int col = n_base + n * 8 + tig * 2;
            float b0v = bi[col], b1v = bi[col + 1];
            uint32_t hw, lw;
            split2(c[n][0] + b0v, c[n][1] + b1v, hw, lw);
            dsth[(size_t)row * 32 + (col >> 1)] = hw;
            dstl[(size_t)row * 32 + (col >> 1)] = lw;
            split2(c[n][2] + b0v, c[n][3] + b1v, hw, lw);
            dsth[(size_t)(row + 8) * 32 + (col >> 1)] = hw;
            dstl[(size_t)(row + 8) * 32 + (col >> 1)] = lw;
        }
    }
}

// ---------------------------------------------------------------------------
// Kernel 2: banded attention + fused output projection.
// K tiles cp.async double-buffered; MMAs term-major & non-volatile for ILP.
// ---------------------------------------------------------------------------
#define QSTR 72    // bf16 stride for 64-wide tiles
#define WSTR 136   // bf16 stride for 128-wide Wo chunks
#define KBUF_BYTES (64 * QSTR * 2)   // 9216
// smem byte offsets
#define Q_OFF    0            // Qh 9216 | Ql 9216
#define K_OFF    18432        // Kh[2] 18432 | Kl[2] 18432
#define RED_OFF  55296        // float red[64][66] = 16896
#define ATT_OFF  72192        // AttH 9216 | AttL 9216
#define ATTN_SMEM_BYTES 90624
// Wo chunk aliases the Q/K region: WoH @0 (17408B), WoL @17408

__global__ void __launch_bounds__(256) attn_kernel(const float* __restrict__ bo,
                                                   float* __restrict__ out)
{
    extern __shared__ __align__(16) char asmem[];
    __nv_bfloat16* Qh = reinterpret_cast<__nv_bfloat16*>(asmem + Q_OFF);
    __nv_bfloat16* Ql = Qh + 64 * QSTR;
    float (*red)[66]  = reinterpret_cast<float(*)[66]>(asmem + RED_OFF);
    __nv_bfloat16* AttH = reinterpret_cast<__nv_bfloat16*>(asmem + ATT_OFF);
    __nv_bfloat16* AttL = AttH + 64 * QSTR;
    __nv_bfloat16* WoH = reinterpret_cast<__nv_bfloat16*>(asmem);           // alias
    __nv_bfloat16* WoL = reinterpret_cast<__nv_bfloat16*>(asmem + 17408);   // alias

    const int t    = threadIdx.x;
    const int lane = t & 31;
    const int warp = t >> 5;
    const int b    = blockIdx.x >> 6;
    const int qs   = blockIdx.x & 63;
    const int q0   = qs * 64;

    const int wm = warp & 3;
    const int wj = warp >> 2;
    const int m_base = wm * 16;
    const int jcol0  = wj * 32;

    const uint32_t qhB = (uint32_t)__cvta_generic_to_shared(Qh);
    const uint32_t qlB = (uint32_t)__cvta_generic_to_shared(Ql);
    const uint32_t smemB = (uint32_t)__cvta_generic_to_shared(asmem);
    const uint32_t athB = (uint32_t)__cvta_generic_to_shared(AttH);
    const uint32_t atlB = (uint32_t)__cvta_generic_to_shared(AttL);
    const uint32_t whB = (uint32_t)__cvta_generic_to_shared(WoH);
    const uint32_t wlB = (uint32_t)__cvta_generic_to_shared(WoL);

    // loaders: rows r0 & r0+32, 16B segment s0
    const int r0 = t >> 3;
    const int s0 = t & 7;

    // ---- prologue: cp.async Q tile (group 0), K tile 0 (group 1) ----
    {
        size_t gb0 = ((size_t)b * SEQ + q0 + r0) * DK + s0 * 8;
        size_t gb1 = gb0 + (size_t)32 * DK;
        uint32_t d0 = r0 * QSTR * 2 + s0 * 16;
        uint32_t d1 = (r0 + 32) * QSTR * 2 + s0 * 16;
        CP_ASYNC16(qhB + d0, g_qh + gb0);
        CP_ASYNC16(qhB + d1, g_qh + gb1);
        CP_ASYNC16(qlB + d0, g_ql + gb0);
        CP_ASYNC16(qlB + d1, g_ql + gb1);
    }
    CP_COMMIT();

    // build valid tile list
    int tiles[5];
    int nt = 0;
    for (int jt = qs - 2; jt <= qs + 2; jt++)
        if (jt >= 0 && jt < 64) tiles[nt++] = jt;

    // issue K tile 0 into buf 0
    {
        size_t gb0 = ((size_t)b * SEQ + tiles[0] * 64 + r0) * DK + s0 * 8;
        size_t gb1 = gb0 + (size_t)32 * DK;
        uint32_t kh = smemB + K_OFF;
        uint32_t kl = smemB + K_OFF + 2 * KBUF_BYTES;
        uint32_t d0 = r0 * QSTR * 2 + s0 * 16;
        uint32_t d1 = (r0 + 32) * QSTR * 2 + s0 * 16;
        CP_ASYNC16(kh + d0, g_kvh + gb0);
        CP_ASYNC16(kh + d1, g_kvh + gb1);
        CP_ASYNC16(kl + d0, g_kvl + gb0);
        CP_ASYNC16(kl + d1, g_kvl + gb1);
    }
    CP_COMMIT();

    CP_WAIT(1);          // Q complete (K0 may still be in flight)
    __syncthreads();

    // ldmatrix lane addressing
    const int a_row = lane & 15;
    const int a_c8  = (lane >> 4) * 8;
    const int b_row = (lane & 7) + ((lane >> 4) & 1) * 8;
    const int b_c8  = ((lane >> 3) & 1) * 8;
    const int tj    = (lane & 7) + ((lane >> 3) & 1) * 8;
    const int td8   = (lane >> 4) * 8;

    // Q a-fragments: persistent across all j-tiles
    uint32_t qha[4][4], qla[4][4];
#pragma unroll
    for (int kc = 0; kc < 4; kc++) {
        uint32_t off = (uint32_t)(((m_base + a_row) * QSTR + kc * 16 + a_c8) * 2);
        LDSM_X4(qha[kc][0], qha[kc][1], qha[kc][2], qha[kc][3], qhB + off);
        LDSM_X4(qla[kc][0], qla[kc][1], qla[kc][2], qla[kc][3], qlB + off);
    }

    float attv[8][4];
#pragma unroll
    for (int n = 0; n < 8; n++)
#pragma unroll
        for (int r = 0; r < 4; r++) attv[n][r] = 0.0f;

    const int g = lane >> 2, tq = lane & 3;
    const int gi_lo = q0 + m_base;
    const int gi_hi = gi_lo + 15;

    for (int it = 0; it < nt; it++) {
        const int jt  = tiles[it];
        const int cur = it & 1;
        CP_WAIT(0);          // tile it resident
        __syncthreads();     // visible to all; all warps done reading other buf

        // issue cp.async for tile it+1 into the other buffer (overlaps compute)
        if (it + 1 < nt) {
            size_t gb0 = ((size_t)b * SEQ + tiles[it + 1] * 64 + r0) * DK + s0 * 8;
            size_t gb1 = gb0 + (size_t)32 * DK;
            uint32_t kh = smemB + K_OFF + (cur ^ 1) * KBUF_BYTES;
            uint32_t kl = smemB + K_OFF + 2 * KBUF_BYTES + (cur ^ 1) * KBUF_BYTES;
            uint32_t d0 = r0 * QSTR * 2 + s0 * 16;
            uint32_t d1 = (r0 + 32) * QSTR * 2 + s0 * 16;
            CP_ASYNC16(kh + d0, g_kvh + gb0);
            CP_ASYNC16(kh + d1, g_kvh + gb1);
            CP_ASYNC16(kl + d0, g_kvl + gb0);
            CP_ASYNC16(kl + d1, g_kvl + gb1);
            CP_COMMIT();
        }

        const uint32_t khB = smemB + K_OFF + cur * KBUF_BYTES;
        const uint32_t klB = smemB + K_OFF + 2 * KBUF_BYTES + cur * KBUF_BYTES;
        const int jbase = jt * 64;

        // block in-band predicates for this warp's two 16-wide j blocks
        bool keep[2];
#pragma unroll
        for (int blk = 0; blk < 2; blk++) {
            int jlo = jbase + jcol0 + blk * 16;
            keep[blk] = !(gi_lo - (jlo + 15) > BAND || jlo - gi_hi > BAND);
        }

        // ---- Phase A: S (m16 x n32) = Q K^T, 3-term split, term-major ----
        float S[4][4];
#pragma unroll
        for (int n = 0; n < 4; n++)
#pragma unroll
            for (int r = 0; r < 4; r++) S[n][r] = 0.0f;

#pragma unroll
        for (int kc = 0; kc < 4; kc++) {
            uint32_t bh[8], bl[8];
#pragma unroll
            for (int ng = 0; ng < 2; ng++) {
                if (!keep[ng]) continue;
                uint32_t off = (uint32_t)(((jcol0 + ng * 16 + b_row) * QSTR + kc * 16 + b_c8) * 2);
                LDSM_X4(bh[4 * ng], bh[4 * ng + 1], bh[4 * ng + 2], bh[4 * ng + 3], khB + off);
                LDSM_X4(bl[4 * ng], bl[4 * ng + 1], bl[4 * ng + 2], bl[4 * ng + 3], klB + off);
            }
            // hh over 4 accumulators, then hl, then lh
#pragma unroll
            for (int ng = 0; ng < 2; ng++) {
                if (!keep[ng]) continue;
                MMA_BF16(S[2 * ng],     qha[kc], bh[4 * ng],     bh[4 * ng + 1]);
                MMA_BF16(S[2 * ng + 1], qha[kc], bh[4 * ng + 2], bh[4 * ng + 3]);
            }
#pragma unroll
            for (int ng = 0; ng < 2; ng++) {
                if (!keep[ng]) continue;
                MMA_BF16(S[2 * ng],     qha[kc], bl[4 * ng],     bl[4 * ng + 1]);
                MMA_BF16(S[2 * ng + 1], qha[kc], bl[4 * ng + 2], bl[4 * ng + 3]);
            }
#pragma unroll
            for (int ng = 0; ng < 2; ng++) {
                if (!keep[ng]) continue;
                MMA_BF16(S[2 * ng],     qla[kc], bh[4 * ng],     bh[4 * ng + 1]);
                MMA_BF16(S[2 * ng + 1], qla[kc], bh[4 * ng + 2], bh[4 * ng + 3]);
            }
        }

        // ---- mask + scale in registers ----
        const int gi0 = gi_lo + g;
#pragma unroll
        for (int n = 0; n < 4; n++) {
            int gj = jbase + jcol0 + n * 8 + tq * 2;
            int d0 = gi0 - gj;
            int d1 = d0 - 1;
            int d2 = d0 + 8;
            int d3 = d2 - 1;
            S[n][0] = (d0 <= BAND && d0 >= -BAND) ? S[n][0] * SCALE : 0.0f;
            S[n][1] = (d1 <= BAND && d1 >= -BAND) ? S[n][1] * SCALE : 0.0f;
            S[n][2] = (d2 <= BAND && d2 >= -BAND) ? S[n][2] * SCALE : 0.0f;
            S[n][3] = (d3 <= BAND && d3 >= -BAND) ? S[n][3] * SCALE : 0.0f;
        }

        // ---- split S C-frags into phase-B A-frags ----
        uint32_t pah[2][4], pal[2][4];
#pragma unroll
        for (int kc = 0; kc < 2; kc++) {
            split2(S[2 * kc][0],     S[2 * kc][1],     pah[kc][0], pal[kc][0]);
            split2(S[2 * kc][2],     S[2 * kc][3],     pah[kc][1], pal[kc][1]);
            split2(S[2 * kc + 1][0], S[2 * kc + 1][1], pah[kc][2], pal[kc][2]);
            split2(S[2 * kc + 1][2], S[2 * kc + 1][3], pah[kc][3], pal[kc][3]);
        }

        // ---- Phase B: attv += S @ KV, term-major per kc (8 chains) ----
#pragma unroll
        for (int kc = 0; kc < 2; kc++) {
            if (!keep[kc]) continue;
#pragma unroll
            for (int dg = 0; dg < 4; dg += 2) {
                uint32_t vh[8], vl[8];
                uint32_t off0 = (uint32_t)(((jcol0 + kc * 16 + tj) * QSTR + dg * 16 + td8) * 2);
                uint32_t off1 = (uint32_t)(((jcol0 + kc * 16 + tj) * QSTR + (dg + 1) * 16 + td8) * 2);
                LDSM_X4_T(vh[0], vh[1], vh[2], vh[3], khB + off0);
                LDSM_X4_T(vh[4], vh[5], vh[6], vh[7], khB + off1);
                LDSM_X4_T(vl[0], vl[1], vl[2], vl[3], klB + off0);
                LDSM_X4_T(vl[4], vl[5], vl[6], vl[7], klB + off1);
                // hh x4, hl x4, lh x4 (4 independent accumulators per term)
                MMA_BF16(attv[2 * dg],     pah[kc], vh[0], vh[1]);
                MMA_BF16(attv[2 * dg + 1], pah[kc], vh[2], vh[3]);
                MMA_BF16(attv[2 * dg + 2], pah[kc], vh[4], vh[5]);
                MMA_BF16(attv[2 * dg + 3], pah[kc], vh[6], vh[7]);
                MMA_BF16(attv[2 * dg],     pah[kc], vl[0], vl[1]);
                MMA_BF16(attv[2 * dg + 1], pah[kc], vl[2], vl[3]);
                MMA_BF16(attv[2 * dg + 2], pah[kc], vl[4], vl[5]);
                MMA_BF16(attv[2 * dg + 3], pah[kc], vl[6], vl[7]);
                MMA_BF16(attv[2 * dg],     pal[kc], vh[0], vh[1]);
                MMA_BF16(attv[2 * dg + 1], pal[kc], vh[2], vh[3]);
                MMA_BF16(attv[2 * dg + 2], pal[kc], vh[4], vh[5]);
                MMA_BF16(attv[2 * dg + 3], pal[kc], vh[6], vh[7]);
            }
        }
    }

    // ---- cross-warp reduction over wj; att (split bf16) goes to smem ----
    __syncthreads();
    if (wj == 1) {
#pragma unroll
        for (int n = 0; n < 8; n++) {
            int col = n * 8 + tq * 2;
            *reinterpret_cast<float2*>(&red[m_base + g][col])     = make_float2(attv[n][0], attv[n][1]);
            *reinterpret_cast<float2*>(&red[m_base + g + 8][col]) = make_float2(attv[n][2], attv[n][3]);
        }
    }
    __syncthreads();
    if (wj == 0) {
        uint32_t* ath = reinterpret_cast<uint32_t*>(AttH);
        uint32_t* atl = reinterpret_cast<uint32_t*>(AttL);
#pragma unroll
        for (int n = 0; n < 8; n++) {
            int col = n * 8 + tq * 2;
            float2 rr0 = *reinterpret_cast<const float2*>(&red[m_base + g][col]);
            float2 rr1 = *reinterpret_cast<const float2*>(&red[m_base + g + 8][col]);
            int cw = n * 4 + tq;   // word index within row
            uint32_t hw, lw;
            split2(attv[n][0] + rr0.x, attv[n][1] + rr0.y, hw, lw);
            ath[(m_base + g) * (QSTR / 2) + cw] = hw;
            atl[(m_base + g) * (QSTR / 2) + cw] = lw;
            split2(attv[n][2] + rr1.x, attv[n][3] + rr1.y, hw, lw);
            ath[(m_base + g + 8) * (QSTR / 2) + cw] = hw;
            atl[(m_base + g + 8) * (QSTR / 2) + cw] = lw;
        }
    }
    __syncthreads();

    // ---- fused output GEMM: out[64, 512] = att @ Wo + bo ----
    uint32_t oah[4][4], oal[4][4];
#pragma unroll
    for (int kc = 0; kc < 4; kc++) {
        uint32_t off = (uint32_t)(((m_base + a_row) * QSTR + kc * 16 + a_c8) * 2);
        LDSM_X4(oah[kc][0], oah[kc][1], oah[kc][2], oah[kc][3], athB + off);
        LDSM_X4(oal[kc][0], oal[kc][1], oal[kc][2], oal[kc][3], atlB + off);
    }

    const int wn = wj;          // column half within each 128-col chunk
    const int wk = t >> 2;      // Wo loader: k row
    const int seg = (t & 3) * 32;

    // prefetch Wo chunk 0 into registers
    uint4 pwh[4], pwl[4];
    {
        const uint4* sh = reinterpret_cast<const uint4*>(g_woh + (size_t)wk * DIM + seg);
        const uint4* sl = reinterpret_cast<const uint4*>(g_wol + (size_t)wk * DIM + seg);
#pragma unroll
        for (int v = 0; v < 4; v++) { pwh[v] = sh[v]; pwl[v] = sl[v]; }
    }

    const size_t row_g = (size_t)b * SEQ + q0 + m_base + g;

#pragma unroll
    for (int cc = 0; cc < 4; cc++) {
        // store prefetched Wo chunk to smem
        {
            uint4* dh = reinterpret_cast<uint4*>(&WoH[wk * WSTR + seg]);
            uint4* dl = reinterpret_cast<uint4*>(&WoL[wk * WSTR + seg]);
#pragma unroll
            for (int v = 0; v < 4; v++) { dh[v] = pwh[v]; dl[v] = pwl[v]; }
        }
        __syncthreads();
        // prefetch next chunk
        if (cc < 3) {
            const uint4* sh = reinterpret_cast<const uint4*>(
                g_woh + (size_t)wk * DIM + (cc + 1) * 128 + seg);
            const uint4* sl = reinterpret_cast<const uint4*>(
                g_wol + (size_t)wk * DIM + (cc + 1) * 128 + seg);
#pragma unroll
            for (int v = 0; v < 4; v++) { pwh[v] = sh[v]; pwl[v] = sl[v]; }
        }

        float oc[8][4];
#pragma unroll
        for (int n = 0; n < 8; n++)
#pragma unroll
            for (int r = 0; r < 4; r++) oc[n][r] = 0.0f;

#pragma unroll
        for (int kc = 0; kc < 4; kc++) {
#pragma unroll
            for (int dg = 0; dg < 4; dg += 2) {
                uint32_t vh[8], vl[8];
                uint32_t off0 = (uint32_t)(((kc * 16 + tj) * WSTR + wn * 64 + dg * 16 + td8) * 2);
                uint32_t off1 = (uint32_t)(((kc * 16 + tj) * WSTR + wn * 64 + (dg + 1) * 16 + td8) * 2);
                LDSM_X4_T(vh[0], vh[1], vh[2], vh[3], whB + off0);
                LDSM_X4_T(vh[4], vh[5], vh[6], vh[7], whB + off1);
                LDSM_X4_T(vl[0], vl[1], vl[2], vl[3], wlB + off0);
                LDSM_X4_T(vl[4], vl[5], vl[6], vl[7], wlB + off1);
                MMA_BF16(oc[2 * dg],     oah[kc], vh[0], vh[1]);
                MMA_BF16(oc[2 * dg + 1], oah[kc], vh[2], vh[3]);
                MMA_BF16(oc[2 * dg + 2], oah[kc], vh[4], vh[5]);
                MMA_BF16(oc[2 * dg + 3], oah[kc], vh[6], vh[7]);
                MMA_BF16(oc[2 * dg],     oah[kc], vl[0], vl[1]);
                MMA_BF16(oc[2 * dg + 1], oah[kc], vl[2], vl[3]);
                MMA_BF16(oc[2 * dg + 2], oah[kc], vl[4], vl[5]);
                MMA_BF16(oc[2 * dg + 3], oah[kc], vl[6], vl[7]);
                MMA_BF16(oc[2 * dg],     oal[kc], vh[0], vh[1]);
                MMA_BF16(oc[2 * dg + 1], oal[kc], vh[2], vh[3]);
                MMA_BF16(oc[2 * dg + 2], oal[kc], vh[4], vh[5]);
                MMA_BF16(oc[2 * dg + 3], oal[kc], vh[6], vh[7]);
            }
        }

        // epilogue: bias + fp32 store for this chunk
#pragma unroll
        for (int n = 0; n < 8; n++) {
            int col = cc * 128 + wn * 64 + n * 8 + tq * 2;
            float b0v = bo[col], b1v = bo[col + 1];
            float2 o0 = {oc[n][0] + b0v, oc[n][1] + b1v};
            float2 o1 = {oc[n][2] + b0v, oc[n][3] + b1v};
            *reinterpret_cast<float2*>(&out[row_g * DIM + col]) = o0;
            *reinterpret_cast<float2*>(&out[(row_g + 8) * DIM + col]) = o1;
        }
        __syncthreads();   // all reads of WoH/WoL done before next overwrite
    }
}

// ---------------------------------------------------------------------------
extern "C" void kernel_launch(void* const* d_in, const int* in_sizes, int n_in,
                              void* d_out, int out_size)
{
    const float* query = (const float*)d_in[0];
    const float* value = (const float*)d_in[1];
    const float* Wi    = (const float*)d_in[2];
    const float* bi    = (const float*)d_in[3];
    const float* Wo    = (const float*)d_in[4];
    const float* bo    = (const float*)d_in[5];
    float* out = (float*)d_out;

    static bool attr_set = false;
    if (!attr_set) {
        cudaFuncSetAttribute(proj_kernel, cudaFuncAttributeMaxDynamicSharedMemorySize,
                             PROJ_SMEM_BYTES);
        cudaFuncSetAttribute(attn_kernel, cudaFuncAttributeMaxDynamicSharedMemorySize,
                             ATTN_SMEM_BYTES);
        attr_set = true;
    }

    proj_kernel<<<MTOT / 64 + 8, 256, PROJ_SMEM_BYTES>>>(query, value, Wi, Wo, bi);
    attn_kernel<<<BATCH * (SEQ / 64), 256, ATTN_SMEM_BYTES>>>(bo, out);
}

// round 15
// speedup vs baseline: 1.4556x; 1.0049x over previous
#include <cuda_runtime.h>
#include <cuda_bf16.h>
#include <cstdint>

// Problem constants (fixed by dataset)
#define BATCH 4
#define SEQ   4096
#define DIM   512
#define DK    64
#define BAND  128
#define SCALE 0.125f            // 1/sqrt(64)
#define ROWS  (BATCH*SEQ)       // 16384
#define MTOT  (2*ROWS)          // 32768 (q rows then kv rows)

// ---- tensor-core helpers ---------------------------------------------------
#define LDSM_X4(r0, r1, r2, r3, addr) \
    asm volatile("ldmatrix.sync.aligned.m8n8.x4.shared.b16 {%0,%1,%2,%3}, [%4];" \
        : "=r"(r0), "=r"(r1), "=r"(r2), "=r"(r3) : "r"(addr))

#define LDSM_X4_T(r0, r1, r2, r3, addr) \
    asm volatile("ldmatrix.sync.aligned.m8n8.x4.trans.shared.b16 {%0,%1,%2,%3}, [%4];" \
        : "=r"(r0), "=r"(r1), "=r"(r2), "=r"(r3) : "r"(addr))

// NOT volatile: pure register ops; lets ptxas interleave independent MMA chains.
#define MMA_BF16(c, a, b0, b1) \
    asm("mma.sync.aligned.m16n8k16.row.col.f32.bf16.bf16.f32 " \
        "{%0,%1,%2,%3},{%4,%5,%6,%7},{%8,%9},{%0,%1,%2,%3};" \
        : "+f"((c)[0]), "+f"((c)[1]), "+f"((c)[2]), "+f"((c)[3]) \
        : "r"((a)[0]), "r"((a)[1]), "r"((a)[2]), "r"((a)[3]), "r"(b0), "r"(b1))

#define CP_ASYNC16(dst_u32, src_ptr) \
    asm volatile("cp.async.cg.shared.global [%0], [%1], 16;" \
        :: "r"(dst_u32), "l"(src_ptr) : "memory")
#define CP_COMMIT() asm volatile("cp.async.commit_group;" ::: "memory")
#define CP_WAIT(N)  asm volatile("cp.async.wait_group %0;" :: "n"(N) : "memory")

__device__ __forceinline__ uint32_t pack_bf16x2(__nv_bfloat16 a, __nv_bfloat16 b) {
    __nv_bfloat162 p;
    p.x = a; p.y = b;
    return *reinterpret_cast<uint32_t*>(&p);
}
// split two f32 into (hi, lo) bf16x2 words
__device__ __forceinline__ void split2(float x0, float x1, uint32_t& hw, uint32_t& lw) {
    __nv_bfloat16 h0 = __float2bfloat16(x0);
    __nv_bfloat16 h1 = __float2bfloat16(x1);
    __nv_bfloat16 l0 = __float2bfloat16(x0 - __bfloat162float(h0));
    __nv_bfloat16 l1 = __float2bfloat16(x1 - __bfloat162float(h1));
    hw = pack_bf16x2(h0, h1);
    lw = pack_bf16x2(l0, l1);
}

// Scratch (device globals; no allocation allowed). All split bf16 hi/lo pairs.
__device__ __nv_bfloat16 g_qh[ROWS * DK];
__device__ __nv_bfloat16 g_ql[ROWS * DK];
__device__ __nv_bfloat16 g_kvh[ROWS * DK];
__device__ __nv_bfloat16 g_kvl[ROWS * DK];
__device__ __nv_bfloat16 g_woh[DK * DIM];    // Wo split: [k=64][n=512]
__device__ __nv_bfloat16 g_wol[DK * DIM];

// ---------------------------------------------------------------------------
// Kernel 1: shared input projection via split-bf16 MMA, K-chunks of 64,
// double-buffered smem + 1-deep register prefetch. 8 tail CTAs split Wo.
// CTA: 64 rows x 64 cols, 256 threads = 8 warps (wm 0..3 m16, wn 0..1 n32).
// ---------------------------------------------------------------------------
#define PSTR 72   // bf16 stride (64 data + 8 pad)
#define PBUF_ELEMS (64 * PSTR)               // 4608
#define PROJ_SMEM_BYTES (8 * PBUF_ELEMS * 2) // Ah[2],Al[2],Wh[2],Wl[2] = 73728 B

__global__ void __launch_bounds__(256, 2) proj_kernel(const float* __restrict__ query,
                                                      const float* __restrict__ value,
                                                      const float* __restrict__ Wi,
                                                      const float* __restrict__ Wo,
                                                      const float* __restrict__ bi)
{
    const int t    = threadIdx.x;
    const int row0 = blockIdx.x * 64;

    // ---- tail CTAs: split Wo once ----
    if (row0 >= MTOT) {
        int base = (blockIdx.x - (MTOT / 64)) * 4096 + t * 16;
        const float4* wp = reinterpret_cast<const float4*>(Wo + base);
        uint32_t hw[8], lw[8];
#pragma unroll
        for (int v = 0; v < 4; v++) {
            float4 f = wp[v];
            split2(f.x, f.y, hw[2 * v],     lw[2 * v]);
            split2(f.z, f.w, hw[2 * v + 1], lw[2 * v + 1]);
        }
        uint4* dh = reinterpret_cast<uint4*>(g_woh + base);
        uint4* dl = reinterpret_cast<uint4*>(g_wol + base);
        dh[0] = make_uint4(hw[0], hw[1], hw[2], hw[3]);
        dh[1] = make_uint4(hw[4], hw[5], hw[6], hw[7]);
        dl[0] = make_uint4(lw[0], lw[1], lw[2], lw[3]);
        dl[1] = make_uint4(lw[4], lw[5], lw[6], lw[7]);
        return;
    }

    extern __shared__ __align__(16) __nv_bfloat16 psmem[];
    __nv_bfloat16* Ah = psmem;                    // [2][PBUF_ELEMS]
    __nv_bfloat16* Al = psmem + 2 * PBUF_ELEMS;
    __nv_bfloat16* Wh = psmem + 4 * PBUF_ELEMS;   // [n][k]
    __nv_bfloat16* Wl = psmem + 6 * PBUF_ELEMS;

    const int lane = t & 31;
    const int warp = t >> 5;

    const float* src;
    uint32_t* dsth;
    uint32_t* dstl;
    int roff;
    if (row0 < ROWS) {
        src = query;
        dsth = reinterpret_cast<uint32_t*>(g_qh);
        dstl = reinterpret_cast<uint32_t*>(g_ql);
        roff = row0;
    } else {
        src = value;
        dsth = reinterpret_cast<uint32_t*>(g_kvh);
        dstl = reinterpret_cast<uint32_t*>(g_kvl);
        roff = row0 - ROWS;
    }

    const int wm = warp & 3;
    const int wn = warp >> 2;
    const int m_base = wm * 16;
    const int n_base = wn * 32;

    // A loader: 64 rows x 64 k fp32, each thread 16 fp32 (4 float4) of one row
    const int lr = t >> 2;
    const int ls = (t & 3) * 16;
    // W loader: col wcol, 16 consecutive k (strided source reads)
    const int wcol = t & 63;
    const int wkg  = (t >> 6) * 16;

    // ldmatrix lane addressing
    const int a_row = lane & 15;
    const int a_c8  = (lane >> 4) * 8;
    const int b_row = (lane & 7) + ((lane >> 4) & 1) * 8;
    const int b_c8  = ((lane >> 3) & 1) * 8;

    const uint32_t ahB0 = (uint32_t)__cvta_generic_to_shared(Ah);
    const uint32_t alB0 = (uint32_t)__cvta_generic_to_shared(Al);
    const uint32_t whB0 = (uint32_t)__cvta_generic_to_shared(Wh);
    const uint32_t wlB0 = (uint32_t)__cvta_generic_to_shared(Wl);
    const uint32_t bufBytes = PBUF_ELEMS * 2;

    float c[4][4];
#pragma unroll
    for (int n = 0; n < 4; n++)
#pragma unroll
        for (int r = 0; r < 4; r++) c[n][r] = 0.0f;

    // 1-deep register prefetch
    float4 fA[4];
    float wv[16];

    const float* arow_p = src + (size_t)(roff + lr) * DIM + ls;

    // load chunk 0
    {
        const float4* ap = reinterpret_cast<const float4*>(arow_p);
#pragma unroll
        for (int v = 0; v < 4; v++) fA[v] = ap[v];
        const float* wp = Wi + (size_t)wkg * DK + wcol;
#pragma unroll
        for (int j = 0; j < 16; j++) wv[j] = wp[j * DK];
    }

    for (int k0i = 0; k0i < 8; k0i++) {
        const int buf = k0i & 1;
        // split + store prefetched chunk into smem[buf]
        {
            uint32_t hw[8], lw[8];
#pragma unroll
            for (int v = 0; v < 4; v++) {
                split2(fA[v].x, fA[v].y, hw[2 * v],     lw[2 * v]);
                split2(fA[v].z, fA[v].w, hw[2 * v + 1], lw[2 * v + 1]);
            }
            int wo = lr * (PSTR / 2) + (ls >> 1);
            uint32_t* ahW = reinterpret_cast<uint32_t*>(Ah + buf * PBUF_ELEMS);
            uint32_t* alW = reinterpret_cast<uint32_t*>(Al + buf * PBUF_ELEMS);
            *reinterpret_cast<uint4*>(ahW + wo)     = make_uint4(hw[0], hw[1], hw[2], hw[3]);
            *reinterpret_cast<uint4*>(ahW + wo + 4) = make_uint4(hw[4], hw[5], hw[6], hw[7]);
            *reinterpret_cast<uint4*>(alW + wo)     = make_uint4(lw[0], lw[1], lw[2], lw[3]);
            *reinterpret_cast<uint4*>(alW + wo + 4) = make_uint4(lw[4], lw[5], lw[6], lw[7]);
#pragma unroll
            for (int v = 0; v < 8; v++) split2(wv[2 * v], wv[2 * v + 1], hw[v], lw[v]);
            int wo2 = wcol * (PSTR / 2) + (wkg >> 1);
            uint32_t* whW = reinterpret_cast<uint32_t*>(Wh + buf * PBUF_ELEMS);
            uint32_t* wlW = reinterpret_cast<uint32_t*>(Wl + buf * PBUF_ELEMS);
            *reinterpret_cast<uint4*>(whW + wo2)     = make_uint4(hw[0], hw[1], hw[2], hw[3]);
            *reinterpret_cast<uint4*>(whW + wo2 + 4) = make_uint4(hw[4], hw[5], hw[6], hw[7]);
            *reinterpret_cast<uint4*>(wlW + wo2)     = make_uint4(lw[0], lw[1], lw[2], lw[3]);
            *reinterpret_cast<uint4*>(wlW + wo2 + 4) = make_uint4(lw[4], lw[5], lw[6], lw[7]);
        }
        __syncthreads();

        // issue global loads for next chunk (overlap with MMA below)
        if (k0i < 7) {
            int k0 = (k0i + 1) * 64;
            const float4* ap = reinterpret_cast<const float4*>(arow_p + k0);
#pragma unroll
            for (int v = 0; v < 4; v++) fA[v] = ap[v];
            const float* wp = Wi + (size_t)(k0 + wkg) * DK + wcol;
#pragma unroll
            for (int j = 0; j < 16; j++) wv[j] = wp[j * DK];
        }

        const uint32_t ahB = ahB0 + buf * bufBytes;
        const uint32_t alB = alB0 + buf * bufBytes;
        const uint32_t whB = whB0 + buf * bufBytes;
        const uint32_t wlB = wlB0 + buf * bufBytes;

#pragma unroll
        for (int ks = 0; ks < 64; ks += 16) {
            uint32_t ah[4], al[4];
            {
                uint32_t off = (uint32_t)(((m_base + a_row) * PSTR + ks + a_c8) * 2);
                LDSM_X4(ah[0], ah[1], ah[2], ah[3], ahB + off);
                LDSM_X4(al[0], al[1], al[2], al[3], alB + off);
            }
            uint32_t bh[8], bl[8];
            {
                uint32_t off0 = (uint32_t)(((n_base + b_row) * PSTR + ks + b_c8) * 2);
                uint32_t off1 = off0 + 16 * PSTR * 2;
                LDSM_X4(bh[0], bh[1], bh[2], bh[3], whB + off0);
                LDSM_X4(bh[4], bh[5], bh[6], bh[7], whB + off1);
                LDSM_X4(bl[0], bl[1], bl[2], bl[3], wlB + off0);
                LDSM_X4(bl[4], bl[5], bl[6], bl[7], wlB + off1);
            }
            // term-major: 4 independent chains per term
#pragma unroll
            for (int n = 0; n < 4; n++) MMA_BF16(c[n], ah, bh[2 * n], bh[2 * n + 1]);
#pragma unroll
            for (int n = 0; n < 4; n++) MMA_BF16(c[n], ah, bl[2 * n], bl[2 * n + 1]);
#pragma unroll
            for (int n = 0; n < 4; n++) MMA_BF16(c[n], al, bh[2 * n], bh[2 * n + 1]);
        }
    }

    // epilogue: add bias, split to bf16 hi/lo, store packed words
    const int g = lane >> 2, tig = lane & 3;
    {
        int row = roff + m_base + g;
#pragma unroll
        for (int n = 0; n < 4; n++) {
            int col = n_base + n * 8 + tig * 2;
            float b0v = bi[col], b1v = bi[col + 1];
            uint32_t hw, lw;
            split2(c[n][0] + b0v, c[n][1] + b1v, hw, lw);
            dsth[(size_t)row * 32 + (col >> 1)] = hw;
            dstl[(size_t)row * 32 + (col >> 1)] = lw;
            split2(c[n][2] + b0v, c[n][3] + b1v, hw, lw);
            dsth[(size_t)(row + 8) * 32 + (col >> 1)] = hw;
            dstl[(size_t)(row + 8) * 32 + (col >> 1)] = lw;
        }
    }
}

// ---------------------------------------------------------------------------
// Kernel 2: banded attention + fused output projection.
// K tiles cp.async double-buffered; MMAs term-major & non-volatile for ILP.
// ---------------------------------------------------------------------------
#define QSTR 72    // bf16 stride for 64-wide tiles
#define WSTR 136   // bf16 stride for 128-wide Wo chunks
#define KBUF_BYTES (64 * QSTR * 2)   // 9216
// smem byte offsets
#define Q_OFF    0            // Qh 9216 | Ql 9216
#define K_OFF    18432        // Kh[2] 18432 | Kl[2] 18432
#define RED_OFF  55296        // float red[64][66] = 16896
#define ATT_OFF  72192        // AttH 9216 | AttL 9216
#define ATTN_SMEM_BYTES 90624
// Wo chunk aliases the Q/K region: WoH @0 (17408B), WoL @17408

__global__ void __launch_bounds__(256, 2) attn_kernel(const float* __restrict__ bo,
                                                      float* __restrict__ out)
{
    extern __shared__ __align__(16) char asmem[];
    __nv_bfloat16* Qh = reinterpret_cast<__nv_bfloat16*>(asmem + Q_OFF);
    __nv_bfloat16* Ql = Qh + 64 * QSTR;
    float (*red)[66]  = reinterpret_cast<float(*)[66]>(asmem + RED_OFF);
    __nv_bfloat16* AttH = reinterpret_cast<__nv_bfloat16*>(asmem + ATT_OFF);
    __nv_bfloat16* AttL = AttH + 64 * QSTR;
    __nv_bfloat16* WoH = reinterpret_cast<__nv_bfloat16*>(asmem);           // alias
    __nv_bfloat16* WoL = reinterpret_cast<__nv_bfloat16*>(asmem + 17408);   // alias

    const int t    = threadIdx.x;
    const int lane = t & 31;
    const int warp = t >> 5;
    const int b    = blockIdx.x >> 6;
    const int qs   = blockIdx.x & 63;
    const int q0   = qs * 64;

    const int wm = warp & 3;
    const int wj = warp >> 2;
    const int m_base = wm * 16;
    const int jcol0  = wj * 32;

    const uint32_t qhB = (uint32_t)__cvta_generic_to_shared(Qh);
    const uint32_t qlB = (uint32_t)__cvta_generic_to_shared(Ql);
    const uint32_t smemB = (uint32_t)__cvta_generic_to_shared(asmem);
    const uint32_t athB = (uint32_t)__cvta_generic_to_shared(AttH);
    const uint32_t atlB = (uint32_t)__cvta_generic_to_shared(AttL);
    const uint32_t whB = (uint32_t)__cvta_generic_to_shared(WoH);
    const uint32_t wlB = (uint32_t)__cvta_generic_to_shared(WoL);

    // loaders: rows r0 & r0+32, 16B segment s0
    const int r0 = t >> 3;
    const int s0 = t & 7;

    // ---- prologue: cp.async Q tile (group 0), K tile 0 (group 1) ----
    {
        size_t gb0 = ((size_t)b * SEQ + q0 + r0) * DK + s0 * 8;
        size_t gb1 = gb0 + (size_t)32 * DK;
        uint32_t d0 = r0 * QSTR * 2 + s0 * 16;
        uint32_t d1 = (r0 + 32) * QSTR * 2 + s0 * 16;
        CP_ASYNC16(qhB + d0, g_qh + gb0);
        CP_ASYNC16(qhB + d1, g_qh + gb1);
        CP_ASYNC16(qlB + d0, g_ql + gb0);
        CP_ASYNC16(qlB + d1, g_ql + gb1);
    }
    CP_COMMIT();

    // build valid tile list
    int tiles[5];
    int nt = 0;
    for (int jt = qs - 2; jt <= qs + 2; jt++)
        if (jt >= 0 && jt < 64) tiles[nt++] = jt;

    // issue K tile 0 into buf 0
    {
        size_t gb0 = ((size_t)b * SEQ + tiles[0] * 64 + r0) * DK + s0 * 8;
        size_t gb1 = gb0 + (size_t)32 * DK;
        uint32_t kh = smemB + K_OFF;
        uint32_t kl = smemB + K_OFF + 2 * KBUF_BYTES;
        uint32_t d0 = r0 * QSTR * 2 + s0 * 16;
        uint32_t d1 = (r0 + 32) * QSTR * 2 + s0 * 16;
        CP_ASYNC16(kh + d0, g_kvh + gb0);
        CP_ASYNC16(kh + d1, g_kvh + gb1);
        CP_ASYNC16(kl + d0, g_kvl + gb0);
        CP_ASYNC16(kl + d1, g_kvl + gb1);
    }
    CP_COMMIT();

    CP_WAIT(1);          // Q complete (K0 may still be in flight)
    __syncthreads();

    // ldmatrix lane addressing
    const int a_row = lane & 15;
    const int a_c8  = (lane >> 4) * 8;
    const int b_row = (lane & 7) + ((lane >> 4) & 1) * 8;
    const int b_c8  = ((lane >> 3) & 1) * 8;
    const int tj    = (lane & 7) + ((lane >> 3) & 1) * 8;
    const int td8   = (lane >> 4) * 8;

    // Q a-fragments: persistent across all j-tiles
    uint32_t qha[4][4], qla[4][4];
#pragma unroll
    for (int kc = 0; kc < 4; kc++) {
        uint32_t off = (uint32_t)(((m_base + a_row) * QSTR + kc * 16 + a_c8) * 2);
        LDSM_X4(qha[kc][0], qha[kc][1], qha[kc][2], qha[kc][3], qhB + off);
        LDSM_X4(qla[kc][0], qla[kc][1], qla[kc][2], qla[kc][3], qlB + off);
    }

    float attv[8][4];
#pragma unroll
    for (int n = 0; n < 8; n++)
#pragma unroll
        for (int r = 0; r < 4; r++) attv[n][r] = 0.0f;

    const int g = lane >> 2, tq = lane & 3;
    const int gi_lo = q0 + m_base;
    const int gi_hi = gi_lo + 15;

    for (int it = 0; it < nt; it++) {
        const int jt  = tiles[it];
        const int cur = it & 1;
        CP_WAIT(0);          // tile it resident
        __syncthreads();     // visible to all; all warps done reading other buf

        // issue cp.async for tile it+1 into the other buffer (overlaps compute)
        if (it + 1 < nt) {
            size_t gb0 = ((size_t)b * SEQ + tiles[it + 1] * 64 + r0) * DK + s0 * 8;
            size_t gb1 = gb0 + (size_t)32 * DK;
            uint32_t kh = smemB + K_OFF + (cur ^ 1) * KBUF_BYTES;
            uint32_t kl = smemB + K_OFF + 2 * KBUF_BYTES + (cur ^ 1) * KBUF_BYTES;
            uint32_t d0 = r0 * QSTR * 2 + s0 * 16;
            uint32_t d1 = (r0 + 32) * QSTR * 2 + s0 * 16;
            CP_ASYNC16(kh + d0, g_kvh + gb0);
            CP_ASYNC16(kh + d1, g_kvh + gb1);
            CP_ASYNC16(kl + d0, g_kvl + gb0);
            CP_ASYNC16(kl + d1, g_kvl + gb1);
            CP_COMMIT();
        }

        const uint32_t khB = smemB + K_OFF + cur * KBUF_BYTES;
        const uint32_t klB = smemB + K_OFF + 2 * KBUF_BYTES + cur * KBUF_BYTES;
        const int jbase = jt * 64;

        // block in-band predicates for this warp's two 16-wide j blocks
        bool keep[2];
#pragma unroll
        for (int blk = 0; blk < 2; blk++) {
            int jlo = jbase + jcol0 + blk * 16;
            keep[blk] = !(gi_lo - (jlo + 15) > BAND || jlo - gi_hi > BAND);
        }

        // ---- Phase A: S (m16 x n32) = Q K^T, 3-term split, term-major ----
        float S[4][4];
#pragma unroll
        for (int n = 0; n < 4; n++)
#pragma unroll
            for (int r = 0; r < 4; r++) S[n][r] = 0.0f;

#pragma unroll
        for (int kc = 0; kc < 4; kc++) {
            uint32_t bh[8], bl[8];
#pragma unroll
            for (int ng = 0; ng < 2; ng++) {
                if (!keep[ng]) continue;
                uint32_t off = (uint32_t)(((jcol0 + ng * 16 + b_row) * QSTR + kc * 16 + b_c8) * 2);
                LDSM_X4(bh[4 * ng], bh[4 * ng + 1], bh[4 * ng + 2], bh[4 * ng + 3], khB + off);
                LDSM_X4(bl[4 * ng], bl[4 * ng + 1], bl[4 * ng + 2], bl[4 * ng + 3], klB + off);
            }
            // hh over 4 accumulators, then hl, then lh
#pragma unroll
            for (int ng = 0; ng < 2; ng++) {
                if (!keep[ng]) continue;
                MMA_BF16(S[2 * ng],     qha[kc], bh[4 * ng],     bh[4 * ng + 1]);
                MMA_BF16(S[2 * ng + 1], qha[kc], bh[4 * ng + 2], bh[4 * ng + 3]);
            }
#pragma unroll
            for (int ng = 0; ng < 2; ng++) {
                if (!keep[ng]) continue;
                MMA_BF16(S[2 * ng],     qha[kc], bl[4 * ng],     bl[4 * ng + 1]);
                MMA_BF16(S[2 * ng + 1], qha[kc], bl[4 * ng + 2], bl[4 * ng + 3]);
            }
#pragma unroll
            for (int ng = 0; ng < 2; ng++) {
                if (!keep[ng]) continue;
                MMA_BF16(S[2 * ng],     qla[kc], bh[4 * ng],     bh[4 * ng + 1]);
                MMA_BF16(S[2 * ng + 1], qla[kc], bh[4 * ng + 2], bh[4 * ng + 3]);
            }
        }

        // ---- mask + scale in registers ----
        const int gi0 = gi_lo + g;
#pragma unroll
        for (int n = 0; n < 4; n++) {
            int gj = jbase + jcol0 + n * 8 + tq * 2;
            int d0 = gi0 - gj;
            int d1 = d0 - 1;
            int d2 = d0 + 8;
            int d3 = d2 - 1;
            S[n][0] = (d0 <= BAND && d0 >= -BAND) ? S[n][0] * SCALE : 0.0f;
            S[n][1] = (d1 <= BAND && d1 >= -BAND) ? S[n][1] * SCALE : 0.0f;
            S[n][2] = (d2 <= BAND && d2 >= -BAND) ? S[n][2] * SCALE : 0.0f;
            S[n][3] = (d3 <= BAND && d3 >= -BAND) ? S[n][3] * SCALE : 0.0f;
        }

        // ---- split S C-frags into phase-B A-frags ----
        uint32_t pah[2][4], pal[2][4];
#pragma unroll
        for (int kc = 0; kc < 2; kc++) {
            split2(S[2 * kc][0],     S[2 * kc][1],     pah[kc][0], pal[kc][0]);
            split2(S[2 * kc][2],     S[2 * kc][3],     pah[kc][1], pal[kc][1]);
            split2(S[2 * kc + 1][0], S[2 * kc + 1][1], pah[kc][2], pal[kc][2]);
            split2(S[2 * kc + 1][2], S[2 * kc + 1][3], pah[kc][3], pal[kc][3]);
        }

        // ---- Phase B: attv += S @ KV, term-major per kc (8 chains) ----
#pragma unroll
        for (int kc = 0; kc < 2; kc++) {
            if (!keep[kc]) continue;
#pragma unroll
            for (int dg = 0; dg < 4; dg += 2) {
                uint32_t vh[8], vl[8];
                uint32_t off0 = (uint32_t)(((jcol0 + kc * 16 + tj) * QSTR + dg * 16 + td8) * 2);
                uint32_t off1 = (uint32_t)(((jcol0 + kc * 16 + tj) * QSTR + (dg + 1) * 16 + td8) * 2);
                LDSM_X4_T(vh[0], vh[1], vh[2], vh[3], khB + off0);
                LDSM_X4_T(vh[4], vh[5], vh[6], vh[7], khB + off1);
                LDSM_X4_T(vl[0], vl[1], vl[2], vl[3], klB + off0);
                LDSM_X4_T(vl[4], vl[5], vl[6], vl[7], klB + off1);
                // hh x4, hl x4, lh x4 (4 independent accumulators per term)
                MMA_BF16(attv[2 * dg],     pah[kc], vh[0], vh[1]);
                MMA_BF16(attv[2 * dg + 1], pah[kc], vh[2], vh[3]);
                MMA_BF16(attv[2 * dg + 2], pah[kc], vh[4], vh[5]);
                MMA_BF16(attv[2 * dg + 3], pah[kc], vh[6], vh[7]);
                MMA_BF16(attv[2 * dg],     pah[kc], vl[0], vl[1]);
                MMA_BF16(attv[2 * dg + 1], pah[kc], vl[2], vl[3]);
                MMA_BF16(attv[2 * dg + 2], pah[kc], vl[4], vl[5]);
                MMA_BF16(attv[2 * dg + 3], pah[kc], vl[6], vl[7]);
                MMA_BF16(attv[2 * dg],     pal[kc], vh[0], vh[1]);
                MMA_BF16(attv[2 * dg + 1], pal[kc], vh[2], vh[3]);
                MMA_BF16(attv[2 * dg + 2], pal[kc], vh[4], vh[5]);
                MMA_BF16(attv[2 * dg + 3], pal[kc], vh[6], vh[7]);
            }
        }
    }

    // ---- cross-warp reduction over wj; att (split bf16) goes to smem ----
    __syncthreads();
    if (wj == 1) {
#pragma unroll
        for (int n = 0; n < 8; n++) {
            int col = n * 8 + tq * 2;
            *reinterpret_cast<float2*>(&red[m_base + g][col])     = make_float2(attv[n][0], attv[n][1]);
            *reinterpret_cast<float2*>(&red[m_base + g + 8][col]) = make_float2(attv[n][2], attv[n][3]);
        }
    }
    __syncthreads();
    if (wj == 0) {
        uint32_t* ath = reinterpret_cast<uint32_t*>(AttH);
        uint32_t* atl = reinterpret_cast<uint32_t*>(AttL);
#pragma unroll
        for (int n = 0; n < 8; n++) {
            int col = n * 8 + tq * 2;
            float2 rr0 = *reinterpret_cast<const float2*>(&red[m_base + g][col]);
            float2 rr1 = *reinterpret_cast<const float2*>(&red[m_base + g + 8][col]);
            int cw = n * 4 + tq;   // word index within row
            uint32_t hw, lw;
            split2(attv[n][0] + rr0.x, attv[n][1] + rr0.y, hw, lw);
            ath[(m_base + g) * (QSTR / 2) + cw] = hw;
            atl[(m_base + g) * (QSTR / 2) + cw] = lw;
            split2(attv[n][2] + rr1.x, attv[n][3] + rr1.y, hw, lw);
            ath[(m_base + g + 8) * (QSTR / 2) + cw] = hw;
            atl[(m_base + g + 8) * (QSTR / 2) + cw] = lw;
        }
    }
    __syncthreads();

    // ---- fused output GEMM: out[64, 512] = att @ Wo + bo ----
    uint32_t oah[4][4], oal[4][4];
#pragma unroll
    for (int kc = 0; kc < 4; kc++) {
        uint32_t off = (uint32_t)(((m_base + a_row) * QSTR + kc * 16 + a_c8) * 2);
        LDSM_X4(oah[kc][0], oah[kc][1], oah[kc][2], oah[kc][3], athB + off);
        LDSM_X4(oal[kc][0], oal[kc][1], oal[kc][2], oal[kc][3], atlB + off);
    }

    const int wn = wj;          // column half within each 128-col chunk
    const int wk = t >> 2;      // Wo loader: k row
    const int seg = (t & 3) * 32;

    // prefetch Wo chunk 0 into registers
    uint4 pwh[4], pwl[4];
    {
        const uint4* sh = reinterpret_cast<const uint4*>(g_woh + (size_t)wk * DIM + seg);
        const uint4* sl = reinterpret_cast<const uint4*>(g_wol + (size_t)wk * DIM + seg);
#pragma unroll
        for (int v = 0; v < 4; v++) { pwh[v] = sh[v]; pwl[v] = sl[v]; }
    }

    const size_t row_g = (size_t)b * SEQ + q0 + m_base + g;

#pragma unroll
    for (int cc = 0; cc < 4; cc++) {
        // store prefetched Wo chunk to smem
        {
            uint4* dh = reinterpret_cast<uint4*>(&WoH[wk * WSTR + seg]);
            uint4* dl = reinterpret_cast<uint4*>(&WoL[wk * WSTR + seg]);
#pragma unroll
            for (int v = 0; v < 4; v++) { dh[v] = pwh[v]; dl[v] = pwl[v]; }
        }
        __syncthreads();
        // prefetch next chunk
        if (cc < 3) {
            const uint4* sh = reinterpret_cast<const uint4*>(
                g_woh + (size_t)wk * DIM + (cc + 1) * 128 + seg);
            const uint4* sl = reinterpret_cast<const uint4*>(
                g_wol + (size_t)wk * DIM + (cc + 1) * 128 + seg);
#pragma unroll
            for (int v = 0; v < 4; v++) { pwh[v] = sh[v]; pwl[v] = sl[v]; }
        }

        float oc[8][4];
#pragma unroll
        for (int n = 0; n < 8; n++)
#pragma unroll
            for (int r = 0; r < 4; r++) oc[n][r] = 0.0f;

#pragma unroll
        for (int kc = 0; kc < 4; kc++) {
#pragma unroll
            for (int dg = 0; dg < 4; dg += 2) {
                uint32_t vh[8], vl[8];
                uint32_t off0 = (uint32_t)(((kc * 16 + tj) * WSTR + wn * 64 + dg * 16 + td8) * 2);
                uint32_t off1 = (uint32_t)(((kc * 16 + tj) * WSTR + wn * 64 + (dg + 1) * 16 + td8) * 2);
                LDSM_X4_T(vh[0], vh[1], vh[2], vh[3], whB + off0);
                LDSM_X4_T(vh[4], vh[5], vh[6], vh[7], whB + off1);
                LDSM_X4_T(vl[0], vl[1], vl[2], vl[3], wlB + off0);
                LDSM_X4_T(vl[4], vl[5], vl[6], vl[7], wlB + off1);
                MMA_BF16(oc[2 * dg],     oah[kc], vh[0], vh[1]);
                MMA_BF16(oc[2 * dg + 1], oah[kc], vh[2], vh[3]);
                MMA_BF16(oc[2 * dg + 2], oah[kc], vh[4], vh[5]);
                MMA_BF16(oc[2 * dg + 3], oah[kc], vh[6], vh[7]);
                MMA_BF16(oc[2 * dg],     oah[kc], vl[0], vl[1]);
                MMA_BF16(oc[2 * dg + 1], oah[kc], vl[2], vl[3]);
                MMA_BF16(oc[2 * dg + 2], oah[kc], vl[4], vl[5]);
                MMA_BF16(oc[2 * dg + 3], oah[kc], vl[6], vl[7]);
                MMA_BF16(oc[2 * dg],     oal[kc], vh[0], vh[1]);
                MMA_BF16(oc[2 * dg + 1], oal[kc], vh[2], vh[3]);
                MMA_BF16(oc[2 * dg + 2], oal[kc], vh[4], vh[5]);
                MMA_BF16(oc[2 * dg + 3], oal[kc], vh[6], vh[7]);
            }
        }

        // epilogue: bias + fp32 store for this chunk
#pragma unroll
        for (int n = 0; n < 8; n++) {
            int col = cc * 128 + wn * 64 + n * 8 + tq * 2;
            float b0v = bo[col], b1v = bo[col + 1];
            float2 o0 = {oc[n][0] + b0v, oc[n][1] + b1v};
            float2 o1 = {oc[n][2] + b0v, oc[n][3] + b1v};
            *reinterpret_cast<float2*>(&out[row_g * DIM + col]) = o0;
            *reinterpret_cast<float2*>(&out[(row_g + 8) * DIM + col]) = o1;
        }
        __syncthreads();   // all reads of WoH/WoL done before next overwrite
    }
}

// ---------------------------------------------------------------------------
extern "C" void kernel_launch(void* const* d_in, const int* in_sizes, int n_in,
                              void* d_out, int out_size)
{
    const float* query = (const float*)d_in[0];
    const float* value = (const float*)d_in[1];
    const float* Wi    = (const float*)d_in[2];
    const float* bi    = (const float*)d_in[3];
    const float* Wo    = (const float*)d_in[4];
    const float* bo    = (const float*)d_in[5];
    float* out = (float*)d_out;

    static bool attr_set = false;
    if (!attr_set) {
        cudaFuncSetAttribute(proj_kernel, cudaFuncAttributeMaxDynamicSharedMemorySize,
                             PROJ_SMEM_BYTES);
        cudaFuncSetAttribute(attn_kernel, cudaFuncAttributeMaxDynamicSharedMemorySize,
                             ATTN_SMEM_BYTES);
        attr_set = true;
    }

    proj_kernel<<<MTOT / 64 + 8, 256, PROJ_SMEM_BYTES>>>(query, value, Wi, Wo, bi);
    attn_kernel<<<BATCH * (SEQ / 64), 256, ATTN_SMEM_BYTES>>>(bo, out);
}

// round 16
// speedup vs baseline: 2.1957x; 1.5084x over previous
#include <cuda_runtime.h>
#include <cuda_fp16.h>
#include <cstdint>

// Problem constants (fixed by dataset)
#define BATCH 4
#define SEQ   4096
#define DIM   512
#define DK    64
#define BAND  128
#define SCALE 0.125f            // 1/sqrt(64)
#define ROWS  (BATCH*SEQ)       // 16384
#define MTOT  (2*ROWS)          // 32768 (q rows then kv rows)

// ---- tensor-core helpers ---------------------------------------------------
#define LDSM_X4(r0, r1, r2, r3, addr) \
    asm volatile("ldmatrix.sync.aligned.m8n8.x4.shared.b16 {%0,%1,%2,%3}, [%4];" \
        : "=r"(r0), "=r"(r1), "=r"(r2), "=r"(r3) : "r"(addr))

#define LDSM_X4_T(r0, r1, r2, r3, addr) \
    asm volatile("ldmatrix.sync.aligned.m8n8.x4.trans.shared.b16 {%0,%1,%2,%3}, [%4];" \
        : "=r"(r0), "=r"(r1), "=r"(r2), "=r"(r3) : "r"(addr))

// fp16 MMA, fp32 accumulate. NOT volatile (pure register ops -> ptxas can interleave).
#define MMA_F16(c, a, b0, b1) \
    asm("mma.sync.aligned.m16n8k16.row.col.f32.f16.f16.f32 " \
        "{%0,%1,%2,%3},{%4,%5,%6,%7},{%8,%9},{%0,%1,%2,%3};" \
        : "+f"((c)[0]), "+f"((c)[1]), "+f"((c)[2]), "+f"((c)[3]) \
        : "r"((a)[0]), "r"((a)[1]), "r"((a)[2]), "r"((a)[3]), "r"(b0), "r"(b1))

#define CP_ASYNC16(dst_u32, src_ptr) \
    asm volatile("cp.async.cg.shared.global [%0], [%1], 16;" \
        :: "r"(dst_u32), "l"(src_ptr) : "memory")
#define CP_COMMIT() asm volatile("cp.async.commit_group;" ::: "memory")
#define CP_WAIT(N)  asm volatile("cp.async.wait_group %0;" :: "n"(N) : "memory")

// pack two fp32 into one fp16x2 word
__device__ __forceinline__ uint32_t cvt2h(float x0, float x1) {
    __half2 h = __floats2half2_rn(x0, x1);
    return *reinterpret_cast<uint32_t*>(&h);
}

// Scratch (device globals; no allocation allowed). fp16.
__device__ __half g_q16[ROWS * DK];
__device__ __half g_kv16[ROWS * DK];
__device__ __half g_wo16[DK * DIM];   // Wo: [k=64][n=512]

// ---------------------------------------------------------------------------
// Kernel 1: shared input projection via fp16 MMA, K-chunks of 64,
// double-buffered smem + 1-deep register prefetch. 8 tail CTAs convert Wo.
// CTA: 64 rows x 64 cols, 256 threads = 8 warps (wm 0..3 m16, wn 0..1 n32).
// ---------------------------------------------------------------------------
#define PSTR 72   // fp16 stride (64 data + 8 pad)
#define PBUF_ELEMS (64 * PSTR)               // 4608
#define PROJ_SMEM_BYTES (4 * PBUF_ELEMS * 2) // Ah[2], Wh[2] = 36864 B

__global__ void __launch_bounds__(256, 2) proj_kernel(const float* __restrict__ query,
                                                      const float* __restrict__ value,
                                                      const float* __restrict__ Wi,
                                                      const float* __restrict__ Wo,
                                                      const float* __restrict__ bi)
{
    const int t    = threadIdx.x;
    const int row0 = blockIdx.x * 64;

    // ---- tail CTAs: convert Wo to fp16 once ----
    if (row0 >= MTOT) {
        int base = (blockIdx.x - (MTOT / 64)) * 4096 + t * 16;
        const float4* wp = reinterpret_cast<const float4*>(Wo + base);
        uint32_t hw[8];
#pragma unroll
        for (int v = 0; v < 4; v++) {
            float4 f = wp[v];
            hw[2 * v]     = cvt2h(f.x, f.y);
            hw[2 * v + 1] = cvt2h(f.z, f.w);
        }
        uint4* dh = reinterpret_cast<uint4*>(g_wo16 + base);
        dh[0] = make_uint4(hw[0], hw[1], hw[2], hw[3]);
        dh[1] = make_uint4(hw[4], hw[5], hw[6], hw[7]);
        return;
    }

    extern __shared__ __align__(16) __half psmem[];
    __half* Ah = psmem;                    // [2][PBUF_ELEMS]
    __half* Wh = psmem + 2 * PBUF_ELEMS;   // [n][k]

    const int lane = t & 31;
    const int warp = t >> 5;

    const float* src;
    uint32_t* dsth;
    int roff;
    if (row0 < ROWS) {
        src = query;
        dsth = reinterpret_cast<uint32_t*>(g_q16);
        roff = row0;
    } else {
        src = value;
        dsth = reinterpret_cast<uint32_t*>(g_kv16);
        roff = row0 - ROWS;
    }

    const int wm = warp & 3;
    const int wn = warp >> 2;
    const int m_base = wm * 16;
    const int n_base = wn * 32;

    // A loader: 64 rows x 64 k fp32, each thread 16 fp32 of one row
    const int lr = t >> 2;
    const int ls = (t & 3) * 16;
    // W loader: col wcol, 16 consecutive k
    const int wcol = t & 63;
    const int wkg  = (t >> 6) * 16;

    // ldmatrix lane addressing
    const int a_row = lane & 15;
    const int a_c8  = (lane >> 4) * 8;
    const int b_row = (lane & 7) + ((lane >> 4) & 1) * 8;
    const int b_c8  = ((lane >> 3) & 1) * 8;

    const uint32_t ahB0 = (uint32_t)__cvta_generic_to_shared(Ah);
    const uint32_t whB0 = (uint32_t)__cvta_generic_to_shared(Wh);
    const uint32_t bufBytes = PBUF_ELEMS * 2;

    float c[4][4];
#pragma unroll
    for (int n = 0; n < 4; n++)
#pragma unroll
        for (int r = 0; r < 4; r++) c[n][r] = 0.0f;

    // 1-deep register prefetch
    float4 fA[4];
    float wv[16];

    const float* arow_p = src + (size_t)(roff + lr) * DIM + ls;

    // load chunk 0
    {
        const float4* ap = reinterpret_cast<const float4*>(arow_p);
#pragma unroll
        for (int v = 0; v < 4; v++) fA[v] = ap[v];
        const float* wp = Wi + (size_t)wkg * DK + wcol;
#pragma unroll
        for (int j = 0; j < 16; j++) wv[j] = wp[j * DK];
    }

    for (int k0i = 0; k0i < 8; k0i++) {
        const int buf = k0i & 1;
        // convert + store prefetched chunk into smem[buf]
        {
            uint32_t hw[8];
#pragma unroll
            for (int v = 0; v < 4; v++) {
                hw[2 * v]     = cvt2h(fA[v].x, fA[v].y);
                hw[2 * v + 1] = cvt2h(fA[v].z, fA[v].w);
            }
            int wo = lr * (PSTR / 2) + (ls >> 1);
            uint32_t* ahW = reinterpret_cast<uint32_t*>(Ah + buf * PBUF_ELEMS);
            *reinterpret_cast<uint4*>(ahW + wo)     = make_uint4(hw[0], hw[1], hw[2], hw[3]);
            *reinterpret_cast<uint4*>(ahW + wo + 4) = make_uint4(hw[4], hw[5], hw[6], hw[7]);
#pragma unroll
            for (int v = 0; v < 8; v++) hw[v] = cvt2h(wv[2 * v], wv[2 * v + 1]);
            int wo2 = wcol * (PSTR / 2) + (wkg >> 1);
            uint32_t* whW = reinterpret_cast<uint32_t*>(Wh + buf * PBUF_ELEMS);
            *reinterpret_cast<uint4*>(whW + wo2)     = make_uint4(hw[0], hw[1], hw[2], hw[3]);
            *reinterpret_cast<uint4*>(whW + wo2 + 4) = make_uint4(hw[4], hw[5], hw[6], hw[7]);
        }
        __syncthreads();

        // issue global loads for next chunk (overlap with MMA below)
        if (k0i < 7) {
            int k0 = (k0i + 1) * 64;
            const float4* ap = reinterpret_cast<const float4*>(arow_p + k0);
#pragma unroll
            for (int v = 0; v < 4; v++) fA[v] = ap[v];
            const float* wp = Wi + (size_t)(k0 + wkg) * DK + wcol;
#pragma unroll
            for (int j = 0; j < 16; j++) wv[j] = wp[j * DK];
        }

        const uint32_t ahB = ahB0 + buf * bufBytes;
        const uint32_t whB = whB0 + buf * bufBytes;

#pragma unroll
        for (int ks = 0; ks < 64; ks += 16) {
            uint32_t ah[4];
            {
                uint32_t off = (uint32_t)(((m_base + a_row) * PSTR + ks + a_c8) * 2);
                LDSM_X4(ah[0], ah[1], ah[2], ah[3], ahB + off);
            }
            uint32_t bh[8];
            {
                uint32_t off0 = (uint32_t)(((n_base + b_row) * PSTR + ks + b_c8) * 2);
                uint32_t off1 = off0 + 16 * PSTR * 2;
                LDSM_X4(bh[0], bh[1], bh[2], bh[3], whB + off0);
                LDSM_X4(bh[4], bh[5], bh[6], bh[7], whB + off1);
            }
#pragma unroll
            for (int n = 0; n < 4; n++) MMA_F16(c[n], ah, bh[2 * n], bh[2 * n + 1]);
        }
    }

    // epilogue: add bias, convert to fp16, store packed words
    const int g = lane >> 2, tig = lane & 3;
    {
        int row = roff + m_base + g;
#pragma unroll
        for (int n = 0; n < 4; n++) {
            int col = n_base + n * 8 + tig * 2;
            float b0v = bi[col], b1v = bi[col + 1];
            dsth[(size_t)row * 32 + (col >> 1)]       = cvt2h(c[n][0] + b0v, c[n][1] + b1v);
            dsth[(size_t)(row + 8) * 32 + (col >> 1)] = cvt2h(c[n][2] + b0v, c[n][3] + b1v);
        }
    }
}

// ---------------------------------------------------------------------------
// Kernel 2: banded attention + fused output projection, fp16 single-term.
// K tiles cp.async double-buffered.
// ---------------------------------------------------------------------------
#define QSTR 72    // fp16 stride for 64-wide tiles (144B rows)
#define WSTR 136   // fp16 stride for 128-wide Wo chunks
#define KBUF_BYTES (64 * QSTR * 2)   // 9216
// smem byte offsets
#define Q_OFF    0            // Qh 9216
#define K_OFF    9216         // Kh[2] 18432
#define RED_OFF  27648        // float red[64][66] = 16896
#define ATT_OFF  44544        // AttH 9216
#define ATTN_SMEM_BYTES 53760
// Wo chunk aliases the Q/K region: WoH @0 (17408B < 27648)

__global__ void __launch_bounds__(256, 2) attn_kernel(const float* __restrict__ bo,
                                                      float* __restrict__ out)
{
    extern __shared__ __align__(16) char asmem[];
    __half* Qh = reinterpret_cast<__half*>(asmem + Q_OFF);
    float (*red)[66]  = reinterpret_cast<float(*)[66]>(asmem + RED_OFF);
    __half* AttH = reinterpret_cast<__half*>(asmem + ATT_OFF);
    __half* WoH = reinterpret_cast<__half*>(asmem);   // alias over Q/K region

    const int t    = threadIdx.x;
    const int lane = t & 31;
    const int warp = t >> 5;
    const int b    = blockIdx.x >> 6;
    const int qs   = blockIdx.x & 63;
    const int q0   = qs * 64;

    const int wm = warp & 3;
    const int wj = warp >> 2;
    const int m_base = wm * 16;
    const int jcol0  = wj * 32;

    const uint32_t qhB = (uint32_t)__cvta_generic_to_shared(Qh);
    const uint32_t smemB = (uint32_t)__cvta_generic_to_shared(asmem);
    const uint32_t athB = (uint32_t)__cvta_generic_to_shared(AttH);
    const uint32_t whB = (uint32_t)__cvta_generic_to_shared(WoH);

    // loaders: rows r0 & r0+32, 16B segment s0 (row = 64 fp16 = 128 B = 8 segs)
    const int r0 = t >> 3;
    const int s0 = t & 7;

    // ---- prologue: cp.async Q tile (group 0), K tile 0 (group 1) ----
    {
        size_t gb0 = ((size_t)b * SEQ + q0 + r0) * DK + s0 * 8;
        size_t gb1 = gb0 + (size_t)32 * DK;
        uint32_t d0 = r0 * QSTR * 2 + s0 * 16;
        uint32_t d1 = (r0 + 32) * QSTR * 2 + s0 * 16;
        CP_ASYNC16(qhB + d0, g_q16 + gb0);
        CP_ASYNC16(qhB + d1, g_q16 + gb1);
    }
    CP_COMMIT();

    // build valid tile list
    int tiles[5];
    int nt = 0;
    for (int jt = qs - 2; jt <= qs + 2; jt++)
        if (jt >= 0 && jt < 64) tiles[nt++] = jt;

    // issue K tile 0 into buf 0
    {
        size_t gb0 = ((size_t)b * SEQ + tiles[0] * 64 + r0) * DK + s0 * 8;
        size_t gb1 = gb0 + (size_t)32 * DK;
        uint32_t kh = smemB + K_OFF;
        uint32_t d0 = r0 * QSTR * 2 + s0 * 16;
        uint32_t d1 = (r0 + 32) * QSTR * 2 + s0 * 16;
        CP_ASYNC16(kh + d0, g_kv16 + gb0);
        CP_ASYNC16(kh + d1, g_kv16 + gb1);
    }
    CP_COMMIT();

    CP_WAIT(1);          // Q complete
    __syncthreads();

    // ldmatrix lane addressing
    const int a_row = lane & 15;
    const int a_c8  = (lane >> 4) * 8;
    const int b_row = (lane & 7) + ((lane >> 4) & 1) * 8;
    const int b_c8  = ((lane >> 3) & 1) * 8;
    const int tj    = (lane & 7) + ((lane >> 3) & 1) * 8;
    const int td8   = (lane >> 4) * 8;

    // Q a-fragments: persistent across all j-tiles
    uint32_t qha[4][4];
#pragma unroll
    for (int kc = 0; kc < 4; kc++) {
        uint32_t off = (uint32_t)(((m_base + a_row) * QSTR + kc * 16 + a_c8) * 2);
        LDSM_X4(qha[kc][0], qha[kc][1], qha[kc][2], qha[kc][3], qhB + off);
    }

    float attv[8][4];
#pragma unroll
    for (int n = 0; n < 8; n++)
#pragma unroll
        for (int r = 0; r < 4; r++) attv[n][r] = 0.0f;

    const int g = lane >> 2, tq = lane & 3;
    const int gi_lo = q0 + m_base;
    const int gi_hi = gi_lo + 15;

    for (int it = 0; it < nt; it++) {
        const int jt  = tiles[it];
        const int cur = it & 1;
        CP_WAIT(0);          // tile it resident
        __syncthreads();     // all warps done reading other buf

        // issue cp.async for tile it+1 into the other buffer (overlaps compute)
        if (it + 1 < nt) {
            size_t gb0 = ((size_t)b * SEQ + tiles[it + 1] * 64 + r0) * DK + s0 * 8;
            size_t gb1 = gb0 + (size_t)32 * DK;
            uint32_t kh = smemB + K_OFF + (cur ^ 1) * KBUF_BYTES;
            uint32_t d0 = r0 * QSTR * 2 + s0 * 16;
            uint32_t d1 = (r0 + 32) * QSTR * 2 + s0 * 16;
            CP_ASYNC16(kh + d0, g_kv16 + gb0);
            CP_ASYNC16(kh + d1, g_kv16 + gb1);
            CP_COMMIT();
        }

        const uint32_t khB = smemB + K_OFF + cur * KBUF_BYTES;
        const int jbase = jt * 64;

        // block in-band predicates for this warp's two 16-wide j blocks
        bool keep[2];
#pragma unroll
        for (int blk = 0; blk < 2; blk++) {
            int jlo = jbase + jcol0 + blk * 16;
            keep[blk] = !(gi_lo - (jlo + 15) > BAND || jlo - gi_hi > BAND);
        }

        // ---- Phase A: S (m16 x n32) = Q K^T ----
        float S[4][4];
#pragma unroll
        for (int n = 0; n < 4; n++)
#pragma unroll
            for (int r = 0; r < 4; r++) S[n][r] = 0.0f;

#pragma unroll
        for (int kc = 0; kc < 4; kc++) {
#pragma unroll
            for (int ng = 0; ng < 2; ng++) {
                if (!keep[ng]) continue;
                uint32_t off = (uint32_t)(((jcol0 + ng * 16 + b_row) * QSTR + kc * 16 + b_c8) * 2);
                uint32_t bh[4];
                LDSM_X4(bh[0], bh[1], bh[2], bh[3], khB + off);
                MMA_F16(S[2 * ng],     qha[kc], bh[0], bh[1]);
                MMA_F16(S[2 * ng + 1], qha[kc], bh[2], bh[3]);
            }
        }

        // ---- mask + scale in registers ----
        const int gi0 = gi_lo + g;
#pragma unroll
        for (int n = 0; n < 4; n++) {
            int gj = jbase + jcol0 + n * 8 + tq * 2;
            int d0 = gi0 - gj;
            int d1 = d0 - 1;
            int d2 = d0 + 8;
            int d3 = d2 - 1;
            S[n][0] = (d0 <= BAND && d0 >= -BAND) ? S[n][0] * SCALE : 0.0f;
            S[n][1] = (d1 <= BAND && d1 >= -BAND) ? S[n][1] * SCALE : 0.0f;
            S[n][2] = (d2 <= BAND && d2 >= -BAND) ? S[n][2] * SCALE : 0.0f;
            S[n][3] = (d3 <= BAND && d3 >= -BAND) ? S[n][3] * SCALE : 0.0f;
        }

        // ---- convert S C-frags into phase-B A-frags (fp16) ----
        uint32_t pah[2][4];
#pragma unroll
        for (int kc = 0; kc < 2; kc++) {
            pah[kc][0] = cvt2h(S[2 * kc][0],     S[2 * kc][1]);
            pah[kc][1] = cvt2h(S[2 * kc][2],     S[2 * kc][3]);
            pah[kc][2] = cvt2h(S[2 * kc + 1][0], S[2 * kc + 1][1]);
            pah[kc][3] = cvt2h(S[2 * kc + 1][2], S[2 * kc + 1][3]);
        }

        // ---- Phase B: attv += S @ KV (this warp's j-half) ----
#pragma unroll
        for (int kc = 0; kc < 2; kc++) {
            if (!keep[kc]) continue;
#pragma unroll
            for (int dg = 0; dg < 4; dg += 2) {
                uint32_t vh[8];
                uint32_t off0 = (uint32_t)(((jcol0 + kc * 16 + tj) * QSTR + dg * 16 + td8) * 2);
                uint32_t off1 = (uint32_t)(((jcol0 + kc * 16 + tj) * QSTR + (dg + 1) * 16 + td8) * 2);
                LDSM_X4_T(vh[0], vh[1], vh[2], vh[3], khB + off0);
                LDSM_X4_T(vh[4], vh[5], vh[6], vh[7], khB + off1);
                MMA_F16(attv[2 * dg],     pah[kc], vh[0], vh[1]);
                MMA_F16(attv[2 * dg + 1], pah[kc], vh[2], vh[3]);
                MMA_F16(attv[2 * dg + 2], pah[kc], vh[4], vh[5]);
                MMA_F16(attv[2 * dg + 3], pah[kc], vh[6], vh[7]);
            }
        }
    }

    // ---- cross-warp reduction over wj; att (fp16) goes to smem ----
    __syncthreads();
    if (wj == 1) {
#pragma unroll
        for (int n = 0; n < 8; n++) {
            int col = n * 8 + tq * 2;
            *reinterpret_cast<float2*>(&red[m_base + g][col])     = make_float2(attv[n][0], attv[n][1]);
            *reinterpret_cast<float2*>(&red[m_base + g + 8][col]) = make_float2(attv[n][2], attv[n][3]);
        }
    }
    __syncthreads();
    if (wj == 0) {
        uint32_t* ath = reinterpret_cast<uint32_t*>(AttH);
#pragma unroll
        for (int n = 0; n < 8; n++) {
            int col = n * 8 + tq * 2;
            float2 rr0 = *reinterpret_cast<const float2*>(&red[m_base + g][col]);
            float2 rr1 = *reinterpret_cast<const float2*>(&red[m_base + g + 8][col]);
            int cw = n * 4 + tq;   // word index within row
            ath[(m_base + g) * (QSTR / 2) + cw]     = cvt2h(attv[n][0] + rr0.x, attv[n][1] + rr0.y);
            ath[(m_base + g + 8) * (QSTR / 2) + cw] = cvt2h(attv[n][2] + rr1.x, attv[n][3] + rr1.y);
        }
    }
    __syncthreads();

    // ---- fused output GEMM: out[64, 512] = att @ Wo + bo ----
    uint32_t oah[4][4];
#pragma unroll
    for (int kc = 0; kc < 4; kc++) {
        uint32_t off = (uint32_t)(((m_base + a_row) * QSTR + kc * 16 + a_c8) * 2);
        LDSM_X4(oah[kc][0], oah[kc][1], oah[kc][2], oah[kc][3], athB + off);
    }

    const int wn = wj;          // column half within each 128-col chunk
    const int wk = t >> 2;      // Wo loader: k row
    const int seg = (t & 3) * 32;

    // prefetch Wo chunk 0 into registers
    uint4 pwh[4];
    {
        const uint4* sh = reinterpret_cast<const uint4*>(g_wo16 + (size_t)wk * DIM + seg);
#pragma unroll
        for (int v = 0; v < 4; v++) pwh[v] = sh[v];
    }

    const size_t row_g = (size_t)b * SEQ + q0 + m_base + g;

#pragma unroll
    for (int cc = 0; cc < 4; cc++) {
        // store prefetched Wo chunk to smem
        {
            uint4* dh = reinterpret_cast<uint4*>(&WoH[wk * WSTR + seg]);
#pragma unroll
            for (int v = 0; v < 4; v++) dh[v] = pwh[v];
        }
        __syncthreads();
        // prefetch next chunk
        if (cc < 3) {
            const uint4* sh = reinterpret_cast<const uint4*>(
                g_wo16 + (size_t)wk * DIM + (cc + 1) * 128 + seg);
#pragma unroll
            for (int v = 0; v < 4; v++) pwh[v] = sh[v];
        }

        float oc[8][4];
#pragma unroll
        for (int n = 0; n < 8; n++)
#pragma unroll
            for (int r = 0; r < 4; r++) oc[n][r] = 0.0f;

#pragma unroll
        for (int kc = 0; kc < 4; kc++) {
#pragma unroll
            for (int dg = 0; dg < 4; dg += 2) {
                uint32_t vh[8];
                uint32_t off0 = (uint32_t)(((kc * 16 + tj) * WSTR + wn * 64 + dg * 16 + td8) * 2);
                uint32_t off1 = (uint32_t)(((kc * 16 + tj) * WSTR + wn * 64 + (dg + 1) * 16 + td8) * 2);
                LDSM_X4_T(vh[0], vh[1], vh[2], vh[3], whB + off0);
                LDSM_X4_T(vh[4], vh[5], vh[6], vh[7], whB + off1);
                MMA_F16(oc[2 * dg],     oah[kc], vh[0], vh[1]);
                MMA_F16(oc[2 * dg + 1], oah[kc], vh[2], vh[3]);
                MMA_F16(oc[2 * dg + 2], oah[kc], vh[4], vh[5]);
                MMA_F16(oc[2 * dg + 3], oah[kc], vh[6], vh[7]);
            }
        }

        // epilogue: bias + fp32 store for this chunk
#pragma unroll
        for (int n = 0; n < 8; n++) {
            int col = cc * 128 + wn * 64 + n * 8 + tq * 2;
            float b0v = bo[col], b1v = bo[col + 1];
            float2 o0 = {oc[n][0] + b0v, oc[n][1] + b1v};
            float2 o1 = {oc[n][2] + b0v, oc[n][3] + b1v};
            *reinterpret_cast<float2*>(&out[row_g * DIM + col]) = o0;
            *reinterpret_cast<float2*>(&out[(row_g + 8) * DIM + col]) = o1;
        }
        __syncthreads();   // all reads of WoH done before next overwrite
    }
}

// ---------------------------------------------------------------------------
extern "C" void kernel_launch(void* const* d_in, const int* in_sizes, int n_in,
                              void* d_out, int out_size)
{
    const float* query = (const float*)d_in[0];
    const float* value = (const float*)d_in[1];
    const float* Wi    = (const float*)d_in[2];
    const float* bi    = (const float*)d_in[3];
    const float* Wo    = (const float*)d_in[4];
    const float* bo    = (const float*)d_in[5];
    float* out = (float*)d_out;

    static bool attr_set = false;
    if (!attr_set) {
        cudaFuncSetAttribute(proj_kernel, cudaFuncAttributeMaxDynamicSharedMemorySize,
                             PROJ_SMEM_BYTES);
        cudaFuncSetAttribute(attn_kernel, cudaFuncAttributeMaxDynamicSharedMemorySize,
                             ATTN_SMEM_BYTES);
        attr_set = true;
    }

    proj_kernel<<<MTOT / 64 + 8, 256, PROJ_SMEM_BYTES>>>(query, value, Wi, Wo, bi);
    attn_kernel<<<BATCH * (SEQ / 64), 256, ATTN_SMEM_BYTES>>>(bo, out);
}

// round 17
// speedup vs baseline: 2.2211x; 1.0116x over previous
#include <cuda_runtime.h>
#include <cuda_fp16.h>
#include <cstdint>

// Problem constants (fixed by dataset)
#define BATCH 4
#define SEQ   4096
#define DIM   512
#define DK    64
#define BAND  128
#define SCALE 0.125f            // 1/sqrt(64)
#define ROWS  (BATCH*SEQ)       // 16384
#define MTOT  (2*ROWS)          // 32768 (q rows then kv rows)

// ---- tensor-core helpers ---------------------------------------------------
#define LDSM_X4(r0, r1, r2, r3, addr) \
    asm volatile("ldmatrix.sync.aligned.m8n8.x4.shared.b16 {%0,%1,%2,%3}, [%4];" \
        : "=r"(r0), "=r"(r1), "=r"(r2), "=r"(r3) : "r"(addr))

#define LDSM_X4_T(r0, r1, r2, r3, addr) \
    asm volatile("ldmatrix.sync.aligned.m8n8.x4.trans.shared.b16 {%0,%1,%2,%3}, [%4];" \
        : "=r"(r0), "=r"(r1), "=r"(r2), "=r"(r3) : "r"(addr))

// fp16 MMA, fp32 accumulate. NOT volatile (pure register ops -> ptxas can interleave).
#define MMA_F16(c, a, b0, b1) \
    asm("mma.sync.aligned.m16n8k16.row.col.f32.f16.f16.f32 " \
        "{%0,%1,%2,%3},{%4,%5,%6,%7},{%8,%9},{%0,%1,%2,%3};" \
        : "+f"((c)[0]), "+f"((c)[1]), "+f"((c)[2]), "+f"((c)[3]) \
        : "r"((a)[0]), "r"((a)[1]), "r"((a)[2]), "r"((a)[3]), "r"(b0), "r"(b1))

#define CP_ASYNC16(dst_u32, src_ptr) \
    asm volatile("cp.async.cg.shared.global [%0], [%1], 16;" \
        :: "r"(dst_u32), "l"(src_ptr) : "memory")
#define CP_COMMIT() asm volatile("cp.async.commit_group;" ::: "memory")
#define CP_WAIT(N)  asm volatile("cp.async.wait_group %0;" :: "n"(N) : "memory")

// pack two fp32 into one fp16x2 word
__device__ __forceinline__ uint32_t cvt2h(float x0, float x1) {
    __half2 h = __floats2half2_rn(x0, x1);
    return *reinterpret_cast<uint32_t*>(&h);
}

// Scratch (device globals; no allocation allowed). fp16.
__device__ __half g_q16[ROWS * DK];
__device__ __half g_kv16[ROWS * DK];
__device__ __half g_wo16[DK * DIM];   // Wo: [k=64][n=512]

// ---------------------------------------------------------------------------
// Kernel 1: shared input projection via fp16 MMA, K-chunks of 64,
// double-buffered smem + 1-deep register prefetch. 8 tail CTAs convert Wo.
// CTA: 64 rows x 64 cols, 256 threads = 8 warps (wm 0..3 m16, wn 0..1 n32).
// (unchanged from the 47.6us version)
// ---------------------------------------------------------------------------
#define PSTR 72   // fp16 stride (64 data + 8 pad)
#define PBUF_ELEMS (64 * PSTR)               // 4608
#define PROJ_SMEM_BYTES (4 * PBUF_ELEMS * 2) // Ah[2], Wh[2] = 36864 B

__global__ void __launch_bounds__(256, 2) proj_kernel(const float* __restrict__ query,
                                                      const float* __restrict__ value,
                                                      const float* __restrict__ Wi,
                                                      const float* __restrict__ Wo,
                                                      const float* __restrict__ bi)
{
    const int t    = threadIdx.x;
    const int row0 = blockIdx.x * 64;

    // ---- tail CTAs: convert Wo to fp16 once ----
    if (row0 >= MTOT) {
        int base = (blockIdx.x - (MTOT / 64)) * 4096 + t * 16;
        const float4* wp = reinterpret_cast<const float4*>(Wo + base);
        uint32_t hw[8];
#pragma unroll
        for (int v = 0; v < 4; v++) {
            float4 f = wp[v];
            hw[2 * v]     = cvt2h(f.x, f.y);
            hw[2 * v + 1] = cvt2h(f.z, f.w);
        }
        uint4* dh = reinterpret_cast<uint4*>(g_wo16 + base);
        dh[0] = make_uint4(hw[0], hw[1], hw[2], hw[3]);
        dh[1] = make_uint4(hw[4], hw[5], hw[6], hw[7]);
        return;
    }

    extern __shared__ __align__(16) __half psmem[];
    __half* Ah = psmem;                    // [2][PBUF_ELEMS]
    __half* Wh = psmem + 2 * PBUF_ELEMS;   // [n][k]

    const int lane = t & 31;
    const int warp = t >> 5;

    const float* src;
    uint32_t* dsth;
    int roff;
    if (row0 < ROWS) {
        src = query;
        dsth = reinterpret_cast<uint32_t*>(g_q16);
        roff = row0;
    } else {
        src = value;
        dsth = reinterpret_cast<uint32_t*>(g_kv16);
        roff = row0 - ROWS;
    }

    const int wm = warp & 3;
    const int wn = warp >> 2;
    const int m_base = wm * 16;
    const int n_base = wn * 32;

    // A loader: 64 rows x 64 k fp32, each thread 16 fp32 of one row
    const int lr = t >> 2;
    const int ls = (t & 3) * 16;
    // W loader: col wcol, 16 consecutive k
    const int wcol = t & 63;
    const int wkg  = (t >> 6) * 16;

    // ldmatrix lane addressing
    const int a_row = lane & 15;
    const int a_c8  = (lane >> 4) * 8;
    const int b_row = (lane & 7) + ((lane >> 4) & 1) * 8;
    const int b_c8  = ((lane >> 3) & 1) * 8;

    const uint32_t ahB0 = (uint32_t)__cvta_generic_to_shared(Ah);
    const uint32_t whB0 = (uint32_t)__cvta_generic_to_shared(Wh);
    const uint32_t bufBytes = PBUF_ELEMS * 2;

    float c[4][4];
#pragma unroll
    for (int n = 0; n < 4; n++)
#pragma unroll
        for (int r = 0; r < 4; r++) c[n][r] = 0.0f;

    // 1-deep register prefetch
    float4 fA[4];
    float wv[16];

    const float* arow_p = src + (size_t)(roff + lr) * DIM + ls;

    // load chunk 0
    {
        const float4* ap = reinterpret_cast<const float4*>(arow_p);
#pragma unroll
        for (int v = 0; v < 4; v++) fA[v] = ap[v];
        const float* wp = Wi + (size_t)wkg * DK + wcol;
#pragma unroll
        for (int j = 0; j < 16; j++) wv[j] = wp[j * DK];
    }

    for (int k0i = 0; k0i < 8; k0i++) {
        const int buf = k0i & 1;
        // convert + store prefetched chunk into smem[buf]
        {
            uint32_t hw[8];
#pragma unroll
            for (int v = 0; v < 4; v++) {
                hw[2 * v]     = cvt2h(fA[v].x, fA[v].y);
                hw[2 * v + 1] = cvt2h(fA[v].z, fA[v].w);
            }
            int wo = lr * (PSTR / 2) + (ls >> 1);
            uint32_t* ahW = reinterpret_cast<uint32_t*>(Ah + buf * PBUF_ELEMS);
            *reinterpret_cast<uint4*>(ahW + wo)     = make_uint4(hw[0], hw[1], hw[2], hw[3]);
            *reinterpret_cast<uint4*>(ahW + wo + 4) = make_uint4(hw[4], hw[5], hw[6], hw[7]);
#pragma unroll
            for (int v = 0; v < 8; v++) hw[v] = cvt2h(wv[2 * v], wv[2 * v + 1]);
            int wo2 = wcol * (PSTR / 2) + (wkg >> 1);
            uint32_t* whW = reinterpret_cast<uint32_t*>(Wh + buf * PBUF_ELEMS);
            *reinterpret_cast<uint4*>(whW + wo2)     = make_uint4(hw[0], hw[1], hw[2], hw[3]);
            *reinterpret_cast<uint4*>(whW + wo2 + 4) = make_uint4(hw[4], hw[5], hw[6], hw[7]);
        }
        __syncthreads();

        // issue global loads for next chunk (overlap with MMA below)
        if (k0i < 7) {
            int k0 = (k0i + 1) * 64;
            const float4* ap = reinterpret_cast<const float4*>(arow_p + k0);
#pragma unroll
            for (int v = 0; v < 4; v++) fA[v] = ap[v];
            const float* wp = Wi + (size_t)(k0 + wkg) * DK + wcol;
#pragma unroll
            for (int j = 0; j < 16; j++) wv[j] = wp[j * DK];
        }

        const uint32_t ahB = ahB0 + buf * bufBytes;
        const uint32_t whB = whB0 + buf * bufBytes;

#pragma unroll
        for (int ks = 0; ks < 64; ks += 16) {
            uint32_t ah[4];
            {
                uint32_t off = (uint32_t)(((m_base + a_row) * PSTR + ks + a_c8) * 2);
                LDSM_X4(ah[0], ah[1], ah[2], ah[3], ahB + off);
            }
            uint32_t bh[8];
            {
                uint32_t off0 = (uint32_t)(((n_base + b_row) * PSTR + ks + b_c8) * 2);
                uint32_t off1 = off0 + 16 * PSTR * 2;
                LDSM_X4(bh[0], bh[1], bh[2], bh[3], whB + off0);
                LDSM_X4(bh[4], bh[5], bh[6], bh[7], whB + off1);
            }
#pragma unroll
            for (int n = 0; n < 4; n++) MMA_F16(c[n], ah, bh[2 * n], bh[2 * n + 1]);
        }
    }

    // epilogue: add bias, convert to fp16, store packed words
    const int g = lane >> 2, tig = lane & 3;
    {
        int row = roff + m_base + g;
#pragma unroll
        for (int n = 0; n < 4; n++) {
            int col = n_base + n * 8 + tig * 2;
            float b0v = bi[col], b1v = bi[col + 1];
            dsth[(size_t)row * 32 + (col >> 1)]       = cvt2h(c[n][0] + b0v, c[n][1] + b1v);
            dsth[(size_t)(row + 8) * 32 + (col >> 1)] = cvt2h(c[n][2] + b0v, c[n][3] + b1v);
        }
    }
}

// ---------------------------------------------------------------------------
// Kernel 2: banded attention + fused output projection, fp16.
// Wo is loaded ONCE into a dedicated smem region in the prologue (cp.async,
// overlapped with the attention mainloop). The fused out-GEMM reads it
// directly: no staging, no syncs in the chunk loop.
// smem: [Qh 9216 -> later AttH] [Kh[2] 18432 -> later red 16896] [WoH 66560]
// ---------------------------------------------------------------------------
#define QSTR 72        // fp16 stride for 64-wide tiles (144B rows)
#define WSTRF 520      // fp16 stride for full 512-wide Wo (1040B rows, odd granules)
#define KBUF_BYTES (64 * QSTR * 2)   // 9216
#define Q_OFF    0                    // Qh 9216 ; AttH aliases after mainloop
#define K_OFF    9216                 // Kh[2] 18432 ; red aliases after mainloop
#define WO_OFF   27648                // WoH 64*520*2 = 66560
#define ATTN_SMEM_BYTES (27648 + 66560)   // 94208

__global__ void __launch_bounds__(256, 2) attn_kernel(const float* __restrict__ bo,
                                                      float* __restrict__ out)
{
    extern __shared__ __align__(16) char asmem[];
    __half* Qh = reinterpret_cast<__half*>(asmem + Q_OFF);
    float (*red)[66]  = reinterpret_cast<float(*)[66]>(asmem + K_OFF);   // alias (post-loop)
    __half* AttH = reinterpret_cast<__half*>(asmem + Q_OFF);             // alias (post-loop)

    const int t    = threadIdx.x;
    const int lane = t & 31;
    const int warp = t >> 5;
    const int b    = blockIdx.x >> 6;
    const int qs   = blockIdx.x & 63;
    const int q0   = qs * 64;

    const int wm = warp & 3;
    const int wj = warp >> 2;
    const int m_base = wm * 16;
    const int jcol0  = wj * 32;

    const uint32_t smemB = (uint32_t)__cvta_generic_to_shared(asmem);
    const uint32_t qhB  = smemB + Q_OFF;
    const uint32_t athB = smemB + Q_OFF;
    const uint32_t whB  = smemB + WO_OFF;

    // loaders: rows r0 & r0+32, 16B segment s0 (row = 64 fp16 = 128 B = 8 segs)
    const int r0 = t >> 3;
    const int s0 = t & 7;

    // ---- prologue: cp.async Q (group 0), K tile 0 (group 1), Wo (group 2) ----
    {
        size_t gb0 = ((size_t)b * SEQ + q0 + r0) * DK + s0 * 8;
        size_t gb1 = gb0 + (size_t)32 * DK;
        uint32_t d0 = r0 * QSTR * 2 + s0 * 16;
        uint32_t d1 = (r0 + 32) * QSTR * 2 + s0 * 16;
        CP_ASYNC16(qhB + d0, g_q16 + gb0);
        CP_ASYNC16(qhB + d1, g_q16 + gb1);
    }
    CP_COMMIT();

    // build valid tile list
    int tiles[5];
    int nt = 0;
    for (int jt = qs - 2; jt <= qs + 2; jt++)
        if (jt >= 0 && jt < 64) tiles[nt++] = jt;

    // issue K tile 0 into buf 0
    {
        size_t gb0 = ((size_t)b * SEQ + tiles[0] * 64 + r0) * DK + s0 * 8;
        size_t gb1 = gb0 + (size_t)32 * DK;
        uint32_t kh = smemB + K_OFF;
        uint32_t d0 = r0 * QSTR * 2 + s0 * 16;
        uint32_t d1 = (r0 + 32) * QSTR * 2 + s0 * 16;
        CP_ASYNC16(kh + d0, g_kv16 + gb0);
        CP_ASYNC16(kh + d1, g_kv16 + gb1);
    }
    CP_COMMIT();

    // issue Wo load (64 rows x 1024 B = 4096 segments, 16 per thread)
    {
#pragma unroll
        for (int i = 0; i < 16; i++) {
            int f = t + i * 256;
            int wr = f >> 6;         // Wo row (k)
            int wsg = f & 63;        // 16B segment within row
            CP_ASYNC16(whB + (uint32_t)(wr * (WSTRF * 2) + wsg * 16),
                       g_wo16 + (size_t)wr * DIM + wsg * 8);
        }
    }
    CP_COMMIT();

    CP_WAIT(2);          // Q complete (K0/Wo may still be in flight)
    __syncthreads();

    // ldmatrix lane addressing
    const int a_row = lane & 15;
    const int a_c8  = (lane >> 4) * 8;
    const int b_row = (lane & 7) + ((lane >> 4) & 1) * 8;
    const int b_c8  = ((lane >> 3) & 1) * 8;
    const int tj    = (lane & 7) + ((lane >> 3) & 1) * 8;
    const int td8   = (lane >> 4) * 8;

    // Q a-fragments: persistent across all j-tiles
    uint32_t qha[4][4];
#pragma unroll
    for (int kc = 0; kc < 4; kc++) {
        uint32_t off = (uint32_t)(((m_base + a_row) * QSTR + kc * 16 + a_c8) * 2);
        LDSM_X4(qha[kc][0], qha[kc][1], qha[kc][2], qha[kc][3], qhB + off);
    }

    float attv[8][4];
#pragma unroll
    for (int n = 0; n < 8; n++)
#pragma unroll
        for (int r = 0; r < 4; r++) attv[n][r] = 0.0f;

    const int g = lane >> 2, tq = lane & 3;
    const int gi_lo = q0 + m_base;
    const int gi_hi = gi_lo + 15;

    for (int it = 0; it < nt; it++) {
        const int jt  = tiles[it];
        const int cur = it & 1;
        CP_WAIT(0);          // tile it (and, on it==0, Wo) resident
        __syncthreads();     // all warps done reading other buf

        // issue cp.async for tile it+1 into the other buffer (overlaps compute)
        if (it + 1 < nt) {
            size_t gb0 = ((size_t)b * SEQ + tiles[it + 1] * 64 + r0) * DK + s0 * 8;
            size_t gb1 = gb0 + (size_t)32 * DK;
            uint32_t kh = smemB + K_OFF + (cur ^ 1) * KBUF_BYTES;
            uint32_t d0 = r0 * QSTR * 2 + s0 * 16;
            uint32_t d1 = (r0 + 32) * QSTR * 2 + s0 * 16;
            CP_ASYNC16(kh + d0, g_kv16 + gb0);
            CP_ASYNC16(kh + d1, g_kv16 + gb1);
            CP_COMMIT();
        }

        const uint32_t khB = smemB + K_OFF + cur * KBUF_BYTES;
        const int jbase = jt * 64;

        // block in-band predicates for this warp's two 16-wide j blocks
        bool keep[2];
#pragma unroll
        for (int blk = 0; blk < 2; blk++) {
            int jlo = jbase + jcol0 + blk * 16;
            keep[blk] = !(gi_lo - (jlo + 15) > BAND || jlo - gi_hi > BAND);
        }

        // ---- Phase A: S (m16 x n32) = Q K^T ----
        float S[4][4];
#pragma unroll
        for (int n = 0; n < 4; n++)
#pragma unroll
            for (int r = 0; r < 4; r++) S[n][r] = 0.0f;

#pragma unroll
        for (int kc = 0; kc < 4; kc++) {
#pragma unroll
            for (int ng = 0; ng < 2; ng++) {
                if (!keep[ng]) continue;
                uint32_t off = (uint32_t)(((jcol0 + ng * 16 + b_row) * QSTR + kc * 16 + b_c8) * 2);
                uint32_t bh[4];
                LDSM_X4(bh[0], bh[1], bh[2], bh[3], khB + off);
                MMA_F16(S[2 * ng],     qha[kc], bh[0], bh[1]);
                MMA_F16(S[2 * ng + 1], qha[kc], bh[2], bh[3]);
            }
        }

        // ---- mask + scale in registers ----
        const int gi0 = gi_lo + g;
#pragma unroll
        for (int n = 0; n < 4; n++) {
            int gj = jbase + jcol0 + n * 8 + tq * 2;
            int d0 = gi0 - gj;
            int d1 = d0 - 1;
            int d2 = d0 + 8;
            int d3 = d2 - 1;
            S[n][0] = (d0 <= BAND && d0 >= -BAND) ? S[n][0] * SCALE : 0.0f;
            S[n][1] = (d1 <= BAND && d1 >= -BAND) ? S[n][1] * SCALE : 0.0f;
            S[n][2] = (d2 <= BAND && d2 >= -BAND) ? S[n][2] * SCALE : 0.0f;
            S[n][3] = (d3 <= BAND && d3 >= -BAND) ? S[n][3] * SCALE : 0.0f;
        }

        // ---- convert S C-frags into phase-B A-frags (fp16) ----
        uint32_t pah[2][4];
#pragma unroll
        for (int kc = 0; kc < 2; kc++) {
            pah[kc][0] = cvt2h(S[2 * kc][0],     S[2 * kc][1]);
            pah[kc][1] = cvt2h(S[2 * kc][2],     S[2 * kc][3]);
            pah[kc][2] = cvt2h(S[2 * kc + 1][0], S[2 * kc + 1][1]);
            pah[kc][3] = cvt2h(S[2 * kc + 1][2], S[2 * kc + 1][3]);
        }

        // ---- Phase B: attv += S @ KV (this warp's j-half) ----
#pragma unroll
        for (int kc = 0; kc < 2; kc++) {
            if (!keep[kc]) continue;
#pragma unroll
            for (int dg = 0; dg < 4; dg += 2) {
                uint32_t vh[8];
                uint32_t off0 = (uint32_t)(((jcol0 + kc * 16 + tj) * QSTR + dg * 16 + td8) * 2);
                uint32_t off1 = (uint32_t)(((jcol0 + kc * 16 + tj) * QSTR + (dg + 1) * 16 + td8) * 2);
                LDSM_X4_T(vh[0], vh[1], vh[2], vh[3], khB + off0);
                LDSM_X4_T(vh[4], vh[5], vh[6], vh[7], khB + off1);
                MMA_F16(attv[2 * dg],     pah[kc], vh[0], vh[1]);
                MMA_F16(attv[2 * dg + 1], pah[kc], vh[2], vh[3]);
                MMA_F16(attv[2 * dg + 2], pah[kc], vh[4], vh[5]);
                MMA_F16(attv[2 * dg + 3], pah[kc], vh[6], vh[7]);
            }
        }
    }

    // ---- cross-warp reduction over wj; att (fp16) goes to smem ----
    __syncthreads();   // K buffers dead from here; red aliases them
    if (wj == 1) {
#pragma unroll
        for (int n = 0; n < 8; n++) {
            int col = n * 8 + tq * 2;
            *reinterpret_cast<float2*>(&red[m_base + g][col])     = make_float2(attv[n][0], attv[n][1]);
            *reinterpret_cast<float2*>(&red[m_base + g + 8][col]) = make_float2(attv[n][2], attv[n][3]);
        }
    }
    __syncthreads();   // Q dead from here; AttH aliases it
    if (wj == 0) {
        uint32_t* ath = reinterpret_cast<uint32_t*>(AttH);
#pragma unroll
        for (int n = 0; n < 8; n++) {
            int col = n * 8 + tq * 2;
            float2 rr0 = *reinterpret_cast<const float2*>(&red[m_base + g][col]);
            float2 rr1 = *reinterpret_cast<const float2*>(&red[m_base + g + 8][col]);
            int cw = n * 4 + tq;   // word index within row
            ath[(m_base + g) * (QSTR / 2) + cw]     = cvt2h(attv[n][0] + rr0.x, attv[n][1] + rr0.y);
            ath[(m_base + g + 8) * (QSTR / 2) + cw] = cvt2h(attv[n][2] + rr1.x, attv[n][3] + rr1.y);
        }
    }
    __syncthreads();

    // ---- fused output GEMM: out[64, 512] = att @ Wo + bo ----
    // att a-fragments (persistent), Wo read straight from resident smem.
    uint32_t oah[4][4];
#pragma unroll
    for (int kc = 0; kc < 4; kc++) {
        uint32_t off = (uint32_t)(((m_base + a_row) * QSTR + kc * 16 + a_c8) * 2);
        LDSM_X4(oah[kc][0], oah[kc][1], oah[kc][2], oah[kc][3], athB + off);
    }

    const int wn = wj;          // column half within each 128-col chunk
    const size_t row_g = (size_t)b * SEQ + q0 + m_base + g;

#pragma unroll
    for (int cc = 0; cc < 4; cc++) {
        const int col0 = cc * 128 + wn * 64;
        float oc[8][4];
#pragma unroll
        for (int n = 0; n < 8; n++)
#pragma unroll
            for (int r = 0; r < 4; r++) oc[n][r] = 0.0f;

#pragma unroll
        for (int kc = 0; kc < 4; kc++) {
#pragma unroll
            for (int dg = 0; dg < 4; dg += 2) {
                uint32_t vh[8];
                uint32_t off0 = (uint32_t)(((kc * 16 + tj) * WSTRF + col0 + dg * 16 + td8) * 2);
                uint32_t off1 = (uint32_t)(((kc * 16 + tj) * WSTRF + col0 + (dg + 1) * 16 + td8) * 2);
                LDSM_X4_T(vh[0], vh[1], vh[2], vh[3], whB + off0);
                LDSM_X4_T(vh[4], vh[5], vh[6], vh[7], whB + off1);
                MMA_F16(oc[2 * dg],     oah[kc], vh[0], vh[1]);
                MMA_F16(oc[2 * dg + 1], oah[kc], vh[2], vh[3]);
                MMA_F16(oc[2 * dg + 2], oah[kc], vh[4], vh[5]);
                MMA_F16(oc[2 * dg + 3], oah[kc], vh[6], vh[7]);
            }
        }

        // epilogue: bias + fp32 store for this chunk
#pragma unroll
        for (int n = 0; n < 8; n++) {
            int col = col0 + n * 8 + tq * 2;
            float b0v = bo[col], b1v = bo[col + 1];
            float2 o0 = {oc[n][0] + b0v, oc[n][1] + b1v};
            float2 o1 = {oc[n][2] + b0v, oc[n][3] + b1v};
            *reinterpret_cast<float2*>(&out[row_g * DIM + col]) = o0;
            *reinterpret_cast<float2*>(&out[(row_g + 8) * DIM + col]) = o1;
        }
    }
}

// ---------------------------------------------------------------------------
extern "C" void kernel_launch(void* const* d_in, const int* in_sizes, int n_in,
                              void* d_out, int out_size)
{
    const float* query = (const float*)d_in[0];
    const float* value = (const float*)d_in[1];
    const float* Wi    = (const float*)d_in[2];
    const float* bi    = (const float*)d_in[3];
    const float* Wo    = (const float*)d_in[4];
    const float* bo    = (const float*)d_in[5];
    float* out = (float*)d_out;

    static bool attr_set = false;
    if (!attr_set) {
        cudaFuncSetAttribute(proj_kernel, cudaFuncAttributeMaxDynamicSharedMemorySize,
                             PROJ_SMEM_BYTES);
        cudaFuncSetAttribute(attn_kernel, cudaFuncAttributeMaxDynamicSharedMemorySize,
                             ATTN_SMEM_BYTES);
        attr_set = true;
    }

    proj_kernel<<<MTOT / 64 + 8, 256, PROJ_SMEM_BYTES>>>(query, value, Wi, Wo, bi);
    attn_kernel<<<BATCH * (SEQ / 64), 256, ATTN_SMEM_BYTES>>>(bo, out);
}